// round 2
// baseline (speedup 1.0000x reference)
#include <cuda_runtime.h>
#include <math.h>

#define MAXN 20000
#define MAXE 320000

typedef unsigned long long ull;

// ---------------- scratch (device globals; no runtime allocation) ----------
__device__ float g_pre[MAXN * 256];   // pre_x: [s(64) | v(64x3)] (standard layout)
__device__ float g_tmp[MAXN * 256];   // gated features before Wn e3_linear (standard)
__device__ float g_xg [MAXN * 256];   // xg (gather source for edges, standard)
__device__ float g_acc[MAXN * 256];   // self_x + scatter accumulator (QUAD layout: [u][4])
__device__ float g_h1a[MAXE * 32];
__device__ float g_h1l[MAXE * 32];
__device__ float g_WfT[320 * 32];     // Wf2^T * (1/sqrt(32))
__device__ float g_WlT[320 * 32];     // Wl2^T * (1/sqrt(32))
__device__ float g_Wl1s[64 * 32];     // (Wl1[u]+Wl1[u+64]) / sqrt(192)
__device__ float g_Wl1i[64 * 32];     // Wl1[u+128] / sqrt(192)

__device__ __forceinline__ float sspf(float x) {
    float sp = (x > 15.f) ? x : log1pf(expf(x));
    return sp - 0.69314718055994531f;
}
__device__ __forceinline__ float siluf(float x) {
    return x / (1.f + expf(-x));
}

// ---- f32x2 packed math helpers ---------------------------------------------
__device__ __forceinline__ ull pack2(float a, float b) {
    ull r; asm("mov.b64 %0, {%1, %2};" : "=l"(r) : "f"(a), "f"(b)); return r;
}
__device__ __forceinline__ void fma2(ull& d, ull a, ull b) {
    asm("fma.rn.f32x2 %0, %1, %2, %0;" : "+l"(d) : "l"(a), "l"(b));
}
__device__ __forceinline__ ull mul2(ull a, ull b) {
    ull r; asm("mul.rn.f32x2 %0, %1, %2;" : "=l"(r) : "l"(a), "l"(b)); return r;
}
__device__ __forceinline__ void unpack2(ull v, float& lo, float& hi) {
    asm("mov.b64 {%0, %1}, %2;" : "=f"(lo), "=f"(hi) : "l"(v));
}

// ---------------- weight prep --------------------------------------------
__global__ void prep_kernel(const float* __restrict__ Wf2,
                            const float* __restrict__ Wl2,
                            const float* __restrict__ Wl1) {
    int i = blockIdx.x * 256 + threadIdx.x;
    const float is32 = 0.17677669529663687f;   // 1/sqrt(32)
    if (i < 320 * 32) {
        int c = i >> 5, k = i & 31;
        g_WfT[i] = Wf2[k * 320 + c] * is32;
        g_WlT[i] = Wl2[k * 320 + c] * is32;
    }
    if (i < 64 * 32) {
        const float r192 = 0.07216878364870323f;  // 1/sqrt(192)
        g_Wl1s[i] = (Wl1[i] + Wl1[64 * 32 + i]) * r192;
        g_Wl1i[i] = Wl1[128 * 32 + i] * r192;
    }
}

// ---------------- e3_linear, layout-templated ------------------------------
// Layout 0 (standard): s[64] | v interleaved [u][3]
// Layout 1 (quad):     [u][4] = (s_u, v0_u, v1_u, v2_u)   (16B-aligned quads)
template<int IL, int OL, int OL2>
__global__ void e3_kernel(const float* __restrict__ in,
                          const float* __restrict__ W0,
                          const float* __restrict__ b0,
                          const float* __restrict__ W1,
                          float* __restrict__ out,
                          float* __restrict__ out2, int nN) {
    __shared__ float W0s[64 * 64];
    __shared__ float W1s[64 * 64];
    __shared__ float b0s[64];
    __shared__ float ins[4][256];
    int tid = threadIdx.x;
    for (int i = tid; i < 4096; i += 256) { W0s[i] = W0[i]; W1s[i] = W1[i]; }
    if (tid < 64) b0s[tid] = b0[tid];
    int n0 = blockIdx.x * 4;
    for (int i = tid; i < 1024; i += 256) {
        int nl = i >> 8, f = i & 255;
        int n = n0 + nl;
        ins[nl][f] = (n < nN) ? in[n * 256 + f] : 0.f;
    }
    __syncthreads();
    int nl = tid >> 6, v = tid & 63;
    int n = n0 + nl;
    if (n < nN) {
        float accs = 0.f, a0 = 0.f, a1 = 0.f, a2 = 0.f;
        const float* row = ins[nl];
        #pragma unroll 16
        for (int u = 0; u < 64; u++) {
            float w0 = W0s[u * 64 + v];
            float w1 = W1s[u * 64 + v];
            float su, v0, v1, v2;
            if (IL == 0) {
                su = row[u];
                v0 = row[64 + u * 3 + 0]; v1 = row[64 + u * 3 + 1]; v2 = row[64 + u * 3 + 2];
            } else {
                su = row[u * 4];
                v0 = row[u * 4 + 1]; v1 = row[u * 4 + 2]; v2 = row[u * 4 + 3];
            }
            accs += su * w0;
            a0 += v0 * w1; a1 += v1 * w1; a2 += v2 * w1;
        }
        float os = accs * 0.125f + b0s[v];
        float o0 = a0 * 0.125f, o1 = a1 * 0.125f, o2 = a2 * 0.125f;
        float* po = out + n * 256;
        if (OL == 0) {
            po[v] = os;
            po[64 + v * 3 + 0] = o0; po[64 + v * 3 + 1] = o1; po[64 + v * 3 + 2] = o2;
        } else {
            po[v * 4] = os; po[v * 4 + 1] = o0; po[v * 4 + 2] = o1; po[v * 4 + 3] = o2;
        }
        if (out2) {
            float* p2 = out2 + n * 256;
            if (OL2 == 0) {
                p2[v] = os;
                p2[64 + v * 3 + 0] = o0; p2[64 + v * 3 + 1] = o1; p2[64 + v * 3 + 2] = o2;
            } else {
                p2[v * 4] = os; p2[v * 4 + 1] = o0; p2[v * 4 + 2] = o1; p2[v * 4 + 3] = o2;
            }
        }
    }
}

// ---------------- gate MLP (f32x2, 16 nodes/block) -------------------------
// g = silu(f0@Wg1+bg1)@Wg2+bg2; then gated features written standard layout.
__global__ void gate_kernel(const float* __restrict__ x,
                            const float* __restrict__ Wg1,
                            const float* __restrict__ bg1,
                            const float* __restrict__ Wg2,
                            const float* __restrict__ bg2,
                            float* __restrict__ outb, int nN) {
    extern __shared__ float sm[];
    float* W1s = sm;                 // 16384
    float* W2s = sm + 16384;         // 16384
    float* f0t = sm + 32768;         // 128*18 = 2304 (node-major pairs, padded)
    float* hst = sm + 32768 + 2304;  // 128*18 = 2304
    int tid = threadIdx.x;
    for (int i = tid; i < 16384; i += 256) { W1s[i] = Wg1[i]; W2s[i] = Wg2[i]; }
    int n0 = blockIdx.x * 16;
    // stage f0 transposed: f0t[j*18 + nl], nl in [0,16)
    for (int i = tid; i < 2048; i += 256) {
        int nl = i & 15, j = i >> 4;
        int n = n0 + nl;
        float val = 0.f;
        if (n < nN) {
            const float* xr = x + n * 256;
            if (j < 64) val = xr[j];
            else {
                int u = j - 64;
                float v0 = xr[64 + u * 3], v1 = xr[64 + u * 3 + 1], v2 = xr[64 + u * 3 + 2];
                val = sqrtf(v0 * v0 + v1 * v1 + v2 * v2 + 1e-12f);
            }
        }
        f0t[j * 18 + nl] = val;
    }
    __syncthreads();
    int j = tid & 127, half = tid >> 7;   // half selects node group [half*8, half*8+8)
    // layer 1
    {
        ull a0 = 0, a1 = 0, a2 = 0, a3 = 0;
        #pragma unroll 8
        for (int k = 0; k < 128; k++) {
            float w = W1s[k * 128 + j];
            ull wp = pack2(w, w);
            const ull* f = (const ull*)&f0t[k * 18 + half * 8];
            fma2(a0, wp, f[0]); fma2(a1, wp, f[1]); fma2(a2, wp, f[2]); fma2(a3, wp, f[3]);
        }
        float b = bg1[j];
        float lo, hi;
        unpack2(a0, lo, hi); hst[j * 18 + half * 8 + 0] = siluf(lo + b); hst[j * 18 + half * 8 + 1] = siluf(hi + b);
        unpack2(a1, lo, hi); hst[j * 18 + half * 8 + 2] = siluf(lo + b); hst[j * 18 + half * 8 + 3] = siluf(hi + b);
        unpack2(a2, lo, hi); hst[j * 18 + half * 8 + 4] = siluf(lo + b); hst[j * 18 + half * 8 + 5] = siluf(hi + b);
        unpack2(a3, lo, hi); hst[j * 18 + half * 8 + 6] = siluf(lo + b); hst[j * 18 + half * 8 + 7] = siluf(hi + b);
    }
    __syncthreads();
    // layer 2
    float g[8];
    {
        ull a0 = 0, a1 = 0, a2 = 0, a3 = 0;
        #pragma unroll 8
        for (int k = 0; k < 128; k++) {
            float w = W2s[k * 128 + j];
            ull wp = pack2(w, w);
            const ull* h = (const ull*)&hst[k * 18 + half * 8];
            fma2(a0, wp, h[0]); fma2(a1, wp, h[1]); fma2(a2, wp, h[2]); fma2(a3, wp, h[3]);
        }
        float b = bg2[j];
        unpack2(a0, g[0], g[1]); unpack2(a1, g[2], g[3]);
        unpack2(a2, g[4], g[5]); unpack2(a3, g[6], g[7]);
        #pragma unroll
        for (int p = 0; p < 8; p++) g[p] += b;
    }
    #pragma unroll
    for (int p = 0; p < 8; p++) {
        int n = n0 + half * 8 + p;
        if (n >= nN) continue;
        float* o = outb + n * 256;
        if (j < 64) o[j] = g[p];
        else {
            int u = j - 64;
            const float* xr = x + n * 256 + 64 + u * 3;
            o[64 + u * 3 + 0] = xr[0] * g[p];
            o[64 + u * 3 + 1] = xr[1] * g[p];
            o[64 + u * 3 + 2] = xr[2] * g[p];
        }
    }
}

// ---------------- h1a = ssp(edge_attr @ Wf1 / 8) ---------------------------
__global__ void h1a_kernel(const float* __restrict__ attr,
                           const float* __restrict__ Wf1,
                           float* __restrict__ h1a, int nE) {
    __shared__ float attrs[64 * 64];
    __shared__ float Wf1s[64 * 32];
    int tid = threadIdx.x;
    int e0 = blockIdx.x * 64;
    for (int i = tid; i < 2048; i += 256) Wf1s[i] = Wf1[i];
    for (int i = tid; i < 4096; i += 256) {
        int e = e0 + (i >> 6);
        attrs[i] = (e < nE) ? attr[e * 64 + (i & 63)] : 0.f;
    }
    __syncthreads();
    int k = tid & 31, g = tid >> 5;   // 8 groups x 8 edges
    float acc[8] = {0.f, 0.f, 0.f, 0.f, 0.f, 0.f, 0.f, 0.f};
    for (int u = 0; u < 64; u++) {
        float w = Wf1s[u * 32 + k];
        #pragma unroll
        for (int ee = 0; ee < 8; ee++)
            acc[ee] += attrs[(g * 8 + ee) * 64 + u] * w;
    }
    #pragma unroll
    for (int ee = 0; ee < 8; ee++) {
        int e = e0 + g * 8 + ee;
        if (e < nE) h1a[e * 32 + k] = sspf(acc[ee] * 0.125f);
    }
}

// ---------------- h1l = ssp(s0 @ Wl1 / sqrt(192)) --------------------------
__global__ void h1l_kernel(const int* __restrict__ ei,
                           const float* __restrict__ pre,
                           float* __restrict__ h1l, int nE, int Etot) {
    __shared__ float ps_s[32 * 64];
    __shared__ float ip_s[32 * 64];
    __shared__ float Ws[64 * 32];
    __shared__ float Wi[64 * 32];
    __shared__ int dsts[32], srcs[32];
    int tid = threadIdx.x;
    int e0 = blockIdx.x * 32;
    for (int i = tid; i < 2048; i += 256) { Ws[i] = g_Wl1s[i]; Wi[i] = g_Wl1i[i]; }
    if (tid < 32) {
        int e = e0 + tid;
        dsts[tid] = (e < nE) ? ei[e] : 0;
        srcs[tid] = (e < nE) ? ei[Etot + e] : 0;
    }
    __syncthreads();
    for (int i = tid; i < 2048; i += 256) {
        int el = i >> 6, u = i & 63;
        int e = e0 + el;
        if (e < nE) {
            int d = dsts[el], s = srcs[el];
            ps_s[i] = pre[d * 256 + u];
            const float* pd = pre + d * 256 + 64 + u * 3;
            const float* pv = pre + s * 256 + 64 + u * 3;
            ip_s[i] = (pd[0] * pv[0] + pd[1] * pv[1] + pd[2] * pv[2]) * (1.f / 3.f);
        } else { ps_s[i] = 0.f; ip_s[i] = 0.f; }
    }
    __syncthreads();
    int k = tid & 31, g = tid >> 5;   // 8 groups x 4 edges
    float acc[4] = {0.f, 0.f, 0.f, 0.f};
    for (int u = 0; u < 64; u++) {
        float ws = Ws[u * 32 + k];
        float wi = Wi[u * 32 + k];
        #pragma unroll
        for (int ee = 0; ee < 4; ee++) {
            int el = g * 4 + ee;
            acc[ee] += ps_s[el * 64 + u] * ws + ip_s[el * 64 + u] * wi;
        }
    }
    #pragma unroll
    for (int ee = 0; ee < 4; ee++) {
        int e = e0 + g * 4 + ee;
        if (e < nE) h1l[e * 32 + k] = sspf(acc[ee]);
    }
}

// ---------------- fused edge kernel: w = (h1a@Wf2)*(h1l@Wl2); TP; scatter --
#define TE 64
__global__ void __launch_bounds__(320, 1)
edge_kernel(const int* __restrict__ ei,
            const float* __restrict__ sh,
            const float* __restrict__ h1a,
            const float* __restrict__ h1l,
            const float* __restrict__ xg,
            float* __restrict__ acc, int nE, int Etot) {
    extern __shared__ float sm[];
    float* hA  = sm;                     // 32 * 68
    float* hB  = sm + 32 * 68;           // 32 * 68
    float* ws  = sm + 2 * 32 * 68;       // 64 * 320
    float* shs = ws + 64 * 320;          // 64 * 4
    int*   idxs = (int*)(shs + 256);     // src[64] | dst[64]
    int tid = threadIdx.x;
    int e0 = blockIdx.x * TE;
    if (tid < 64) {
        int e = e0 + tid;
        bool v = (e < nE);
        idxs[tid]      = v ? ei[Etot + e] : 0;   // src
        idxs[64 + tid] = v ? ei[e] : -1;         // dst; -1 => skip
        float4 s4 = v ? *(const float4*)&sh[e * 4] : make_float4(0.f, 0.f, 0.f, 0.f);
        ((float4*)shs)[tid] = s4;
    }
    for (int i = tid; i < 2048; i += 320) {
        int el = i >> 5, k = i & 31;
        int e = e0 + el;
        float a = 0.f, b = 0.f;
        if (e < nE) { a = h1a[e * 32 + k]; b = h1l[e * 32 + k]; }
        hA[k * 68 + el] = a;
        hB[k * 68 + el] = b;
    }
    __syncthreads();
    // phase 1: per-column GEMM, FFMA2 packed pairs, weight splats in registers
    {
        int c = tid;  // 0..319
        ull wf2[32], wl2[32];
        #pragma unroll
        for (int q = 0; q < 8; q++) {
            float4 f = ((const float4*)(g_WfT + c * 32))[q];
            wf2[q * 4 + 0] = pack2(f.x, f.x); wf2[q * 4 + 1] = pack2(f.y, f.y);
            wf2[q * 4 + 2] = pack2(f.z, f.z); wf2[q * 4 + 3] = pack2(f.w, f.w);
            float4 l = ((const float4*)(g_WlT + c * 32))[q];
            wl2[q * 4 + 0] = pack2(l.x, l.x); wl2[q * 4 + 1] = pack2(l.y, l.y);
            wl2[q * 4 + 2] = pack2(l.z, l.z); wl2[q * 4 + 3] = pack2(l.w, l.w);
        }
        #pragma unroll 1
        for (int eg = 0; eg < 8; eg++) {   // 8 edges per group
            ull aA0 = 0, aA1 = 0, aA2 = 0, aA3 = 0;
            ull aB0 = 0, aB1 = 0, aB2 = 0, aB3 = 0;
            const float* baseA = hA + eg * 8;
            const float* baseB = hB + eg * 8;
            #pragma unroll
            for (int k = 0; k < 32; k++) {
                const ull* pa = (const ull*)(baseA + k * 68);
                const ull* pb = (const ull*)(baseB + k * 68);
                fma2(aA0, wf2[k], pa[0]); fma2(aA1, wf2[k], pa[1]);
                fma2(aA2, wf2[k], pa[2]); fma2(aA3, wf2[k], pa[3]);
                fma2(aB0, wl2[k], pb[0]); fma2(aB1, wl2[k], pb[1]);
                fma2(aB2, wl2[k], pb[2]); fma2(aB3, wl2[k], pb[3]);
            }
            float lo, hi;
            unpack2(mul2(aA0, aB0), lo, hi);
            ws[(eg * 8 + 0) * 320 + c] = lo; ws[(eg * 8 + 1) * 320 + c] = hi;
            unpack2(mul2(aA1, aB1), lo, hi);
            ws[(eg * 8 + 2) * 320 + c] = lo; ws[(eg * 8 + 3) * 320 + c] = hi;
            unpack2(mul2(aA2, aB2), lo, hi);
            ws[(eg * 8 + 4) * 320 + c] = lo; ws[(eg * 8 + 5) * 320 + c] = hi;
            unpack2(mul2(aA3, aB3), lo, hi);
            ws[(eg * 8 + 6) * 320 + c] = lo; ws[(eg * 8 + 7) * 320 + c] = hi;
        }
    }
    __syncthreads();
    // phase 2: tensor product + vector red scatter into QUAD-layout acc
    if (tid < 256) {
        const float PW_S = 0.44721359549995793f;    // sqrt(1/5)
        const float PW_V = 0.77459666924148337f;    // sqrt(3/5)
        const float IS3  = 0.57735026918962576f;    // 1/sqrt(3)
        const float IS2  = 0.70710678118654752f;    // 1/sqrt(2)
        int u = tid & 63, sub = tid >> 6;
        for (int e = sub; e < TE; e += 4) {
            int d = idxs[64 + e];
            if (d < 0) continue;
            int s = idxs[e];
            const float* xr = xg + s * 256;
            float es  = xr[u];
            float ev0 = xr[64 + u * 3], ev1 = xr[64 + u * 3 + 1], ev2 = xr[64 + u * 3 + 2];
            float s0 = shs[e * 4], s1 = shs[e * 4 + 1], s2 = shs[e * 4 + 2], s3 = shs[e * 4 + 3];
            const float* we = ws + e * 320;
            float w0 = we[u], w1 = we[64 + u], w2 = we[128 + u], w3 = we[192 + u], w4 = we[256 + u];
            float dotv = ev0 * s1 + ev1 * s2 + ev2 * s3;
            float c0 = ev1 * s3 - ev2 * s2;
            float c1 = ev2 * s1 - ev0 * s3;
            float c2 = ev0 * s2 - ev1 * s1;
            float outs = PW_S * (w0 * es * s0 + w3 * dotv * IS3);
            float k2 = PW_V * w2 * s0;
            float k4 = PW_V * w4 * IS2;
            float k1 = PW_V * w1 * es;
            float o0 = k1 * s1 + k2 * ev0 + k4 * c0;
            float o1 = k1 * s2 + k2 * ev1 + k4 * c1;
            float o2 = k1 * s3 + k2 * ev2 + k4 * c2;
            float* pa = acc + d * 256 + u * 4;   // 16B-aligned quad
            asm volatile("red.global.add.v4.f32 [%0], {%1, %2, %3, %4};"
                         :: "l"(pa), "f"(outs), "f"(o0), "f"(o1), "f"(o2) : "memory");
        }
    }
}

// ---------------- launch ----------------------------------------------------
extern "C" void kernel_launch(void* const* d_in, const int* in_sizes, int n_in,
                              void* d_out, int out_size) {
    const float* x     = (const float*)d_in[0];
    const int*   ei    = (const int*)  d_in[1];
    const float* sh    = (const float*)d_in[2];
    const float* attr  = (const float*)d_in[3];
    const float* Wpre0 = (const float*)d_in[4];
    const float* bpre0 = (const float*)d_in[5];
    const float* Wpre1 = (const float*)d_in[6];
    const float* Wg1   = (const float*)d_in[7];
    const float* bg1   = (const float*)d_in[8];
    const float* Wg2   = (const float*)d_in[9];
    const float* bg2   = (const float*)d_in[10];
    const float* Wn0   = (const float*)d_in[11];
    const float* bn0   = (const float*)d_in[12];
    const float* Wn1   = (const float*)d_in[13];
    const float* Wf1   = (const float*)d_in[14];
    const float* Wf2   = (const float*)d_in[15];
    const float* Wl1   = (const float*)d_in[16];
    const float* Wl2   = (const float*)d_in[17];
    const float* Wo0   = (const float*)d_in[18];
    const float* bo0   = (const float*)d_in[19];
    const float* Wo1   = (const float*)d_in[20];

    int N = in_sizes[0] / 256;
    int E = in_sizes[1] / 2;

    float *pre, *tmp, *xgp, *accp, *h1a, *h1l;
    cudaGetSymbolAddress((void**)&pre,  g_pre);
    cudaGetSymbolAddress((void**)&tmp,  g_tmp);
    cudaGetSymbolAddress((void**)&xgp,  g_xg);
    cudaGetSymbolAddress((void**)&accp, g_acc);
    cudaGetSymbolAddress((void**)&h1a,  g_h1a);
    cudaGetSymbolAddress((void**)&h1l,  g_h1l);

    static const int GATE_SMEM = (16384 * 2 + 2304 * 2) * 4;
    static const int EDGE_SMEM = (2 * 32 * 68 + 64 * 320 + 256 + 128) * 4;
    cudaFuncSetAttribute(gate_kernel, cudaFuncAttributeMaxDynamicSharedMemorySize, GATE_SMEM);
    cudaFuncSetAttribute(edge_kernel, cudaFuncAttributeMaxDynamicSharedMemorySize, EDGE_SMEM);

    prep_kernel<<<(320 * 32 + 255) / 256, 256>>>(Wf2, Wl2, Wl1);
    // pre_x (std -> std)
    e3_kernel<0, 0, 0><<<(N + 3) / 4, 256>>>(x, Wpre0, bpre0, Wpre1, pre, nullptr, N);
    gate_kernel<<<(N + 15) / 16, 256, GATE_SMEM>>>(x, Wg1, bg1, Wg2, bg2, tmp, N);
    // xg (std), acc initialized with self_x in QUAD layout
    e3_kernel<0, 0, 1><<<(N + 3) / 4, 256>>>(tmp, Wn0, bn0, Wn1, xgp, accp, N);
    h1a_kernel<<<(E + 63) / 64, 256>>>(attr, Wf1, h1a, E);
    h1l_kernel<<<(E + 31) / 32, 256>>>(ei, pre, h1l, E, E);
    edge_kernel<<<(E + TE - 1) / TE, 320, EDGE_SMEM>>>(ei, sh, h1a, h1l, xgp, accp, E, E);
    // final e3: QUAD input -> standard output
    e3_kernel<1, 0, 0><<<(N + 3) / 4, 256>>>(accp, Wo0, bo0, Wo1, (float*)d_out, nullptr, N);
}

// round 3
// speedup vs baseline: 1.0485x; 1.0485x over previous
#include <cuda_runtime.h>
#include <math.h>

#define MAXN 20000
#define MAXE 320000

typedef unsigned long long ull;
typedef ulonglong2 ull2;

// ---------------- scratch (device globals) ---------------------------------
// All node tensors in QUAD layout: [n][u][4] = (s_u, v0_u, v1_u, v2_u)
__device__ float g_pre[MAXN * 256];
__device__ float g_tmp[MAXN * 256];
__device__ float g_xg [MAXN * 256];
__device__ float g_acc[MAXN * 256];
__device__ float g_h1a[MAXE * 32];
__device__ float g_h1l[MAXE * 32];
__device__ float g_WfT[320 * 32];   // Wf2^T * (1/sqrt32)
__device__ float g_WlT[320 * 32];
__device__ ull   g_WfS[320 * 32];   // splatted pairs of the above
__device__ ull   g_WlS[320 * 32];
__device__ float g_Wl1s[64 * 32];   // (Wl1[u]+Wl1[u+64]) / sqrt192
__device__ float g_Wl1i[64 * 32];   // Wl1[u+128] / sqrt192
__device__ ull   g_eW[3 * 4096];    // e3 packed (w0,w1)*0.125 for pre/n/o

__device__ __forceinline__ float sspf(float x) {
    float sp = (x > 15.f) ? x : log1pf(expf(x));
    return sp - 0.69314718055994531f;
}
__device__ __forceinline__ float siluf(float x) {
    return x / (1.f + expf(-x));
}
__device__ __forceinline__ ull pack2(float a, float b) {
    ull r; asm("mov.b64 %0, {%1, %2};" : "=l"(r) : "f"(a), "f"(b)); return r;
}
__device__ __forceinline__ void fma2(ull& d, ull a, ull b) {
    asm("fma.rn.f32x2 %0, %1, %2, %0;" : "+l"(d) : "l"(a), "l"(b));
}
__device__ __forceinline__ ull mul2(ull a, ull b) {
    ull r; asm("mul.rn.f32x2 %0, %1, %2;" : "=l"(r) : "l"(a), "l"(b)); return r;
}
__device__ __forceinline__ void unpack2(ull v, float& lo, float& hi) {
    asm("mov.b64 {%0, %1}, %2;" : "=f"(lo), "=f"(hi) : "l"(v));
}

// ---------------- weight prep ----------------------------------------------
__global__ void prep_kernel(const float* __restrict__ Wf2,
                            const float* __restrict__ Wl2,
                            const float* __restrict__ Wl1,
                            const float* __restrict__ Wpre0,
                            const float* __restrict__ Wpre1,
                            const float* __restrict__ Wn0,
                            const float* __restrict__ Wn1,
                            const float* __restrict__ Wo0,
                            const float* __restrict__ Wo1) {
    int i = blockIdx.x * 256 + threadIdx.x;
    const float is32 = 0.17677669529663687f;   // 1/sqrt(32)
    if (i < 320 * 32) {
        int c = i >> 5, k = i & 31;
        float f = Wf2[k * 320 + c] * is32;
        float l = Wl2[k * 320 + c] * is32;
        g_WfT[i] = f; g_WlT[i] = l;
        g_WfS[i] = pack2(f, f); g_WlS[i] = pack2(l, l);
    }
    if (i < 64 * 32) {
        const float r192 = 0.07216878364870323f;  // 1/sqrt(192)
        g_Wl1s[i] = (Wl1[i] + Wl1[64 * 32 + i]) * r192;
        g_Wl1i[i] = Wl1[128 * 32 + i] * r192;
    }
    if (i < 3 * 4096) {
        int p = i >> 12, r = i & 4095;
        const float* w0 = (p == 0) ? Wpre0 : (p == 1) ? Wn0 : Wo0;
        const float* w1 = (p == 0) ? Wpre1 : (p == 1) ? Wn1 : Wo1;
        g_eW[i] = pack2(w0[r] * 0.125f, w1[r] * 0.125f);
    }
}

// ---------------- e3_linear ------------------------------------------------
// IL/OL/OL2: 0 = standard layout (s[64] | v[u][3]), 1 = quad layout.
template<int IL, int OL, int OL2>
__global__ void e3_kernel(const float* __restrict__ in,
                          int widx,
                          const float* __restrict__ b0,
                          float* __restrict__ out,
                          float* __restrict__ out2, int nN) {
    __shared__ ull   Wp[4096];       // (w0,w1)*0.125 per (u,v)
    __shared__ float b0s[64];
    __shared__ float ins[8][256];    // quad
    int tid = threadIdx.x;
    {
        const ull2* src = (const ull2*)(g_eW + widx * 4096);
        ull2* dst = (ull2*)Wp;
        #pragma unroll
        for (int i = tid; i < 2048; i += 256) dst[i] = src[i];
    }
    if (tid < 64) b0s[tid] = b0[tid];
    int n0 = blockIdx.x * 8;
    if (IL == 0) {
        for (int i = tid; i < 2048; i += 256) {
            int nl = i >> 8, r = i & 255, u = r >> 2, c = r & 3;
            int n = n0 + nl;
            float val = 0.f;
            if (n < nN) {
                int f = (c == 0) ? u : 64 + u * 3 + (c - 1);
                val = in[n * 256 + f];
            }
            ins[nl][r] = val;
        }
    } else {
        for (int i = tid; i < 512; i += 256) {
            int nl = i >> 6, q = i & 63;
            int n = n0 + nl;
            float4 v = (n < nN) ? ((const float4*)(in + n * 256))[q]
                                : make_float4(0.f, 0.f, 0.f, 0.f);
            ((float4*)ins[nl])[q] = v;
        }
    }
    __syncthreads();
    int v = tid & 63, g = tid >> 6;     // g in [0,4): node pair (g*2, g*2+1)
    const ull2* rowA = (const ull2*)ins[g * 2];
    const ull2* rowB = (const ull2*)ins[g * 2 + 1];
    ull accA0 = 0, accA1 = 0, accB0 = 0, accB1 = 0;
    #pragma unroll 8
    for (int u = 0; u < 64; u++) {
        ull wp = Wp[u * 64 + v];
        float w0, w1; unpack2(wp, w0, w1);
        ull wq = pack2(w1, w1);
        ull2 qa = rowA[u];
        ull2 qb = rowB[u];
        fma2(accA0, wp, qa.x); fma2(accA1, wq, qa.y);
        fma2(accB0, wp, qb.x); fma2(accB1, wq, qb.y);
    }
    float bias = b0s[v];
    #pragma unroll
    for (int t = 0; t < 2; t++) {
        int n = n0 + g * 2 + t;
        if (n >= nN) continue;
        float s, o0, o1, o2;
        unpack2(t ? accB0 : accA0, s, o0);
        unpack2(t ? accB1 : accA1, o1, o2);
        s += bias;
        if (OL == 0) {
            float* po = out + n * 256;
            po[v] = s;
            po[64 + v * 3 + 0] = o0; po[64 + v * 3 + 1] = o1; po[64 + v * 3 + 2] = o2;
        } else {
            ((float4*)(out + n * 256))[v] = make_float4(s, o0, o1, o2);
        }
        if (out2) {
            if (OL2 == 0) {
                float* p2 = out2 + n * 256;
                p2[v] = s;
                p2[64 + v * 3 + 0] = o0; p2[64 + v * 3 + 1] = o1; p2[64 + v * 3 + 2] = o2;
            } else {
                ((float4*)(out2 + n * 256))[v] = make_float4(s, o0, o1, o2);
            }
        }
    }
}

// ---------------- gate MLP (f32x2, 16 nodes/block) -> quad output ----------
__global__ void gate_kernel(const float* __restrict__ x,
                            const float* __restrict__ Wg1,
                            const float* __restrict__ bg1,
                            const float* __restrict__ Wg2,
                            const float* __restrict__ bg2,
                            float* __restrict__ outb, int nN) {
    extern __shared__ float sm[];
    float* W1s = sm;                 // 16384
    float* W2s = sm + 16384;         // 16384
    float* f0t = sm + 32768;         // 2304 (transposed input; later g staging)
    float* hst = sm + 32768 + 2304;  // 2304
    int tid = threadIdx.x;
    for (int i = tid; i < 16384; i += 256) { W1s[i] = Wg1[i]; W2s[i] = Wg2[i]; }
    int n0 = blockIdx.x * 16;
    for (int i = tid; i < 2048; i += 256) {
        int nl = i & 15, j = i >> 4;
        int n = n0 + nl;
        float val = 0.f;
        if (n < nN) {
            const float* xr = x + n * 256;
            if (j < 64) val = xr[j];
            else {
                int u = j - 64;
                float v0 = xr[64 + u * 3], v1 = xr[64 + u * 3 + 1], v2 = xr[64 + u * 3 + 2];
                val = sqrtf(v0 * v0 + v1 * v1 + v2 * v2 + 1e-12f);
            }
        }
        f0t[j * 18 + nl] = val;
    }
    __syncthreads();
    int j = tid & 127, half = tid >> 7;
    {
        ull a0 = 0, a1 = 0, a2 = 0, a3 = 0;
        #pragma unroll 8
        for (int k = 0; k < 128; k++) {
            float w = W1s[k * 128 + j];
            ull wp = pack2(w, w);
            const ull* f = (const ull*)&f0t[k * 18 + half * 8];
            fma2(a0, wp, f[0]); fma2(a1, wp, f[1]); fma2(a2, wp, f[2]); fma2(a3, wp, f[3]);
        }
        float b = bg1[j];
        float lo, hi;
        unpack2(a0, lo, hi); hst[j * 18 + half * 8 + 0] = siluf(lo + b); hst[j * 18 + half * 8 + 1] = siluf(hi + b);
        unpack2(a1, lo, hi); hst[j * 18 + half * 8 + 2] = siluf(lo + b); hst[j * 18 + half * 8 + 3] = siluf(hi + b);
        unpack2(a2, lo, hi); hst[j * 18 + half * 8 + 4] = siluf(lo + b); hst[j * 18 + half * 8 + 5] = siluf(hi + b);
        unpack2(a3, lo, hi); hst[j * 18 + half * 8 + 6] = siluf(lo + b); hst[j * 18 + half * 8 + 7] = siluf(hi + b);
    }
    __syncthreads();
    float g[8];
    {
        ull a0 = 0, a1 = 0, a2 = 0, a3 = 0;
        #pragma unroll 8
        for (int k = 0; k < 128; k++) {
            float w = W2s[k * 128 + j];
            ull wp = pack2(w, w);
            const ull* h = (const ull*)&hst[k * 18 + half * 8];
            fma2(a0, wp, h[0]); fma2(a1, wp, h[1]); fma2(a2, wp, h[2]); fma2(a3, wp, h[3]);
        }
        float b = bg2[j];
        unpack2(a0, g[0], g[1]); unpack2(a1, g[2], g[3]);
        unpack2(a2, g[4], g[5]); unpack2(a3, g[6], g[7]);
        #pragma unroll
        for (int p = 0; p < 8; p++) g[p] += b;
    }
    __syncthreads();   // hst reads done everywhere before reusing f0t region
    #pragma unroll
    for (int p = 0; p < 8; p++) f0t[(half * 8 + p) * 128 + j] = g[p];
    __syncthreads();
    for (int q = tid; q < 1024; q += 256) {
        int nl = q >> 6, u = q & 63;
        int n = n0 + nl;
        if (n >= nN) continue;
        float gs = f0t[nl * 128 + u];
        float gv = f0t[nl * 128 + 64 + u];
        const float* xr = x + n * 256 + 64 + u * 3;
        ((float4*)(outb + n * 256))[u] = make_float4(gs, xr[0] * gv, xr[1] * gv, xr[2] * gv);
    }
}

// ---------------- h1a = ssp(edge_attr @ Wf1 / 8) ---------------------------
__global__ void h1a_kernel(const float* __restrict__ attr,
                           const float* __restrict__ Wf1,
                           float* __restrict__ h1a, int nE) {
    __shared__ float at[64 * 68];     // [u][edge], pad 68
    __shared__ float Wf1s[64 * 32];
    int tid = threadIdx.x;
    int e0 = blockIdx.x * 64;
    for (int i = tid; i < 2048; i += 256) Wf1s[i] = Wf1[i];
    for (int i = tid; i < 4096; i += 256) {
        int el = i >> 6, u = i & 63;
        int e = e0 + el;
        at[u * 68 + el] = (e < nE) ? attr[e * 64 + u] : 0.f;
    }
    __syncthreads();
    int k = tid & 31, g = tid >> 5;   // 8 groups x 8 edges
    ull a0 = 0, a1 = 0, a2 = 0, a3 = 0;
    #pragma unroll 4
    for (int u = 0; u < 64; u++) {
        float w = Wf1s[u * 32 + k];
        ull wp = pack2(w, w);
        const ull2* pa = (const ull2*)(at + u * 68 + g * 8);
        ull2 A0 = pa[0], A1 = pa[1];
        fma2(a0, wp, A0.x); fma2(a1, wp, A0.y);
        fma2(a2, wp, A1.x); fma2(a3, wp, A1.y);
    }
    float r[8];
    unpack2(a0, r[0], r[1]); unpack2(a1, r[2], r[3]);
    unpack2(a2, r[4], r[5]); unpack2(a3, r[6], r[7]);
    #pragma unroll
    for (int ee = 0; ee < 8; ee++) {
        int e = e0 + g * 8 + ee;
        if (e < nE) h1a[e * 32 + k] = sspf(r[ee] * 0.125f);
    }
}

// ---------------- h1l = ssp(s0 @ Wl1 / sqrt192), quad pre gathers ----------
__global__ void h1l_kernel(const int* __restrict__ ei,
                           const float* __restrict__ pre,
                           float* __restrict__ h1l, int nE, int Etot) {
    __shared__ float ps_t[64 * 36];   // [u][edge], 32 edges pad 36
    __shared__ float ip_t[64 * 36];
    __shared__ float Ws[64 * 32];
    __shared__ float Wi[64 * 32];
    __shared__ int dsts[32], srcs[32];
    int tid = threadIdx.x;
    int e0 = blockIdx.x * 32;
    for (int i = tid; i < 2048; i += 256) { Ws[i] = g_Wl1s[i]; Wi[i] = g_Wl1i[i]; }
    if (tid < 32) {
        int e = e0 + tid;
        dsts[tid] = (e < nE) ? ei[e] : 0;
        srcs[tid] = (e < nE) ? ei[Etot + e] : 0;
    }
    __syncthreads();
    for (int i = tid; i < 2048; i += 256) {
        int el = i >> 6, u = i & 63;
        int e = e0 + el;
        float psv = 0.f, ipv = 0.f;
        if (e < nE) {
            int d = dsts[el], s = srcs[el];
            float4 qd = *(const float4*)&pre[d * 256 + u * 4];
            float4 qs = *(const float4*)&pre[s * 256 + u * 4];
            psv = qd.x;
            ipv = (qd.y * qs.y + qd.z * qs.z + qd.w * qs.w) * (1.f / 3.f);
        }
        ps_t[u * 36 + el] = psv;
        ip_t[u * 36 + el] = ipv;
    }
    __syncthreads();
    int k = tid & 31, g = tid >> 5;   // 8 groups x 4 edges
    ull a0 = 0, a1 = 0;
    #pragma unroll 4
    for (int u = 0; u < 64; u++) {
        float ws = Ws[u * 32 + k];
        float wi = Wi[u * 32 + k];
        ull wps = pack2(ws, ws), wpi = pack2(wi, wi);
        ull2 P = *(const ull2*)(ps_t + u * 36 + g * 4);
        ull2 I = *(const ull2*)(ip_t + u * 36 + g * 4);
        fma2(a0, wps, P.x); fma2(a1, wps, P.y);
        fma2(a0, wpi, I.x); fma2(a1, wpi, I.y);
    }
    float r[4];
    unpack2(a0, r[0], r[1]); unpack2(a1, r[2], r[3]);
    #pragma unroll
    for (int ee = 0; ee < 4; ee++) {
        int e = e0 + g * 4 + ee;
        if (e < nE) h1l[e * 32 + k] = sspf(r[ee]);
    }
}

// ---------------- fused edge kernel ----------------------------------------
#define TE 64
__global__ void __launch_bounds__(320, 1)
edge_kernel(const int* __restrict__ ei,
            const float* __restrict__ sh,
            const float* __restrict__ h1a,
            const float* __restrict__ h1l,
            const float* __restrict__ xg,
            float* __restrict__ acc, int nE, int Etot) {
    extern __shared__ float sm[];
    float* hA  = sm;                     // 32 * 68
    float* hB  = sm + 32 * 68;           // 32 * 68
    float* ws  = sm + 2 * 32 * 68;       // 64 * 320
    float* shs = ws + 64 * 320;          // 64 * 4
    int*   idxs = (int*)(shs + 256);     // src[64] | dst[64]
    int tid = threadIdx.x;
    int e0 = blockIdx.x * TE;
    if (tid < 64) {
        int e = e0 + tid;
        bool v = (e < nE);
        idxs[tid]      = v ? ei[Etot + e] : 0;
        idxs[64 + tid] = v ? ei[e] : -1;
        float4 s4 = v ? *(const float4*)&sh[e * 4] : make_float4(0.f, 0.f, 0.f, 0.f);
        ((float4*)shs)[tid] = s4;
    }
    for (int i = tid; i < 2048; i += 320) {
        int el = i >> 5, k = i & 31;
        int e = e0 + el;
        float a = 0.f, b = 0.f;
        if (e < nE) { a = h1a[e * 32 + k]; b = h1l[e * 32 + k]; }
        hA[k * 68 + el] = a;
        hB[k * 68 + el] = b;
    }
    // weight splats (prologue, from pre-splatted global)
    int c = tid;
    ull wf2[32], wl2[32];
    {
        const ull2* pf = (const ull2*)(g_WfS + (size_t)c * 32);
        const ull2* pl = (const ull2*)(g_WlS + (size_t)c * 32);
        #pragma unroll
        for (int q = 0; q < 16; q++) {
            ull2 f = pf[q]; wf2[q * 2] = f.x; wf2[q * 2 + 1] = f.y;
            ull2 l = pl[q]; wl2[q * 2] = l.x; wl2[q * 2 + 1] = l.y;
        }
    }
    __syncthreads();
    // phase 1: 8 edges per group, LDS.128 + FFMA2
    #pragma unroll 1
    for (int eg = 0; eg < 8; eg++) {
        ull aA0 = 0, aA1 = 0, aA2 = 0, aA3 = 0;
        ull aB0 = 0, aB1 = 0, aB2 = 0, aB3 = 0;
        const float* bA = hA + eg * 8;
        const float* bB = hB + eg * 8;
        #pragma unroll
        for (int k = 0; k < 32; k++) {
            ull2 A0 = *(const ull2*)(bA + k * 68);
            ull2 A1 = *(const ull2*)(bA + k * 68 + 4);
            ull2 B0 = *(const ull2*)(bB + k * 68);
            ull2 B1 = *(const ull2*)(bB + k * 68 + 4);
            fma2(aA0, wf2[k], A0.x); fma2(aA1, wf2[k], A0.y);
            fma2(aA2, wf2[k], A1.x); fma2(aA3, wf2[k], A1.y);
            fma2(aB0, wl2[k], B0.x); fma2(aB1, wl2[k], B0.y);
            fma2(aB2, wl2[k], B1.x); fma2(aB3, wl2[k], B1.y);
        }
        float lo, hi;
        unpack2(mul2(aA0, aB0), lo, hi);
        ws[(eg * 8 + 0) * 320 + c] = lo; ws[(eg * 8 + 1) * 320 + c] = hi;
        unpack2(mul2(aA1, aB1), lo, hi);
        ws[(eg * 8 + 2) * 320 + c] = lo; ws[(eg * 8 + 3) * 320 + c] = hi;
        unpack2(mul2(aA2, aB2), lo, hi);
        ws[(eg * 8 + 4) * 320 + c] = lo; ws[(eg * 8 + 5) * 320 + c] = hi;
        unpack2(mul2(aA3, aB3), lo, hi);
        ws[(eg * 8 + 6) * 320 + c] = lo; ws[(eg * 8 + 7) * 320 + c] = hi;
    }
    __syncthreads();
    // phase 2: tensor product + red.v4 scatter (quad layout)
    if (tid < 256) {
        const float PW_S = 0.44721359549995793f;
        const float PW_V = 0.77459666924148337f;
        const float IS3  = 0.57735026918962576f;
        const float IS2  = 0.70710678118654752f;
        int u = tid & 63, sub = tid >> 6;
        for (int e = sub; e < TE; e += 4) {
            int d = idxs[64 + e];
            if (d < 0) continue;
            int s = idxs[e];
            float4 q = *(const float4*)&xg[s * 256 + u * 4];
            float es = q.x, ev0 = q.y, ev1 = q.z, ev2 = q.w;
            float s0 = shs[e * 4], s1 = shs[e * 4 + 1], s2 = shs[e * 4 + 2], s3 = shs[e * 4 + 3];
            const float* we = ws + e * 320;
            float w0 = we[u], w1 = we[64 + u], w2 = we[128 + u], w3 = we[192 + u], w4 = we[256 + u];
            float dotv = ev0 * s1 + ev1 * s2 + ev2 * s3;
            float c0 = ev1 * s3 - ev2 * s2;
            float c1 = ev2 * s1 - ev0 * s3;
            float c2 = ev0 * s2 - ev1 * s1;
            float outs = PW_S * (w0 * es * s0 + w3 * dotv * IS3);
            float k2 = PW_V * w2 * s0;
            float k4 = PW_V * w4 * IS2;
            float k1 = PW_V * w1 * es;
            float o0 = k1 * s1 + k2 * ev0 + k4 * c0;
            float o1 = k1 * s2 + k2 * ev1 + k4 * c1;
            float o2 = k1 * s3 + k2 * ev2 + k4 * c2;
            float* pa = acc + d * 256 + u * 4;
            asm volatile("red.global.add.v4.f32 [%0], {%1, %2, %3, %4};"
                         :: "l"(pa), "f"(outs), "f"(o0), "f"(o1), "f"(o2) : "memory");
        }
    }
}

// ---------------- launch ----------------------------------------------------
extern "C" void kernel_launch(void* const* d_in, const int* in_sizes, int n_in,
                              void* d_out, int out_size) {
    const float* x     = (const float*)d_in[0];
    const int*   ei    = (const int*)  d_in[1];
    const float* sh    = (const float*)d_in[2];
    const float* attr  = (const float*)d_in[3];
    const float* Wpre0 = (const float*)d_in[4];
    const float* bpre0 = (const float*)d_in[5];
    const float* Wpre1 = (const float*)d_in[6];
    const float* Wg1   = (const float*)d_in[7];
    const float* bg1   = (const float*)d_in[8];
    const float* Wg2   = (const float*)d_in[9];
    const float* bg2   = (const float*)d_in[10];
    const float* Wn0   = (const float*)d_in[11];
    const float* bn0   = (const float*)d_in[12];
    const float* Wn1   = (const float*)d_in[13];
    const float* Wf1   = (const float*)d_in[14];
    const float* Wf2   = (const float*)d_in[15];
    const float* Wl1   = (const float*)d_in[16];
    const float* Wl2   = (const float*)d_in[17];
    const float* Wo0   = (const float*)d_in[18];
    const float* bo0   = (const float*)d_in[19];
    const float* Wo1   = (const float*)d_in[20];

    int N = in_sizes[0] / 256;
    int E = in_sizes[1] / 2;

    float *pre, *tmp, *xgp, *accp, *h1a, *h1l;
    cudaGetSymbolAddress((void**)&pre,  g_pre);
    cudaGetSymbolAddress((void**)&tmp,  g_tmp);
    cudaGetSymbolAddress((void**)&xgp,  g_xg);
    cudaGetSymbolAddress((void**)&accp, g_acc);
    cudaGetSymbolAddress((void**)&h1a,  g_h1a);
    cudaGetSymbolAddress((void**)&h1l,  g_h1l);

    static const int GATE_SMEM = (16384 * 2 + 2304 * 2) * 4;
    static const int EDGE_SMEM = (2 * 32 * 68 + 64 * 320 + 256 + 128) * 4;
    cudaFuncSetAttribute(gate_kernel, cudaFuncAttributeMaxDynamicSharedMemorySize, GATE_SMEM);
    cudaFuncSetAttribute(edge_kernel, cudaFuncAttributeMaxDynamicSharedMemorySize, EDGE_SMEM);

    prep_kernel<<<48, 256>>>(Wf2, Wl2, Wl1, Wpre0, Wpre1, Wn0, Wn1, Wo0, Wo1);
    // pre_x: std x -> quad pre
    e3_kernel<0, 1, 1><<<(N + 7) / 8, 256>>>(x, 0, bpre0, pre, nullptr, N);
    gate_kernel<<<(N + 15) / 16, 256, GATE_SMEM>>>(x, Wg1, bg1, Wg2, bg2, tmp, N);
    // xg quad, acc quad (= self_x)
    e3_kernel<1, 1, 1><<<(N + 7) / 8, 256>>>(tmp, 1, bn0, xgp, accp, N);
    h1a_kernel<<<(E + 63) / 64, 256>>>(attr, Wf1, h1a, E);
    h1l_kernel<<<(E + 31) / 32, 256>>>(ei, pre, h1l, E, E);
    edge_kernel<<<(E + TE - 1) / TE, 320, EDGE_SMEM>>>(ei, sh, h1a, h1l, xgp, accp, E, E);
    // final e3: quad acc -> std output
    e3_kernel<1, 0, 0><<<(N + 7) / 8, 256>>>(accp, 2, bo0, (float*)d_out, nullptr, N);
}

// round 4
// speedup vs baseline: 1.3021x; 1.2419x over previous
#include <cuda_runtime.h>
#include <math.h>

#define MAXN 20000
#define MAXE 320000

typedef unsigned long long ull;
typedef ulonglong2 ull2;

// ---------------- scratch (device globals) ---------------------------------
// All node tensors in QUAD layout: [n][u][4] = (s_u, v0_u, v1_u, v2_u)
__device__ float g_pre[MAXN * 256];
__device__ float g_tmp[MAXN * 256];
__device__ float g_xg [MAXN * 256];
__device__ float g_acc[MAXN * 256];
__device__ float g_h1a[MAXE * 32];
__device__ float g_h1l[MAXE * 32];
__device__ float g_WfT[320 * 32];   // Wf2^T * (1/sqrt32), [col][k]
__device__ float g_WlT[320 * 32];
__device__ float g_Wl1s[64 * 32];   // (Wl1[u]+Wl1[u+64]) / sqrt192
__device__ float g_Wl1i[64 * 32];   // Wl1[u+128] / sqrt192
__device__ ull   g_eW[3 * 4096];    // e3 packed (w0,w1)*0.125 for pre/n/o

__device__ __forceinline__ float sspf(float x) {
    float sp = (x > 15.f) ? x : log1pf(expf(x));
    return sp - 0.69314718055994531f;
}
__device__ __forceinline__ float siluf(float x) {
    return x / (1.f + expf(-x));
}
__device__ __forceinline__ ull pack2(float a, float b) {
    ull r; asm("mov.b64 %0, {%1, %2};" : "=l"(r) : "f"(a), "f"(b)); return r;
}
__device__ __forceinline__ void fma2(ull& d, ull a, ull b) {
    asm("fma.rn.f32x2 %0, %1, %2, %0;" : "+l"(d) : "l"(a), "l"(b));
}
__device__ __forceinline__ ull mul2(ull a, ull b) {
    ull r; asm("mul.rn.f32x2 %0, %1, %2;" : "=l"(r) : "l"(a), "l"(b)); return r;
}
__device__ __forceinline__ void unpack2(ull v, float& lo, float& hi) {
    asm("mov.b64 {%0, %1}, %2;" : "=f"(lo), "=f"(hi) : "l"(v));
}

// ---------------- weight prep ----------------------------------------------
__global__ void prep_kernel(const float* __restrict__ Wf2,
                            const float* __restrict__ Wl2,
                            const float* __restrict__ Wl1,
                            const float* __restrict__ Wpre0,
                            const float* __restrict__ Wpre1,
                            const float* __restrict__ Wn0,
                            const float* __restrict__ Wn1,
                            const float* __restrict__ Wo0,
                            const float* __restrict__ Wo1) {
    int i = blockIdx.x * 256 + threadIdx.x;
    const float is32 = 0.17677669529663687f;   // 1/sqrt(32)
    if (i < 320 * 32) {
        int c = i >> 5, k = i & 31;
        g_WfT[i] = Wf2[k * 320 + c] * is32;
        g_WlT[i] = Wl2[k * 320 + c] * is32;
    }
    if (i < 64 * 32) {
        const float r192 = 0.07216878364870323f;  // 1/sqrt(192)
        g_Wl1s[i] = (Wl1[i] + Wl1[64 * 32 + i]) * r192;
        g_Wl1i[i] = Wl1[128 * 32 + i] * r192;
    }
    if (i < 3 * 4096) {
        int p = i >> 12, r = i & 4095;
        const float* w0 = (p == 0) ? Wpre0 : (p == 1) ? Wn0 : Wo0;
        const float* w1 = (p == 0) ? Wpre1 : (p == 1) ? Wn1 : Wo1;
        g_eW[i] = pack2(w0[r] * 0.125f, w1[r] * 0.125f);
    }
}

// ---------------- e3_linear ------------------------------------------------
// IL/OL/OL2: 0 = standard layout (s[64] | v[u][3]), 1 = quad layout.
template<int IL, int OL, int OL2>
__global__ void e3_kernel(const float* __restrict__ in,
                          int widx,
                          const float* __restrict__ b0,
                          float* __restrict__ out,
                          float* __restrict__ out2, int nN) {
    __shared__ ull   Wp[4096];       // (w0,w1)*0.125 per (u,v)
    __shared__ float b0s[64];
    __shared__ float ins[8][256];    // quad
    int tid = threadIdx.x;
    {
        const ull2* src = (const ull2*)(g_eW + widx * 4096);
        ull2* dst = (ull2*)Wp;
        #pragma unroll
        for (int i = tid; i < 2048; i += 256) dst[i] = src[i];
    }
    if (tid < 64) b0s[tid] = b0[tid];
    int n0 = blockIdx.x * 8;
    if (IL == 0) {
        for (int i = tid; i < 2048; i += 256) {
            int nl = i >> 8, r = i & 255, u = r >> 2, c = r & 3;
            int n = n0 + nl;
            float val = 0.f;
            if (n < nN) {
                int f = (c == 0) ? u : 64 + u * 3 + (c - 1);
                val = in[n * 256 + f];
            }
            ins[nl][r] = val;
        }
    } else {
        for (int i = tid; i < 512; i += 256) {
            int nl = i >> 6, q = i & 63;
            int n = n0 + nl;
            float4 v = (n < nN) ? ((const float4*)(in + n * 256))[q]
                                : make_float4(0.f, 0.f, 0.f, 0.f);
            ((float4*)ins[nl])[q] = v;
        }
    }
    __syncthreads();
    int v = tid & 63, g = tid >> 6;     // g in [0,4): node pair (g*2, g*2+1)
    const ull2* rowA = (const ull2*)ins[g * 2];
    const ull2* rowB = (const ull2*)ins[g * 2 + 1];
    ull accA0 = 0, accA1 = 0, accB0 = 0, accB1 = 0;
    #pragma unroll 8
    for (int u = 0; u < 64; u++) {
        ull wp = Wp[u * 64 + v];
        float w0, w1; unpack2(wp, w0, w1);
        ull wq = pack2(w1, w1);
        ull2 qa = rowA[u];
        ull2 qb = rowB[u];
        fma2(accA0, wp, qa.x); fma2(accA1, wq, qa.y);
        fma2(accB0, wp, qb.x); fma2(accB1, wq, qb.y);
    }
    float bias = b0s[v];
    #pragma unroll
    for (int t = 0; t < 2; t++) {
        int n = n0 + g * 2 + t;
        if (n >= nN) continue;
        float s, o0, o1, o2;
        unpack2(t ? accB0 : accA0, s, o0);
        unpack2(t ? accB1 : accA1, o1, o2);
        s += bias;
        if (OL == 0) {
            float* po = out + n * 256;
            po[v] = s;
            po[64 + v * 3 + 0] = o0; po[64 + v * 3 + 1] = o1; po[64 + v * 3 + 2] = o2;
        } else {
            ((float4*)(out + n * 256))[v] = make_float4(s, o0, o1, o2);
        }
        if (out2) {
            if (OL2 == 0) {
                float* p2 = out2 + n * 256;
                p2[v] = s;
                p2[64 + v * 3 + 0] = o0; p2[64 + v * 3 + 1] = o1; p2[64 + v * 3 + 2] = o2;
            } else {
                ((float4*)(out2 + n * 256))[v] = make_float4(s, o0, o1, o2);
            }
        }
    }
}

// ---------------- gate MLP (f32x2, 16 nodes/block) -> quad output ----------
__global__ void gate_kernel(const float* __restrict__ x,
                            const float* __restrict__ Wg1,
                            const float* __restrict__ bg1,
                            const float* __restrict__ Wg2,
                            const float* __restrict__ bg2,
                            float* __restrict__ outb, int nN) {
    extern __shared__ float sm[];
    float* W1s = sm;                 // 16384
    float* W2s = sm + 16384;         // 16384
    float* f0t = sm + 32768;         // 2304 (transposed input; later g staging)
    float* hst = sm + 32768 + 2304;  // 2304
    int tid = threadIdx.x;
    for (int i = tid; i < 16384; i += 256) { W1s[i] = Wg1[i]; W2s[i] = Wg2[i]; }
    int n0 = blockIdx.x * 16;
    for (int i = tid; i < 2048; i += 256) {
        int nl = i & 15, j = i >> 4;
        int n = n0 + nl;
        float val = 0.f;
        if (n < nN) {
            const float* xr = x + n * 256;
            if (j < 64) val = xr[j];
            else {
                int u = j - 64;
                float v0 = xr[64 + u * 3], v1 = xr[64 + u * 3 + 1], v2 = xr[64 + u * 3 + 2];
                val = sqrtf(v0 * v0 + v1 * v1 + v2 * v2 + 1e-12f);
            }
        }
        f0t[j * 18 + nl] = val;
    }
    __syncthreads();
    int j = tid & 127, half = tid >> 7;
    {
        ull a0 = 0, a1 = 0, a2 = 0, a3 = 0;
        #pragma unroll 8
        for (int k = 0; k < 128; k++) {
            float w = W1s[k * 128 + j];
            ull wp = pack2(w, w);
            const ull* f = (const ull*)&f0t[k * 18 + half * 8];
            fma2(a0, wp, f[0]); fma2(a1, wp, f[1]); fma2(a2, wp, f[2]); fma2(a3, wp, f[3]);
        }
        float b = bg1[j];
        float lo, hi;
        unpack2(a0, lo, hi); hst[j * 18 + half * 8 + 0] = siluf(lo + b); hst[j * 18 + half * 8 + 1] = siluf(hi + b);
        unpack2(a1, lo, hi); hst[j * 18 + half * 8 + 2] = siluf(lo + b); hst[j * 18 + half * 8 + 3] = siluf(hi + b);
        unpack2(a2, lo, hi); hst[j * 18 + half * 8 + 4] = siluf(lo + b); hst[j * 18 + half * 8 + 5] = siluf(hi + b);
        unpack2(a3, lo, hi); hst[j * 18 + half * 8 + 6] = siluf(lo + b); hst[j * 18 + half * 8 + 7] = siluf(hi + b);
    }
    __syncthreads();
    float g[8];
    {
        ull a0 = 0, a1 = 0, a2 = 0, a3 = 0;
        #pragma unroll 8
        for (int k = 0; k < 128; k++) {
            float w = W2s[k * 128 + j];
            ull wp = pack2(w, w);
            const ull* h = (const ull*)&hst[k * 18 + half * 8];
            fma2(a0, wp, h[0]); fma2(a1, wp, h[1]); fma2(a2, wp, h[2]); fma2(a3, wp, h[3]);
        }
        float b = bg2[j];
        unpack2(a0, g[0], g[1]); unpack2(a1, g[2], g[3]);
        unpack2(a2, g[4], g[5]); unpack2(a3, g[6], g[7]);
        #pragma unroll
        for (int p = 0; p < 8; p++) g[p] += b;
    }
    __syncthreads();
    #pragma unroll
    for (int p = 0; p < 8; p++) f0t[(half * 8 + p) * 128 + j] = g[p];
    __syncthreads();
    for (int q = tid; q < 1024; q += 256) {
        int nl = q >> 6, u = q & 63;
        int n = n0 + nl;
        if (n >= nN) continue;
        float gs = f0t[nl * 128 + u];
        float gv = f0t[nl * 128 + 64 + u];
        const float* xr = x + n * 256 + 64 + u * 3;
        ((float4*)(outb + n * 256))[u] = make_float4(gs, xr[0] * gv, xr[1] * gv, xr[2] * gv);
    }
}

// ---------------- h1a = ssp(edge_attr @ Wf1 / 8) ---------------------------
__global__ void h1a_kernel(const float* __restrict__ attr,
                           const float* __restrict__ Wf1,
                           float* __restrict__ h1a, int nE) {
    __shared__ float at[64 * 68];     // [u][edge], pad 68
    __shared__ float Wf1s[64 * 32];
    int tid = threadIdx.x;
    int e0 = blockIdx.x * 64;
    for (int i = tid; i < 2048; i += 256) Wf1s[i] = Wf1[i];
    for (int i = tid; i < 4096; i += 256) {
        int el = i >> 6, u = i & 63;
        int e = e0 + el;
        at[u * 68 + el] = (e < nE) ? attr[e * 64 + u] : 0.f;
    }
    __syncthreads();
    int k = tid & 31, g = tid >> 5;   // 8 groups x 8 edges
    ull a0 = 0, a1 = 0, a2 = 0, a3 = 0;
    #pragma unroll 4
    for (int u = 0; u < 64; u++) {
        float w = Wf1s[u * 32 + k];
        ull wp = pack2(w, w);
        const ull2* pa = (const ull2*)(at + u * 68 + g * 8);
        ull2 A0 = pa[0], A1 = pa[1];
        fma2(a0, wp, A0.x); fma2(a1, wp, A0.y);
        fma2(a2, wp, A1.x); fma2(a3, wp, A1.y);
    }
    float r[8];
    unpack2(a0, r[0], r[1]); unpack2(a1, r[2], r[3]);
    unpack2(a2, r[4], r[5]); unpack2(a3, r[6], r[7]);
    #pragma unroll
    for (int ee = 0; ee < 8; ee++) {
        int e = e0 + g * 8 + ee;
        if (e < nE) h1a[e * 32 + k] = sspf(r[ee] * 0.125f);
    }
}

// ---------------- h1l = ssp(s0 @ Wl1 / sqrt192), quad pre gathers ----------
__global__ void h1l_kernel(const int* __restrict__ ei,
                           const float* __restrict__ pre,
                           float* __restrict__ h1l, int nE, int Etot) {
    __shared__ float ps_t[64 * 36];   // [u][edge], 32 edges pad 36
    __shared__ float ip_t[64 * 36];
    __shared__ float Ws[64 * 32];
    __shared__ float Wi[64 * 32];
    __shared__ int dsts[32], srcs[32];
    int tid = threadIdx.x;
    int e0 = blockIdx.x * 32;
    for (int i = tid; i < 2048; i += 256) { Ws[i] = g_Wl1s[i]; Wi[i] = g_Wl1i[i]; }
    if (tid < 32) {
        int e = e0 + tid;
        dsts[tid] = (e < nE) ? ei[e] : 0;
        srcs[tid] = (e < nE) ? ei[Etot + e] : 0;
    }
    __syncthreads();
    for (int i = tid; i < 2048; i += 256) {
        int el = i >> 6, u = i & 63;
        int e = e0 + el;
        float psv = 0.f, ipv = 0.f;
        if (e < nE) {
            int d = dsts[el], s = srcs[el];
            float4 qd = *(const float4*)&pre[d * 256 + u * 4];
            float4 qs = *(const float4*)&pre[s * 256 + u * 4];
            psv = qd.x;
            ipv = (qd.y * qs.y + qd.z * qs.z + qd.w * qs.w) * (1.f / 3.f);
        }
        ps_t[u * 36 + el] = psv;
        ip_t[u * 36 + el] = ipv;
    }
    __syncthreads();
    int k = tid & 31, g = tid >> 5;   // 8 groups x 4 edges
    ull a0 = 0, a1 = 0;
    #pragma unroll 4
    for (int u = 0; u < 64; u++) {
        float ws = Ws[u * 32 + k];
        float wi = Wi[u * 32 + k];
        ull wps = pack2(ws, ws), wpi = pack2(wi, wi);
        ull2 P = *(const ull2*)(ps_t + u * 36 + g * 4);
        ull2 I = *(const ull2*)(ip_t + u * 36 + g * 4);
        fma2(a0, wps, P.x); fma2(a1, wps, P.y);
        fma2(a0, wpi, I.x); fma2(a1, wpi, I.y);
    }
    float r[4];
    unpack2(a0, r[0], r[1]); unpack2(a1, r[2], r[3]);
    #pragma unroll
    for (int ee = 0; ee < 4; ee++) {
        int e = e0 + g * 4 + ee;
        if (e < nE) h1l[e * 32 + k] = sspf(r[ee]);
    }
}

// ---------------- fused edge kernel ----------------------------------------
// Weights in FLOAT regs (64), splat packed on the fly -> no register spill.
#define TE 64
__global__ void __launch_bounds__(320, 2)
edge_kernel(const int* __restrict__ ei,
            const float* __restrict__ sh,
            const float* __restrict__ h1a,
            const float* __restrict__ h1l,
            const float* __restrict__ xg,
            float* __restrict__ acc, int nE, int Etot) {
    extern __shared__ float sm[];
    float* hA  = sm;                     // 32 * 68
    float* hB  = sm + 32 * 68;           // 32 * 68
    float* ws  = sm + 2 * 32 * 68;       // 64 * 320
    float* shs = ws + 64 * 320;          // 64 * 4
    int*   idxs = (int*)(shs + 256);     // src[64] | dst[64]
    int tid = threadIdx.x;
    int e0 = blockIdx.x * TE;
    if (tid < 64) {
        int e = e0 + tid;
        bool v = (e < nE);
        idxs[tid]      = v ? ei[Etot + e] : 0;
        idxs[64 + tid] = v ? ei[e] : -1;
        float4 s4 = v ? *(const float4*)&sh[e * 4] : make_float4(0.f, 0.f, 0.f, 0.f);
        ((float4*)shs)[tid] = s4;
    }
    for (int i = tid; i < 2048; i += 320) {
        int el = i >> 5, k = i & 31;
        int e = e0 + el;
        float a = 0.f, b = 0.f;
        if (e < nE) { a = h1a[e * 32 + k]; b = h1l[e * 32 + k]; }
        hA[k * 68 + el] = a;
        hB[k * 68 + el] = b;
    }
    // weight columns in float registers (64 regs total)
    int c = tid;
    float wf[32], wl[32];
    {
        const float4* pf = (const float4*)(g_WfT + c * 32);
        const float4* pl = (const float4*)(g_WlT + c * 32);
        #pragma unroll
        for (int q = 0; q < 8; q++) {
            float4 f = pf[q];
            wf[q * 4] = f.x; wf[q * 4 + 1] = f.y; wf[q * 4 + 2] = f.z; wf[q * 4 + 3] = f.w;
            float4 l = pl[q];
            wl[q * 4] = l.x; wl[q * 4 + 1] = l.y; wl[q * 4 + 2] = l.z; wl[q * 4 + 3] = l.w;
        }
    }
    __syncthreads();
    // phase 1: 4 edges per group, pack splats on the fly
    #pragma unroll 1
    for (int eg = 0; eg < 16; eg++) {
        ull aA0 = 0, aA1 = 0, aB0 = 0, aB1 = 0;
        const float* bA = hA + eg * 4;
        const float* bB = hB + eg * 4;
        #pragma unroll
        for (int k = 0; k < 32; k++) {
            ull2 A = *(const ull2*)(bA + k * 68);
            ull2 B = *(const ull2*)(bB + k * 68);
            ull wfp = pack2(wf[k], wf[k]);
            ull wlp = pack2(wl[k], wl[k]);
            fma2(aA0, wfp, A.x); fma2(aA1, wfp, A.y);
            fma2(aB0, wlp, B.x); fma2(aB1, wlp, B.y);
        }
        float lo, hi;
        unpack2(mul2(aA0, aB0), lo, hi);
        ws[(eg * 4 + 0) * 320 + c] = lo; ws[(eg * 4 + 1) * 320 + c] = hi;
        unpack2(mul2(aA1, aB1), lo, hi);
        ws[(eg * 4 + 2) * 320 + c] = lo; ws[(eg * 4 + 3) * 320 + c] = hi;
    }
    __syncthreads();
    // phase 2: tensor product + red.v4 scatter, all 320 threads
    {
        const float PW_S = 0.44721359549995793f;
        const float PW_V = 0.77459666924148337f;
        const float IS3  = 0.57735026918962576f;
        const float IS2  = 0.70710678118654752f;
        for (int it = tid; it < TE * 64; it += 320) {
            int e = it >> 6, u = it & 63;
            int d = idxs[64 + e];
            if (d < 0) continue;
            int s = idxs[e];
            float4 q = *(const float4*)&xg[s * 256 + u * 4];
            float es = q.x, ev0 = q.y, ev1 = q.z, ev2 = q.w;
            float s0 = shs[e * 4], s1 = shs[e * 4 + 1], s2 = shs[e * 4 + 2], s3 = shs[e * 4 + 3];
            const float* we = ws + e * 320;
            float w0 = we[u], w1 = we[64 + u], w2 = we[128 + u], w3 = we[192 + u], w4 = we[256 + u];
            float dotv = ev0 * s1 + ev1 * s2 + ev2 * s3;
            float c0 = ev1 * s3 - ev2 * s2;
            float c1 = ev2 * s1 - ev0 * s3;
            float c2 = ev0 * s2 - ev1 * s1;
            float outs = PW_S * (w0 * es * s0 + w3 * dotv * IS3);
            float k2 = PW_V * w2 * s0;
            float k4 = PW_V * w4 * IS2;
            float k1 = PW_V * w1 * es;
            float o0 = k1 * s1 + k2 * ev0 + k4 * c0;
            float o1 = k1 * s2 + k2 * ev1 + k4 * c1;
            float o2 = k1 * s3 + k2 * ev2 + k4 * c2;
            float* pa = acc + d * 256 + u * 4;
            asm volatile("red.global.add.v4.f32 [%0], {%1, %2, %3, %4};"
                         :: "l"(pa), "f"(outs), "f"(o0), "f"(o1), "f"(o2) : "memory");
        }
    }
}

// ---------------- launch ----------------------------------------------------
extern "C" void kernel_launch(void* const* d_in, const int* in_sizes, int n_in,
                              void* d_out, int out_size) {
    const float* x     = (const float*)d_in[0];
    const int*   ei    = (const int*)  d_in[1];
    const float* sh    = (const float*)d_in[2];
    const float* attr  = (const float*)d_in[3];
    const float* Wpre0 = (const float*)d_in[4];
    const float* bpre0 = (const float*)d_in[5];
    const float* Wpre1 = (const float*)d_in[6];
    const float* Wg1   = (const float*)d_in[7];
    const float* bg1   = (const float*)d_in[8];
    const float* Wg2   = (const float*)d_in[9];
    const float* bg2   = (const float*)d_in[10];
    const float* Wn0   = (const float*)d_in[11];
    const float* bn0   = (const float*)d_in[12];
    const float* Wn1   = (const float*)d_in[13];
    const float* Wf1   = (const float*)d_in[14];
    const float* Wf2   = (const float*)d_in[15];
    const float* Wl1   = (const float*)d_in[16];
    const float* Wl2   = (const float*)d_in[17];
    const float* Wo0   = (const float*)d_in[18];
    const float* bo0   = (const float*)d_in[19];
    const float* Wo1   = (const float*)d_in[20];

    int N = in_sizes[0] / 256;
    int E = in_sizes[1] / 2;

    float *pre, *tmp, *xgp, *accp, *h1a, *h1l;
    cudaGetSymbolAddress((void**)&pre,  g_pre);
    cudaGetSymbolAddress((void**)&tmp,  g_tmp);
    cudaGetSymbolAddress((void**)&xgp,  g_xg);
    cudaGetSymbolAddress((void**)&accp, g_acc);
    cudaGetSymbolAddress((void**)&h1a,  g_h1a);
    cudaGetSymbolAddress((void**)&h1l,  g_h1l);

    static const int GATE_SMEM = (16384 * 2 + 2304 * 2) * 4;
    static const int EDGE_SMEM = (2 * 32 * 68 + 64 * 320 + 256 + 128) * 4;
    cudaFuncSetAttribute(gate_kernel, cudaFuncAttributeMaxDynamicSharedMemorySize, GATE_SMEM);
    cudaFuncSetAttribute(edge_kernel, cudaFuncAttributeMaxDynamicSharedMemorySize, EDGE_SMEM);

    prep_kernel<<<48, 256>>>(Wf2, Wl2, Wl1, Wpre0, Wpre1, Wn0, Wn1, Wo0, Wo1);
    e3_kernel<0, 1, 1><<<(N + 7) / 8, 256>>>(x, 0, bpre0, pre, nullptr, N);
    gate_kernel<<<(N + 15) / 16, 256, GATE_SMEM>>>(x, Wg1, bg1, Wg2, bg2, tmp, N);
    e3_kernel<1, 1, 1><<<(N + 7) / 8, 256>>>(tmp, 1, bn0, xgp, accp, N);
    h1a_kernel<<<(E + 63) / 64, 256>>>(attr, Wf1, h1a, E);
    h1l_kernel<<<(E + 31) / 32, 256>>>(ei, pre, h1l, E, E);
    edge_kernel<<<(E + TE - 1) / TE, 320, EDGE_SMEM>>>(ei, sh, h1a, h1l, xgp, accp, E, E);
    e3_kernel<1, 0, 0><<<(N + 7) / 8, 256>>>(accp, 2, bo0, (float*)d_out, nullptr, N);
}

// round 5
// speedup vs baseline: 1.5349x; 1.1788x over previous
#include <cuda_runtime.h>
#include <math.h>

#define MAXN 20000
#define MAXE 320000

typedef unsigned long long ull;
typedef ulonglong2 ull2;

// ---------------- scratch (device globals) ---------------------------------
// All node tensors in QUAD layout: [n][u][4] = (s_u, v0_u, v1_u, v2_u)
__device__ float g_pre[MAXN * 256];
__device__ float g_tmp[MAXN * 256];
__device__ float g_xg [MAXN * 256];
__device__ float g_acc[MAXN * 256];
__device__ float g_h1a[MAXE * 32];
__device__ float g_h1l[MAXE * 32];
__device__ float g_WfT[320 * 32];   // Wf2^T * (1/sqrt32), [col][k]
__device__ float g_WlT[320 * 32];
__device__ float g_Wl1s[64 * 32];   // (Wl1[u]+Wl1[u+64]) / sqrt192
__device__ float g_Wl1i[64 * 32];   // Wl1[u+128] / sqrt192
__device__ ull   g_eW[3 * 4096];    // e3 packed (w0,w1)*0.125 for pre/n/o

__device__ __forceinline__ float sspf(float x) {
    float sp = (x > 15.f) ? x : log1pf(expf(x));
    return sp - 0.69314718055994531f;
}
__device__ __forceinline__ float siluf(float x) {
    return x / (1.f + expf(-x));
}
__device__ __forceinline__ ull pack2(float a, float b) {
    ull r; asm("mov.b64 %0, {%1, %2};" : "=l"(r) : "f"(a), "f"(b)); return r;
}
__device__ __forceinline__ void fma2(ull& d, ull a, ull b) {
    asm("fma.rn.f32x2 %0, %1, %2, %0;" : "+l"(d) : "l"(a), "l"(b));
}
__device__ __forceinline__ ull mul2(ull a, ull b) {
    ull r; asm("mul.rn.f32x2 %0, %1, %2;" : "=l"(r) : "l"(a), "l"(b)); return r;
}
__device__ __forceinline__ void unpack2(ull v, float& lo, float& hi) {
    asm("mov.b64 {%0, %1}, %2;" : "=f"(lo), "=f"(hi) : "l"(v));
}

// ---------------- weight prep ----------------------------------------------
__global__ void prep_kernel(const float* __restrict__ Wf2,
                            const float* __restrict__ Wl2,
                            const float* __restrict__ Wl1,
                            const float* __restrict__ Wpre0,
                            const float* __restrict__ Wpre1,
                            const float* __restrict__ Wn0,
                            const float* __restrict__ Wn1,
                            const float* __restrict__ Wo0,
                            const float* __restrict__ Wo1) {
    int i = blockIdx.x * 256 + threadIdx.x;
    const float is32 = 0.17677669529663687f;   // 1/sqrt(32)
    if (i < 320 * 32) {
        int c = i >> 5, k = i & 31;
        g_WfT[i] = Wf2[k * 320 + c] * is32;
        g_WlT[i] = Wl2[k * 320 + c] * is32;
    }
    if (i < 64 * 32) {
        const float r192 = 0.07216878364870323f;  // 1/sqrt(192)
        g_Wl1s[i] = (Wl1[i] + Wl1[64 * 32 + i]) * r192;
        g_Wl1i[i] = Wl1[128 * 32 + i] * r192;
    }
    if (i < 3 * 4096) {
        int p = i >> 12, r = i & 4095;
        const float* w0 = (p == 0) ? Wpre0 : (p == 1) ? Wn0 : Wo0;
        const float* w1 = (p == 0) ? Wpre1 : (p == 1) ? Wn1 : Wo1;
        g_eW[i] = pack2(w0[r] * 0.125f, w1[r] * 0.125f);
    }
}

// ---------------- e3_linear: 16 nodes/block, dynamic smem -------------------
// IL/OL/OL2: 0 = standard layout (s[64] | v[u][3]), 1 = quad layout.
template<int IL, int OL, int OL2>
__global__ void e3_kernel(const float* __restrict__ in,
                          int widx,
                          const float* __restrict__ b0,
                          float* __restrict__ out,
                          float* __restrict__ out2, int nN) {
    extern __shared__ float sme3[];
    ull*   Wp  = (ull*)sme3;             // 4096 ull = 32 KB
    float* ins = sme3 + 8192;            // 16*256 = 16 KB
    float* b0s = sme3 + 8192 + 4096;     // 64
    int tid = threadIdx.x;
    {
        const ull2* src = (const ull2*)(g_eW + widx * 4096);
        ull2* dst = (ull2*)Wp;
        for (int i = tid; i < 2048; i += 256) dst[i] = src[i];
    }
    if (tid < 64) b0s[tid] = b0[tid];
    int n0 = blockIdx.x * 16;
    if (IL == 0) {
        for (int i = tid; i < 4096; i += 256) {
            int nl = i >> 8, r = i & 255, u = r >> 2, c = r & 3;
            int n = n0 + nl;
            float val = 0.f;
            if (n < nN) {
                int f = (c == 0) ? u : 64 + u * 3 + (c - 1);
                val = in[n * 256 + f];
            }
            ins[nl * 256 + r] = val;
        }
    } else {
        for (int i = tid; i < 1024; i += 256) {
            int nl = i >> 6, q = i & 63;
            int n = n0 + nl;
            float4 v = (n < nN) ? ((const float4*)(in + n * 256))[q]
                                : make_float4(0.f, 0.f, 0.f, 0.f);
            ((float4*)(ins + nl * 256))[q] = v;
        }
    }
    __syncthreads();
    int v = tid & 63, g = tid >> 6;       // g handles nodes g*4 .. g*4+3
    const float* base = ins + g * 4 * 256;
    ull acc[4][2] = {};
    #pragma unroll 4
    for (int u = 0; u < 64; u++) {
        ull wp = Wp[u * 64 + v];
        float w0, w1; unpack2(wp, w0, w1);
        ull wq = pack2(w1, w1);
        #pragma unroll
        for (int t = 0; t < 4; t++) {
            ull2 q = *(const ull2*)(base + t * 256 + u * 4);
            fma2(acc[t][0], wp, q.x);
            fma2(acc[t][1], wq, q.y);
        }
    }
    float bias = b0s[v];
    #pragma unroll
    for (int t = 0; t < 4; t++) {
        int n = n0 + g * 4 + t;
        if (n >= nN) continue;
        float s, o0, o1, o2;
        unpack2(acc[t][0], s, o0);
        unpack2(acc[t][1], o1, o2);
        s += bias;
        if (OL == 0) {
            float* po = out + n * 256;
            po[v] = s;
            po[64 + v * 3 + 0] = o0; po[64 + v * 3 + 1] = o1; po[64 + v * 3 + 2] = o2;
        } else {
            ((float4*)(out + n * 256))[v] = make_float4(s, o0, o1, o2);
        }
        if (out2) {
            if (OL2 == 0) {
                float* p2 = out2 + n * 256;
                p2[v] = s;
                p2[64 + v * 3 + 0] = o0; p2[64 + v * 3 + 1] = o1; p2[64 + v * 3 + 2] = o2;
            } else {
                ((float4*)(out2 + n * 256))[v] = make_float4(s, o0, o1, o2);
            }
        }
    }
}

// ---------------- gate MLP (f32x2, 32 nodes/block, 512 thr) -> quad output --
__global__ void gate_kernel(const float* __restrict__ x,
                            const float* __restrict__ Wg1,
                            const float* __restrict__ bg1,
                            const float* __restrict__ Wg2,
                            const float* __restrict__ bg2,
                            float* __restrict__ outb, int nN) {
    extern __shared__ float sm[];
    float* W1s = sm;                 // 16384
    float* W2s = sm + 16384;         // 16384
    float* f0t = sm + 32768;         // 128*34 = 4352
    float* hst = sm + 32768 + 4352;  // 4352
    int tid = threadIdx.x;
    for (int i = tid; i < 4096; i += 512) {
        ((float4*)W1s)[i] = ((const float4*)Wg1)[i];
        ((float4*)W2s)[i] = ((const float4*)Wg2)[i];
    }
    int n0 = blockIdx.x * 32;
    // stage f0 transposed: f0t[j*34 + nl], nl in [0,32)
    for (int i = tid; i < 4096; i += 512) {
        int nl = i >> 7, j = i & 127;
        int n = n0 + nl;
        float val = 0.f;
        if (n < nN) {
            const float* xr = x + n * 256;
            if (j < 64) val = xr[j];
            else {
                int u = j - 64;
                float v0 = xr[64 + u * 3], v1 = xr[64 + u * 3 + 1], v2 = xr[64 + u * 3 + 2];
                val = sqrtf(v0 * v0 + v1 * v1 + v2 * v2 + 1e-12f);
            }
        }
        f0t[j * 34 + nl] = val;
    }
    __syncthreads();
    int j = tid & 127, quarter = tid >> 7;   // quarter handles nodes [q*8, q*8+8)
    {
        ull a0 = 0, a1 = 0, a2 = 0, a3 = 0;
        #pragma unroll 8
        for (int k = 0; k < 128; k++) {
            float w = W1s[k * 128 + j];
            ull wp = pack2(w, w);
            const ull* f = (const ull*)&f0t[k * 34 + quarter * 8];
            fma2(a0, wp, f[0]); fma2(a1, wp, f[1]); fma2(a2, wp, f[2]); fma2(a3, wp, f[3]);
        }
        float b = bg1[j];
        float lo, hi;
        unpack2(a0, lo, hi); hst[j * 34 + quarter * 8 + 0] = siluf(lo + b); hst[j * 34 + quarter * 8 + 1] = siluf(hi + b);
        unpack2(a1, lo, hi); hst[j * 34 + quarter * 8 + 2] = siluf(lo + b); hst[j * 34 + quarter * 8 + 3] = siluf(hi + b);
        unpack2(a2, lo, hi); hst[j * 34 + quarter * 8 + 4] = siluf(lo + b); hst[j * 34 + quarter * 8 + 5] = siluf(hi + b);
        unpack2(a3, lo, hi); hst[j * 34 + quarter * 8 + 6] = siluf(lo + b); hst[j * 34 + quarter * 8 + 7] = siluf(hi + b);
    }
    __syncthreads();
    float g[8];
    {
        ull a0 = 0, a1 = 0, a2 = 0, a3 = 0;
        #pragma unroll 8
        for (int k = 0; k < 128; k++) {
            float w = W2s[k * 128 + j];
            ull wp = pack2(w, w);
            const ull* h = (const ull*)&hst[k * 34 + quarter * 8];
            fma2(a0, wp, h[0]); fma2(a1, wp, h[1]); fma2(a2, wp, h[2]); fma2(a3, wp, h[3]);
        }
        float b = bg2[j];
        unpack2(a0, g[0], g[1]); unpack2(a1, g[2], g[3]);
        unpack2(a2, g[4], g[5]); unpack2(a3, g[6], g[7]);
        #pragma unroll
        for (int p = 0; p < 8; p++) g[p] += b;
    }
    __syncthreads();
    #pragma unroll
    for (int p = 0; p < 8; p++) f0t[(quarter * 8 + p) * 128 + j] = g[p];
    __syncthreads();
    for (int q = tid; q < 2048; q += 512) {
        int nl = q >> 6, u = q & 63;
        int n = n0 + nl;
        if (n >= nN) continue;
        float gs = f0t[nl * 128 + u];
        float gv = f0t[nl * 128 + 64 + u];
        const float* xr = x + n * 256 + 64 + u * 3;
        ((float4*)(outb + n * 256))[u] = make_float4(gs, xr[0] * gv, xr[1] * gv, xr[2] * gv);
    }
}

// ---------------- h1a = ssp(edge_attr @ Wf1 / 8) ---------------------------
__global__ void h1a_kernel(const float* __restrict__ attr,
                           const float* __restrict__ Wf1,
                           float* __restrict__ h1a, int nE) {
    __shared__ float at[64 * 68];     // [u][edge], pad 68
    __shared__ float Wf1s[64 * 32];
    int tid = threadIdx.x;
    int e0 = blockIdx.x * 64;
    for (int i = tid; i < 512; i += 256)
        ((float4*)Wf1s)[i] = ((const float4*)Wf1)[i];
    for (int i = tid; i < 1024; i += 256) {
        int el = i >> 4, u0 = (i & 15) * 4;
        int e = e0 + el;
        float4 a4 = (e < nE) ? *(const float4*)&attr[e * 64 + u0]
                             : make_float4(0.f, 0.f, 0.f, 0.f);
        at[(u0 + 0) * 68 + el] = a4.x;
        at[(u0 + 1) * 68 + el] = a4.y;
        at[(u0 + 2) * 68 + el] = a4.z;
        at[(u0 + 3) * 68 + el] = a4.w;
    }
    __syncthreads();
    int k = tid & 31, g = tid >> 5;   // 8 groups x 8 edges
    ull a0 = 0, a1 = 0, a2 = 0, a3 = 0;
    #pragma unroll 4
    for (int u = 0; u < 64; u++) {
        float w = Wf1s[u * 32 + k];
        ull wp = pack2(w, w);
        const ull2* pa = (const ull2*)(at + u * 68 + g * 8);
        ull2 A0 = pa[0], A1 = pa[1];
        fma2(a0, wp, A0.x); fma2(a1, wp, A0.y);
        fma2(a2, wp, A1.x); fma2(a3, wp, A1.y);
    }
    float r[8];
    unpack2(a0, r[0], r[1]); unpack2(a1, r[2], r[3]);
    unpack2(a2, r[4], r[5]); unpack2(a3, r[6], r[7]);
    #pragma unroll
    for (int ee = 0; ee < 8; ee++) {
        int e = e0 + g * 8 + ee;
        if (e < nE) h1a[e * 32 + k] = sspf(r[ee] * 0.125f);
    }
}

// ---------------- h1l = ssp(s0 @ Wl1 / sqrt192), 64 edges/block -------------
__global__ void h1l_kernel(const int* __restrict__ ei,
                           const float* __restrict__ pre,
                           float* __restrict__ h1l, int nE, int Etot) {
    extern __shared__ float smh[];
    float* ps_t = smh;                 // 64*68
    float* ip_t = smh + 4352;          // 64*68
    float* Ws   = smh + 8704;          // 2048
    float* Wi   = smh + 10752;         // 2048
    int*   idx  = (int*)(smh + 12800); // dst[64] | src[64]
    int tid = threadIdx.x;
    int e0 = blockIdx.x * 64;
    for (int i = tid; i < 512; i += 256) {
        ((float4*)Ws)[i] = ((const float4*)g_Wl1s)[i];
        ((float4*)Wi)[i] = ((const float4*)g_Wl1i)[i];
    }
    if (tid < 64) {
        int e = e0 + tid;
        bool v = (e < nE);
        idx[tid]      = v ? ei[e] : 0;
        idx[64 + tid] = v ? ei[Etot + e] : 0;
    }
    __syncthreads();
    for (int i = tid; i < 4096; i += 256) {
        int u = i & 63, el = i >> 6;
        int d = idx[el], s = idx[64 + el];
        float4 qd = *(const float4*)&pre[d * 256 + u * 4];
        float4 qs = *(const float4*)&pre[s * 256 + u * 4];
        ps_t[u * 68 + el] = qd.x;
        ip_t[u * 68 + el] = (qd.y * qs.y + qd.z * qs.z + qd.w * qs.w) * (1.f / 3.f);
    }
    __syncthreads();
    int k = tid & 31, g = tid >> 5;   // 8 groups x 8 edges
    ull a[4] = {};
    #pragma unroll 4
    for (int u = 0; u < 64; u++) {
        float ws = Ws[u * 32 + k];
        float wi = Wi[u * 32 + k];
        ull wps = pack2(ws, ws), wpi = pack2(wi, wi);
        const ull2* P = (const ull2*)(ps_t + u * 68 + g * 8);
        const ull2* I = (const ull2*)(ip_t + u * 68 + g * 8);
        ull2 P0 = P[0], P1 = P[1], I0 = I[0], I1 = I[1];
        fma2(a[0], wps, P0.x); fma2(a[1], wps, P0.y);
        fma2(a[2], wps, P1.x); fma2(a[3], wps, P1.y);
        fma2(a[0], wpi, I0.x); fma2(a[1], wpi, I0.y);
        fma2(a[2], wpi, I1.x); fma2(a[3], wpi, I1.y);
    }
    float r[8];
    unpack2(a[0], r[0], r[1]); unpack2(a[1], r[2], r[3]);
    unpack2(a[2], r[4], r[5]); unpack2(a[3], r[6], r[7]);
    #pragma unroll
    for (int ee = 0; ee < 8; ee++) {
        int e = e0 + g * 8 + ee;
        if (e < nE) h1l[e * 32 + k] = sspf(r[ee]);
    }
}

// ---------------- fused edge kernel ----------------------------------------
#define TE 64
__global__ void __launch_bounds__(320, 2)
edge_kernel(const int* __restrict__ ei,
            const float* __restrict__ sh,
            const float* __restrict__ h1a,
            const float* __restrict__ h1l,
            const float* __restrict__ xg,
            float* __restrict__ acc, int nE, int Etot) {
    extern __shared__ float sm[];
    float* hA  = sm;                     // 32 * 68
    float* hB  = sm + 32 * 68;           // 32 * 68
    float* ws  = sm + 2 * 32 * 68;       // 64 * 320
    float* shs = ws + 64 * 320;          // 64 * 4
    int*   idxs = (int*)(shs + 256);     // src[64] | dst[64]
    int tid = threadIdx.x;
    int e0 = blockIdx.x * TE;
    if (tid < 64) {
        int e = e0 + tid;
        bool v = (e < nE);
        idxs[tid]      = v ? ei[Etot + e] : 0;
        idxs[64 + tid] = v ? ei[e] : -1;
        float4 s4 = v ? *(const float4*)&sh[e * 4] : make_float4(0.f, 0.f, 0.f, 0.f);
        ((float4*)shs)[tid] = s4;
    }
    for (int i = tid; i < 512; i += 320) {
        int el = i >> 3, k0 = (i & 7) * 4;
        int e = e0 + el;
        float4 a = make_float4(0.f, 0.f, 0.f, 0.f), b = a;
        if (e < nE) {
            a = *(const float4*)&h1a[e * 32 + k0];
            b = *(const float4*)&h1l[e * 32 + k0];
        }
        hA[(k0 + 0) * 68 + el] = a.x; hA[(k0 + 1) * 68 + el] = a.y;
        hA[(k0 + 2) * 68 + el] = a.z; hA[(k0 + 3) * 68 + el] = a.w;
        hB[(k0 + 0) * 68 + el] = b.x; hB[(k0 + 1) * 68 + el] = b.y;
        hB[(k0 + 2) * 68 + el] = b.z; hB[(k0 + 3) * 68 + el] = b.w;
    }
    // weight columns in float registers (64 regs total)
    int c = tid;
    float wf[32], wl[32];
    {
        const float4* pf = (const float4*)(g_WfT + c * 32);
        const float4* pl = (const float4*)(g_WlT + c * 32);
        #pragma unroll
        for (int q = 0; q < 8; q++) {
            float4 f = pf[q];
            wf[q * 4] = f.x; wf[q * 4 + 1] = f.y; wf[q * 4 + 2] = f.z; wf[q * 4 + 3] = f.w;
            float4 l = pl[q];
            wl[q * 4] = l.x; wl[q * 4 + 1] = l.y; wl[q * 4 + 2] = l.z; wl[q * 4 + 3] = l.w;
        }
    }
    __syncthreads();
    // phase 1: 4 edges per group, pack splats on the fly
    #pragma unroll 1
    for (int eg = 0; eg < 16; eg++) {
        ull aA0 = 0, aA1 = 0, aB0 = 0, aB1 = 0;
        const float* bA = hA + eg * 4;
        const float* bB = hB + eg * 4;
        #pragma unroll
        for (int k = 0; k < 32; k++) {
            ull2 A = *(const ull2*)(bA + k * 68);
            ull2 B = *(const ull2*)(bB + k * 68);
            ull wfp = pack2(wf[k], wf[k]);
            ull wlp = pack2(wl[k], wl[k]);
            fma2(aA0, wfp, A.x); fma2(aA1, wfp, A.y);
            fma2(aB0, wlp, B.x); fma2(aB1, wlp, B.y);
        }
        float lo, hi;
        unpack2(mul2(aA0, aB0), lo, hi);
        ws[(eg * 4 + 0) * 320 + c] = lo; ws[(eg * 4 + 1) * 320 + c] = hi;
        unpack2(mul2(aA1, aB1), lo, hi);
        ws[(eg * 4 + 2) * 320 + c] = lo; ws[(eg * 4 + 3) * 320 + c] = hi;
    }
    __syncthreads();
    // phase 2: tensor product + red.v4 scatter, all 320 threads
    {
        const float PW_S = 0.44721359549995793f;
        const float PW_V = 0.77459666924148337f;
        const float IS3  = 0.57735026918962576f;
        const float IS2  = 0.70710678118654752f;
        #pragma unroll 4
        for (int it = tid; it < TE * 64; it += 320) {
            int e = it >> 6, u = it & 63;
            int d = idxs[64 + e];
            if (d < 0) continue;
            int s = idxs[e];
            float4 q = *(const float4*)&xg[s * 256 + u * 4];
            float es = q.x, ev0 = q.y, ev1 = q.z, ev2 = q.w;
            float s0 = shs[e * 4], s1 = shs[e * 4 + 1], s2 = shs[e * 4 + 2], s3 = shs[e * 4 + 3];
            const float* we = ws + e * 320;
            float w0 = we[u], w1 = we[64 + u], w2 = we[128 + u], w3 = we[192 + u], w4 = we[256 + u];
            float dotv = ev0 * s1 + ev1 * s2 + ev2 * s3;
            float c0 = ev1 * s3 - ev2 * s2;
            float c1 = ev2 * s1 - ev0 * s3;
            float c2 = ev0 * s2 - ev1 * s1;
            float outs = PW_S * (w0 * es * s0 + w3 * dotv * IS3);
            float k2 = PW_V * w2 * s0;
            float k4 = PW_V * w4 * IS2;
            float k1 = PW_V * w1 * es;
            float o0 = k1 * s1 + k2 * ev0 + k4 * c0;
            float o1 = k1 * s2 + k2 * ev1 + k4 * c1;
            float o2 = k1 * s3 + k2 * ev2 + k4 * c2;
            float* pa = acc + d * 256 + u * 4;
            asm volatile("red.global.add.v4.f32 [%0], {%1, %2, %3, %4};"
                         :: "l"(pa), "f"(outs), "f"(o0), "f"(o1), "f"(o2) : "memory");
        }
    }
}

// ---------------- launch ----------------------------------------------------
extern "C" void kernel_launch(void* const* d_in, const int* in_sizes, int n_in,
                              void* d_out, int out_size) {
    const float* x     = (const float*)d_in[0];
    const int*   ei    = (const int*)  d_in[1];
    const float* sh    = (const float*)d_in[2];
    const float* attr  = (const float*)d_in[3];
    const float* Wpre0 = (const float*)d_in[4];
    const float* bpre0 = (const float*)d_in[5];
    const float* Wpre1 = (const float*)d_in[6];
    const float* Wg1   = (const float*)d_in[7];
    const float* bg1   = (const float*)d_in[8];
    const float* Wg2   = (const float*)d_in[9];
    const float* bg2   = (const float*)d_in[10];
    const float* Wn0   = (const float*)d_in[11];
    const float* bn0   = (const float*)d_in[12];
    const float* Wn1   = (const float*)d_in[13];
    const float* Wf1   = (const float*)d_in[14];
    const float* Wf2   = (const float*)d_in[15];
    const float* Wl1   = (const float*)d_in[16];
    const float* Wl2   = (const float*)d_in[17];
    const float* Wo0   = (const float*)d_in[18];
    const float* bo0   = (const float*)d_in[19];
    const float* Wo1   = (const float*)d_in[20];

    int N = in_sizes[0] / 256;
    int E = in_sizes[1] / 2;

    float *pre, *tmp, *xgp, *accp, *h1a, *h1l;
    cudaGetSymbolAddress((void**)&pre,  g_pre);
    cudaGetSymbolAddress((void**)&tmp,  g_tmp);
    cudaGetSymbolAddress((void**)&xgp,  g_xg);
    cudaGetSymbolAddress((void**)&accp, g_acc);
    cudaGetSymbolAddress((void**)&h1a,  g_h1a);
    cudaGetSymbolAddress((void**)&h1l,  g_h1l);

    static const int E3_SMEM   = (8192 + 4096 + 64) * 4;          // 49,408
    static const int GATE_SMEM = (16384 * 2 + 4352 * 2) * 4;      // 165,888
    static const int H1L_SMEM  = (4352 * 2 + 2048 * 2 + 128) * 4; // 51,712
    static const int EDGE_SMEM = (2 * 32 * 68 + 64 * 320 + 256 + 128) * 4;
    cudaFuncSetAttribute(e3_kernel<0,1,1>, cudaFuncAttributeMaxDynamicSharedMemorySize, E3_SMEM);
    cudaFuncSetAttribute(e3_kernel<1,1,1>, cudaFuncAttributeMaxDynamicSharedMemorySize, E3_SMEM);
    cudaFuncSetAttribute(e3_kernel<1,0,0>, cudaFuncAttributeMaxDynamicSharedMemorySize, E3_SMEM);
    cudaFuncSetAttribute(gate_kernel, cudaFuncAttributeMaxDynamicSharedMemorySize, GATE_SMEM);
    cudaFuncSetAttribute(h1l_kernel,  cudaFuncAttributeMaxDynamicSharedMemorySize, H1L_SMEM);
    cudaFuncSetAttribute(edge_kernel, cudaFuncAttributeMaxDynamicSharedMemorySize, EDGE_SMEM);

    static cudaStream_t s1 = nullptr, s2 = nullptr;
    static cudaEvent_t ev0, evP, ev1, ev2;
    if (!s1) {
        cudaStreamCreateWithFlags(&s1, cudaStreamNonBlocking);
        cudaStreamCreateWithFlags(&s2, cudaStreamNonBlocking);
        cudaEventCreateWithFlags(&ev0, cudaEventDisableTiming);
        cudaEventCreateWithFlags(&evP, cudaEventDisableTiming);
        cudaEventCreateWithFlags(&ev1, cudaEventDisableTiming);
        cudaEventCreateWithFlags(&ev2, cudaEventDisableTiming);
    }
    cudaStream_t d = 0;

    // fork side streams from the capture-origin stream
    cudaEventRecord(ev0, d);
    cudaStreamWaitEvent(s1, ev0, 0);
    cudaStreamWaitEvent(s2, ev0, 0);

    // s1: gate (no prep dependency)
    gate_kernel<<<(N + 31) / 32, 512, GATE_SMEM, s1>>>(x, Wg1, bg1, Wg2, bg2, tmp, N);
    // s2: h1a (no prep dependency)
    h1a_kernel<<<(E + 63) / 64, 256, 0, s2>>>(attr, Wf1, h1a, E);

    // d: prep -> e3pre -> h1l
    prep_kernel<<<48, 256, 0, d>>>(Wf2, Wl2, Wl1, Wpre0, Wpre1, Wn0, Wn1, Wo0, Wo1);
    cudaEventRecord(evP, d);
    e3_kernel<0, 1, 1><<<(N + 15) / 16, 256, E3_SMEM, d>>>(x, 0, bpre0, pre, nullptr, N);
    h1l_kernel<<<(E + 63) / 64, 256, H1L_SMEM, d>>>(ei, pre, h1l, E, E);

    // s1 continues: e3n after gate + prep
    cudaStreamWaitEvent(s1, evP, 0);
    e3_kernel<1, 1, 1><<<(N + 15) / 16, 256, E3_SMEM, s1>>>(tmp, 1, bn0, xgp, accp, N);
    cudaEventRecord(ev1, s1);
    cudaEventRecord(ev2, s2);

    // join on d: edge -> final e3
    cudaStreamWaitEvent(d, ev1, 0);
    cudaStreamWaitEvent(d, ev2, 0);
    edge_kernel<<<(E + TE - 1) / TE, 320, EDGE_SMEM, d>>>(ei, sh, h1a, h1l, xgp, accp, E, E);
    e3_kernel<1, 0, 0><<<(N + 15) / 16, 256, E3_SMEM, d>>>(accp, 2, bo0, (float*)d_out, nullptr, N);
}

// round 6
// speedup vs baseline: 1.5897x; 1.0357x over previous
#include <cuda_runtime.h>
#include <math.h>

#define MAXN 20000
#define MAXE 320000

typedef unsigned long long ull;
typedef ulonglong2 ull2;

// ---------------- scratch (device globals) ---------------------------------
// All node tensors in QUAD layout: [n][u][4] = (s_u, v0_u, v1_u, v2_u)
__device__ float g_pre[MAXN * 256];
__device__ float g_tmp[MAXN * 256];
__device__ float g_xg [MAXN * 256];
__device__ float g_acc[MAXN * 256];
__device__ float g_h1a[MAXE * 32];
__device__ float g_h1l[MAXE * 32];
__device__ float g_WfT[320 * 32];   // Wf2^T * (1/sqrt32), [col][k]
__device__ float g_WlT[320 * 32];
__device__ float g_Wl1s[64 * 32];   // (Wl1[u]+Wl1[u+64]) / sqrt192
__device__ float g_Wl1i[64 * 32];   // Wl1[u+128] / sqrt192
__device__ ull   g_eW[3 * 4096];    // e3 packed (w0,w1)*0.125 for pre/n/o

__device__ __forceinline__ float sspf(float x) {
    float sp = (x > 15.f) ? x : log1pf(expf(x));
    return sp - 0.69314718055994531f;
}
__device__ __forceinline__ float siluf(float x) {
    return x / (1.f + expf(-x));
}
__device__ __forceinline__ ull pack2(float a, float b) {
    ull r; asm("mov.b64 %0, {%1, %2};" : "=l"(r) : "f"(a), "f"(b)); return r;
}
__device__ __forceinline__ void fma2(ull& d, ull a, ull b) {
    asm("fma.rn.f32x2 %0, %1, %2, %0;" : "+l"(d) : "l"(a), "l"(b));
}
__device__ __forceinline__ ull mul2(ull a, ull b) {
    ull r; asm("mul.rn.f32x2 %0, %1, %2;" : "=l"(r) : "l"(a), "l"(b)); return r;
}
__device__ __forceinline__ void unpack2(ull v, float& lo, float& hi) {
    asm("mov.b64 {%0, %1}, %2;" : "=f"(lo), "=f"(hi) : "l"(v));
}

// ---------------- weight prep ----------------------------------------------
__global__ void prep_kernel(const float* __restrict__ Wf2,
                            const float* __restrict__ Wl2,
                            const float* __restrict__ Wl1,
                            const float* __restrict__ Wpre0,
                            const float* __restrict__ Wpre1,
                            const float* __restrict__ Wn0,
                            const float* __restrict__ Wn1,
                            const float* __restrict__ Wo0,
                            const float* __restrict__ Wo1) {
    int i = blockIdx.x * 256 + threadIdx.x;
    const float is32 = 0.17677669529663687f;   // 1/sqrt(32)
    if (i < 320 * 32) {
        int c = i >> 5, k = i & 31;
        g_WfT[i] = Wf2[k * 320 + c] * is32;
        g_WlT[i] = Wl2[k * 320 + c] * is32;
    }
    if (i < 64 * 32) {
        const float r192 = 0.07216878364870323f;  // 1/sqrt(192)
        g_Wl1s[i] = (Wl1[i] + Wl1[64 * 32 + i]) * r192;
        g_Wl1i[i] = Wl1[128 * 32 + i] * r192;
    }
    if (i < 3 * 4096) {
        int p = i >> 12, r = i & 4095;
        const float* w0 = (p == 0) ? Wpre0 : (p == 1) ? Wn0 : Wo0;
        const float* w1 = (p == 0) ? Wpre1 : (p == 1) ? Wn1 : Wo1;
        g_eW[i] = pack2(w0[r] * 0.125f, w1[r] * 0.125f);
    }
}

// ---------------- e3_linear: 16 nodes/block, dynamic smem -------------------
// IL/OL/OL2: 0 = standard layout (s[64] | v[u][3]), 1 = quad layout.
template<int IL, int OL, int OL2>
__global__ void e3_kernel(const float* __restrict__ in,
                          int widx,
                          const float* __restrict__ b0,
                          float* __restrict__ out,
                          float* __restrict__ out2, int nN) {
    extern __shared__ float sme3[];
    ull*   Wp  = (ull*)sme3;             // 4096 ull = 32 KB
    float* ins = sme3 + 8192;            // 16*256 = 16 KB
    float* b0s = sme3 + 8192 + 4096;     // 64
    int tid = threadIdx.x;
    {
        const ull2* src = (const ull2*)(g_eW + widx * 4096);
        ull2* dst = (ull2*)Wp;
        for (int i = tid; i < 2048; i += 256) dst[i] = src[i];
    }
    if (tid < 64) b0s[tid] = b0[tid];
    int n0 = blockIdx.x * 16;
    if (IL == 0) {
        // vectorized std->quad staging: each i handles (node, 4 u's)
        for (int i = tid; i < 256; i += 256) {
            int nl = i >> 4, g4 = i & 15;
            int u0 = g4 * 4;
            int n = n0 + nl;
            float4 a = make_float4(0.f,0.f,0.f,0.f), b = a, cc = a, dd = a;
            if (n < nN) {
                const float* xr = in + n * 256;
                a  = *(const float4*)(xr + u0);
                const float4* vp = (const float4*)(xr + 64 + u0 * 3);
                b = vp[0]; cc = vp[1]; dd = vp[2];
            }
            float4* q = (float4*)(ins + nl * 256 + u0 * 4);
            q[0] = make_float4(a.x, b.x, b.y, b.z);
            q[1] = make_float4(a.y, b.w, cc.x, cc.y);
            q[2] = make_float4(a.z, cc.z, cc.w, dd.x);
            q[3] = make_float4(a.w, dd.y, dd.z, dd.w);
        }
    } else {
        for (int i = tid; i < 1024; i += 256) {
            int nl = i >> 6, q = i & 63;
            int n = n0 + nl;
            float4 v = (n < nN) ? ((const float4*)(in + n * 256))[q]
                                : make_float4(0.f, 0.f, 0.f, 0.f);
            ((float4*)(ins + nl * 256))[q] = v;
        }
    }
    __syncthreads();
    int v = tid & 63, g = tid >> 6;       // g handles nodes g*4 .. g*4+3
    const float* base = ins + g * 4 * 256;
    ull acc[4][2] = {};
    #pragma unroll 4
    for (int u = 0; u < 64; u++) {
        ull wp = Wp[u * 64 + v];
        float w0, w1; unpack2(wp, w0, w1);
        ull wq = pack2(w1, w1);
        #pragma unroll
        for (int t = 0; t < 4; t++) {
            ull2 q = *(const ull2*)(base + t * 256 + u * 4);
            fma2(acc[t][0], wp, q.x);
            fma2(acc[t][1], wq, q.y);
        }
    }
    float bias = b0s[v];
    float rs[4], r0[4], r1[4], r2[4];
    #pragma unroll
    for (int t = 0; t < 4; t++) {
        unpack2(acc[t][0], rs[t], r0[t]);
        unpack2(acc[t][1], r1[t], r2[t]);
        rs[t] += bias;
    }
    // quad-layout direct writes
    #pragma unroll
    for (int t = 0; t < 4; t++) {
        int n = n0 + g * 4 + t;
        if (n >= nN) continue;
        float4 q = make_float4(rs[t], r0[t], r1[t], r2[t]);
        if (OL == 1) ((float4*)(out + n * 256))[v] = q;
        if (out2 && OL2 == 1) ((float4*)(out2 + n * 256))[v] = q;
    }
    if (OL == 0) {
        // std layout via smem transpose then vector stores
        __syncthreads();
        #pragma unroll
        for (int t = 0; t < 4; t++) {
            float* row = ins + (g * 4 + t) * 256;
            row[v] = rs[t];
            row[64 + v * 3 + 0] = r0[t];
            row[64 + v * 3 + 1] = r1[t];
            row[64 + v * 3 + 2] = r2[t];
        }
        __syncthreads();
        for (int i = tid; i < 1024; i += 256) {
            int nl = i >> 6, q = i & 63;
            int n = n0 + nl;
            if (n < nN)
                ((float4*)(out + n * 256))[q] = ((float4*)(ins + nl * 256))[q];
        }
    }
}

// ---------------- gate MLP (f32x2, 32 nodes/block, 512 thr) -> quad output --
__global__ void gate_kernel(const float* __restrict__ x,
                            const float* __restrict__ Wg1,
                            const float* __restrict__ bg1,
                            const float* __restrict__ Wg2,
                            const float* __restrict__ bg2,
                            float* __restrict__ outb, int nN) {
    extern __shared__ float sm[];
    float* W1s = sm;                 // 16384
    float* W2s = sm + 16384;         // 16384
    float* f0t = sm + 32768;         // 128*34 = 4352
    float* hst = sm + 32768 + 4352;  // 4352
    int tid = threadIdx.x;
    for (int i = tid; i < 4096; i += 512) {
        ((float4*)W1s)[i] = ((const float4*)Wg1)[i];
        ((float4*)W2s)[i] = ((const float4*)Wg2)[i];
    }
    int n0 = blockIdx.x * 32;
    for (int i = tid; i < 4096; i += 512) {
        int nl = i >> 7, j = i & 127;
        int n = n0 + nl;
        float val = 0.f;
        if (n < nN) {
            const float* xr = x + n * 256;
            if (j < 64) val = xr[j];
            else {
                int u = j - 64;
                float v0 = xr[64 + u * 3], v1 = xr[64 + u * 3 + 1], v2 = xr[64 + u * 3 + 2];
                val = sqrtf(v0 * v0 + v1 * v1 + v2 * v2 + 1e-12f);
            }
        }
        f0t[j * 34 + nl] = val;
    }
    __syncthreads();
    int j = tid & 127, quarter = tid >> 7;
    {
        ull a0 = 0, a1 = 0, a2 = 0, a3 = 0;
        #pragma unroll 8
        for (int k = 0; k < 128; k++) {
            float w = W1s[k * 128 + j];
            ull wp = pack2(w, w);
            const ull* f = (const ull*)&f0t[k * 34 + quarter * 8];
            fma2(a0, wp, f[0]); fma2(a1, wp, f[1]); fma2(a2, wp, f[2]); fma2(a3, wp, f[3]);
        }
        float b = bg1[j];
        float lo, hi;
        unpack2(a0, lo, hi); hst[j * 34 + quarter * 8 + 0] = siluf(lo + b); hst[j * 34 + quarter * 8 + 1] = siluf(hi + b);
        unpack2(a1, lo, hi); hst[j * 34 + quarter * 8 + 2] = siluf(lo + b); hst[j * 34 + quarter * 8 + 3] = siluf(hi + b);
        unpack2(a2, lo, hi); hst[j * 34 + quarter * 8 + 4] = siluf(lo + b); hst[j * 34 + quarter * 8 + 5] = siluf(hi + b);
        unpack2(a3, lo, hi); hst[j * 34 + quarter * 8 + 6] = siluf(lo + b); hst[j * 34 + quarter * 8 + 7] = siluf(hi + b);
    }
    __syncthreads();
    float g[8];
    {
        ull a0 = 0, a1 = 0, a2 = 0, a3 = 0;
        #pragma unroll 8
        for (int k = 0; k < 128; k++) {
            float w = W2s[k * 128 + j];
            ull wp = pack2(w, w);
            const ull* h = (const ull*)&hst[k * 34 + quarter * 8];
            fma2(a0, wp, h[0]); fma2(a1, wp, h[1]); fma2(a2, wp, h[2]); fma2(a3, wp, h[3]);
        }
        float b = bg2[j];
        unpack2(a0, g[0], g[1]); unpack2(a1, g[2], g[3]);
        unpack2(a2, g[4], g[5]); unpack2(a3, g[6], g[7]);
        #pragma unroll
        for (int p = 0; p < 8; p++) g[p] += b;
    }
    __syncthreads();
    #pragma unroll
    for (int p = 0; p < 8; p++) f0t[(quarter * 8 + p) * 128 + j] = g[p];
    __syncthreads();
    for (int q = tid; q < 2048; q += 512) {
        int nl = q >> 6, u = q & 63;
        int n = n0 + nl;
        if (n >= nN) continue;
        float gs = f0t[nl * 128 + u];
        float gv = f0t[nl * 128 + 64 + u];
        const float* xr = x + n * 256 + 64 + u * 3;
        ((float4*)(outb + n * 256))[u] = make_float4(gs, xr[0] * gv, xr[1] * gv, xr[2] * gv);
    }
}

// ---------------- h1a = ssp(edge_attr @ Wf1 / 8) ---------------------------
__global__ void h1a_kernel(const float* __restrict__ attr,
                           const float* __restrict__ Wf1,
                           float* __restrict__ h1a, int nE) {
    __shared__ float at[64 * 68];     // [u][edge], pad 68
    __shared__ float Wf1s[64 * 32];
    int tid = threadIdx.x;
    int e0 = blockIdx.x * 64;
    for (int i = tid; i < 512; i += 256)
        ((float4*)Wf1s)[i] = ((const float4*)Wf1)[i];
    for (int i = tid; i < 1024; i += 256) {
        int el = i >> 4, u0 = (i & 15) * 4;
        int e = e0 + el;
        float4 a4 = (e < nE) ? *(const float4*)&attr[e * 64 + u0]
                             : make_float4(0.f, 0.f, 0.f, 0.f);
        at[(u0 + 0) * 68 + el] = a4.x;
        at[(u0 + 1) * 68 + el] = a4.y;
        at[(u0 + 2) * 68 + el] = a4.z;
        at[(u0 + 3) * 68 + el] = a4.w;
    }
    __syncthreads();
    int k = tid & 31, g = tid >> 5;   // 8 groups x 8 edges
    ull a0 = 0, a1 = 0, a2 = 0, a3 = 0;
    #pragma unroll 4
    for (int u = 0; u < 64; u++) {
        float w = Wf1s[u * 32 + k];
        ull wp = pack2(w, w);
        const ull2* pa = (const ull2*)(at + u * 68 + g * 8);
        ull2 A0 = pa[0], A1 = pa[1];
        fma2(a0, wp, A0.x); fma2(a1, wp, A0.y);
        fma2(a2, wp, A1.x); fma2(a3, wp, A1.y);
    }
    float r[8];
    unpack2(a0, r[0], r[1]); unpack2(a1, r[2], r[3]);
    unpack2(a2, r[4], r[5]); unpack2(a3, r[6], r[7]);
    #pragma unroll
    for (int ee = 0; ee < 8; ee++) {
        int e = e0 + g * 8 + ee;
        if (e < nE) h1a[e * 32 + k] = sspf(r[ee] * 0.125f);
    }
}

// ---------------- h1l = ssp(s0 @ Wl1 / sqrt192), 64 edges/block -------------
__global__ void h1l_kernel(const int* __restrict__ ei,
                           const float* __restrict__ pre,
                           float* __restrict__ h1l, int nE, int Etot) {
    extern __shared__ float smh[];
    float* ps_t = smh;                 // 64*68
    float* ip_t = smh + 4352;          // 64*68
    float* Ws   = smh + 8704;          // 2048
    float* Wi   = smh + 10752;         // 2048
    int*   idx  = (int*)(smh + 12800); // dst[64] | src[64]
    int tid = threadIdx.x;
    int e0 = blockIdx.x * 64;
    for (int i = tid; i < 512; i += 256) {
        ((float4*)Ws)[i] = ((const float4*)g_Wl1s)[i];
        ((float4*)Wi)[i] = ((const float4*)g_Wl1i)[i];
    }
    if (tid < 64) {
        int e = e0 + tid;
        bool v = (e < nE);
        idx[tid]      = v ? ei[e] : 0;
        idx[64 + tid] = v ? ei[Etot + e] : 0;
    }
    __syncthreads();
    for (int i = tid; i < 4096; i += 256) {
        int u = i & 63, el = i >> 6;
        int d = idx[el], s = idx[64 + el];
        float4 qd = *(const float4*)&pre[d * 256 + u * 4];
        float4 qs = *(const float4*)&pre[s * 256 + u * 4];
        ps_t[u * 68 + el] = qd.x;
        ip_t[u * 68 + el] = (qd.y * qs.y + qd.z * qs.z + qd.w * qs.w) * (1.f / 3.f);
    }
    __syncthreads();
    int k = tid & 31, g = tid >> 5;   // 8 groups x 8 edges
    ull a[4] = {};
    #pragma unroll 4
    for (int u = 0; u < 64; u++) {
        float ws = Ws[u * 32 + k];
        float wi = Wi[u * 32 + k];
        ull wps = pack2(ws, ws), wpi = pack2(wi, wi);
        const ull2* P = (const ull2*)(ps_t + u * 68 + g * 8);
        const ull2* I = (const ull2*)(ip_t + u * 68 + g * 8);
        ull2 P0 = P[0], P1 = P[1], I0 = I[0], I1 = I[1];
        fma2(a[0], wps, P0.x); fma2(a[1], wps, P0.y);
        fma2(a[2], wps, P1.x); fma2(a[3], wps, P1.y);
        fma2(a[0], wpi, I0.x); fma2(a[1], wpi, I0.y);
        fma2(a[2], wpi, I1.x); fma2(a[3], wpi, I1.y);
    }
    float r[8];
    unpack2(a[0], r[0], r[1]); unpack2(a[1], r[2], r[3]);
    unpack2(a[2], r[4], r[5]); unpack2(a[3], r[6], r[7]);
    #pragma unroll
    for (int ee = 0; ee < 8; ee++) {
        int e = e0 + g * 8 + ee;
        if (e < nE) h1l[e * 32 + k] = sspf(r[ee]);
    }
}

// ---------------- fused edge kernel: PERSISTENT ----------------------------
#define TE 64
#define EDGE_BLOCKS 296
__global__ void __launch_bounds__(320, 2)
edge_kernel(const int* __restrict__ ei,
            const float* __restrict__ sh,
            const float* __restrict__ h1a,
            const float* __restrict__ h1l,
            const float* __restrict__ xg,
            float* __restrict__ acc, int nE, int Etot) {
    extern __shared__ float sm[];
    float* hA  = sm;                     // 32 * 68
    float* hB  = sm + 32 * 68;           // 32 * 68
    float* ws  = sm + 2 * 32 * 68;       // 64 * 320
    float* shs = ws + 64 * 320;          // 64 * 4
    int*   idxs = (int*)(shs + 256);     // src[64] | dst[64]
    int tid = threadIdx.x;
    int c = tid;

    // weight columns loaded ONCE per block (persistent reuse)
    float wf[32], wl[32];
    {
        const float4* pf = (const float4*)(g_WfT + c * 32);
        const float4* pl = (const float4*)(g_WlT + c * 32);
        #pragma unroll
        for (int q = 0; q < 8; q++) {
            float4 f = pf[q];
            wf[q * 4] = f.x; wf[q * 4 + 1] = f.y; wf[q * 4 + 2] = f.z; wf[q * 4 + 3] = f.w;
            float4 l = pl[q];
            wl[q * 4] = l.x; wl[q * 4 + 1] = l.y; wl[q * 4 + 2] = l.z; wl[q * 4 + 3] = l.w;
        }
    }

    const float PW_S = 0.44721359549995793f;
    const float PW_V = 0.77459666924148337f;
    const float IS3  = 0.57735026918962576f;
    const float IS2  = 0.70710678118654752f;

    int ntiles = (nE + TE - 1) / TE;
    for (int tile = blockIdx.x; tile < ntiles; tile += gridDim.x) {
        int e0 = tile * TE;
        // ---- stage ----
        if (tid < 64) {
            int e = e0 + tid;
            bool v = (e < nE);
            idxs[tid]      = v ? ei[Etot + e] : 0;
            idxs[64 + tid] = v ? ei[e] : -1;
            float4 s4 = v ? *(const float4*)&sh[e * 4] : make_float4(0.f, 0.f, 0.f, 0.f);
            ((float4*)shs)[tid] = s4;
        }
        for (int i = tid; i < 512; i += 320) {
            int el = i >> 3, k0 = (i & 7) * 4;
            int e = e0 + el;
            float4 a = make_float4(0.f, 0.f, 0.f, 0.f), b = a;
            if (e < nE) {
                a = *(const float4*)&h1a[e * 32 + k0];
                b = *(const float4*)&h1l[e * 32 + k0];
            }
            hA[(k0 + 0) * 68 + el] = a.x; hA[(k0 + 1) * 68 + el] = a.y;
            hA[(k0 + 2) * 68 + el] = a.z; hA[(k0 + 3) * 68 + el] = a.w;
            hB[(k0 + 0) * 68 + el] = b.x; hB[(k0 + 1) * 68 + el] = b.y;
            hB[(k0 + 2) * 68 + el] = b.z; hB[(k0 + 3) * 68 + el] = b.w;
        }
        __syncthreads();
        // ---- phase 1: GEMM pair, FFMA2 ----
        #pragma unroll 1
        for (int eg = 0; eg < 16; eg++) {
            ull aA0 = 0, aA1 = 0, aB0 = 0, aB1 = 0;
            const float* bA = hA + eg * 4;
            const float* bB = hB + eg * 4;
            #pragma unroll
            for (int k = 0; k < 32; k++) {
                ull2 A = *(const ull2*)(bA + k * 68);
                ull2 B = *(const ull2*)(bB + k * 68);
                ull wfp = pack2(wf[k], wf[k]);
                ull wlp = pack2(wl[k], wl[k]);
                fma2(aA0, wfp, A.x); fma2(aA1, wfp, A.y);
                fma2(aB0, wlp, B.x); fma2(aB1, wlp, B.y);
            }
            float lo, hi;
            unpack2(mul2(aA0, aB0), lo, hi);
            ws[(eg * 4 + 0) * 320 + c] = lo; ws[(eg * 4 + 1) * 320 + c] = hi;
            unpack2(mul2(aA1, aB1), lo, hi);
            ws[(eg * 4 + 2) * 320 + c] = lo; ws[(eg * 4 + 3) * 320 + c] = hi;
        }
        __syncthreads();
        // ---- phase 2: tensor product + red.v4 scatter ----
        #pragma unroll 4
        for (int it = tid; it < TE * 64; it += 320) {
            int e = it >> 6, u = it & 63;
            int d = idxs[64 + e];
            if (d < 0) continue;
            int s = idxs[e];
            float4 q = *(const float4*)&xg[s * 256 + u * 4];
            float es = q.x, ev0 = q.y, ev1 = q.z, ev2 = q.w;
            float s0 = shs[e * 4], s1 = shs[e * 4 + 1], s2 = shs[e * 4 + 2], s3 = shs[e * 4 + 3];
            const float* we = ws + e * 320;
            float w0 = we[u], w1 = we[64 + u], w2 = we[128 + u], w3 = we[192 + u], w4 = we[256 + u];
            float dotv = ev0 * s1 + ev1 * s2 + ev2 * s3;
            float c0 = ev1 * s3 - ev2 * s2;
            float c1 = ev2 * s1 - ev0 * s3;
            float c2 = ev0 * s2 - ev1 * s1;
            float outs = PW_S * (w0 * es * s0 + w3 * dotv * IS3);
            float k2 = PW_V * w2 * s0;
            float k4 = PW_V * w4 * IS2;
            float k1 = PW_V * w1 * es;
            float o0 = k1 * s1 + k2 * ev0 + k4 * c0;
            float o1 = k1 * s2 + k2 * ev1 + k4 * c1;
            float o2 = k1 * s3 + k2 * ev2 + k4 * c2;
            float* pa = acc + d * 256 + u * 4;
            asm volatile("red.global.add.v4.f32 [%0], {%1, %2, %3, %4};"
                         :: "l"(pa), "f"(outs), "f"(o0), "f"(o1), "f"(o2) : "memory");
        }
        __syncthreads();   // protect idxs/shs/hA/hB before next tile's staging
    }
}

// ---------------- launch ----------------------------------------------------
extern "C" void kernel_launch(void* const* d_in, const int* in_sizes, int n_in,
                              void* d_out, int out_size) {
    const float* x     = (const float*)d_in[0];
    const int*   ei    = (const int*)  d_in[1];
    const float* sh    = (const float*)d_in[2];
    const float* attr  = (const float*)d_in[3];
    const float* Wpre0 = (const float*)d_in[4];
    const float* bpre0 = (const float*)d_in[5];
    const float* Wpre1 = (const float*)d_in[6];
    const float* Wg1   = (const float*)d_in[7];
    const float* bg1   = (const float*)d_in[8];
    const float* Wg2   = (const float*)d_in[9];
    const float* bg2   = (const float*)d_in[10];
    const float* Wn0   = (const float*)d_in[11];
    const float* bn0   = (const float*)d_in[12];
    const float* Wn1   = (const float*)d_in[13];
    const float* Wf1   = (const float*)d_in[14];
    const float* Wf2   = (const float*)d_in[15];
    const float* Wl1   = (const float*)d_in[16];
    const float* Wl2   = (const float*)d_in[17];
    const float* Wo0   = (const float*)d_in[18];
    const float* bo0   = (const float*)d_in[19];
    const float* Wo1   = (const float*)d_in[20];

    int N = in_sizes[0] / 256;
    int E = in_sizes[1] / 2;

    float *pre, *tmp, *xgp, *accp, *h1a, *h1l;
    cudaGetSymbolAddress((void**)&pre,  g_pre);
    cudaGetSymbolAddress((void**)&tmp,  g_tmp);
    cudaGetSymbolAddress((void**)&xgp,  g_xg);
    cudaGetSymbolAddress((void**)&accp, g_acc);
    cudaGetSymbolAddress((void**)&h1a,  g_h1a);
    cudaGetSymbolAddress((void**)&h1l,  g_h1l);

    static const int E3_SMEM   = (8192 + 4096 + 64) * 4;
    static const int GATE_SMEM = (16384 * 2 + 4352 * 2) * 4;
    static const int H1L_SMEM  = (4352 * 2 + 2048 * 2 + 128) * 4;
    static const int EDGE_SMEM = (2 * 32 * 68 + 64 * 320 + 256 + 128) * 4;
    cudaFuncSetAttribute(e3_kernel<0,1,1>, cudaFuncAttributeMaxDynamicSharedMemorySize, E3_SMEM);
    cudaFuncSetAttribute(e3_kernel<1,1,1>, cudaFuncAttributeMaxDynamicSharedMemorySize, E3_SMEM);
    cudaFuncSetAttribute(e3_kernel<1,0,0>, cudaFuncAttributeMaxDynamicSharedMemorySize, E3_SMEM);
    cudaFuncSetAttribute(gate_kernel, cudaFuncAttributeMaxDynamicSharedMemorySize, GATE_SMEM);
    cudaFuncSetAttribute(h1l_kernel,  cudaFuncAttributeMaxDynamicSharedMemorySize, H1L_SMEM);
    cudaFuncSetAttribute(edge_kernel, cudaFuncAttributeMaxDynamicSharedMemorySize, EDGE_SMEM);

    static cudaStream_t s1 = nullptr, s2 = nullptr;
    static cudaEvent_t ev0, evP, ev1, ev2;
    if (!s1) {
        cudaStreamCreateWithFlags(&s1, cudaStreamNonBlocking);
        cudaStreamCreateWithFlags(&s2, cudaStreamNonBlocking);
        cudaEventCreateWithFlags(&ev0, cudaEventDisableTiming);
        cudaEventCreateWithFlags(&evP, cudaEventDisableTiming);
        cudaEventCreateWithFlags(&ev1, cudaEventDisableTiming);
        cudaEventCreateWithFlags(&ev2, cudaEventDisableTiming);
    }
    cudaStream_t d = 0;

    cudaEventRecord(ev0, d);
    cudaStreamWaitEvent(s1, ev0, 0);
    cudaStreamWaitEvent(s2, ev0, 0);

    gate_kernel<<<(N + 31) / 32, 512, GATE_SMEM, s1>>>(x, Wg1, bg1, Wg2, bg2, tmp, N);
    h1a_kernel<<<(E + 63) / 64, 256, 0, s2>>>(attr, Wf1, h1a, E);

    prep_kernel<<<48, 256, 0, d>>>(Wf2, Wl2, Wl1, Wpre0, Wpre1, Wn0, Wn1, Wo0, Wo1);
    cudaEventRecord(evP, d);
    e3_kernel<0, 1, 1><<<(N + 15) / 16, 256, E3_SMEM, d>>>(x, 0, bpre0, pre, nullptr, N);
    h1l_kernel<<<(E + 63) / 64, 256, H1L_SMEM, d>>>(ei, pre, h1l, E, E);

    cudaStreamWaitEvent(s1, evP, 0);
    e3_kernel<1, 1, 1><<<(N + 15) / 16, 256, E3_SMEM, s1>>>(tmp, 1, bn0, xgp, accp, N);
    cudaEventRecord(ev1, s1);
    cudaEventRecord(ev2, s2);

    cudaStreamWaitEvent(d, ev1, 0);
    cudaStreamWaitEvent(d, ev2, 0);
    int ntiles = (E + TE - 1) / TE;
    int eblocks = ntiles < EDGE_BLOCKS ? ntiles : EDGE_BLOCKS;
    edge_kernel<<<eblocks, 320, EDGE_SMEM, d>>>(ei, sh, h1a, h1l, xgp, accp, E, E);
    e3_kernel<1, 0, 0><<<(N + 15) / 16, 256, E3_SMEM, d>>>(accp, 2, bo0, (float*)d_out, nullptr, N);
}

// round 7
// speedup vs baseline: 2.0609x; 1.2964x over previous
#include <cuda_runtime.h>
#include <math.h>

#define MAXN 20000
#define MAXE 320000

typedef unsigned long long ull;
typedef ulonglong2 ull2;

// ---------------- scratch (device globals) ---------------------------------
__device__ float g_pre[MAXN * 256];
__device__ float g_tmp[MAXN * 256];
__device__ float g_xg [MAXN * 256];
__device__ float g_acc[MAXN * 256];
__device__ float g_h1a[MAXE * 32];
__device__ float g_h1l[MAXE * 32];
__device__ float g_WfT[320 * 32];   // Wf2^T * (1/sqrt32), tf32-rounded, [col][k]
__device__ float g_WlT[320 * 32];
__device__ float g_Wl1s[64 * 32];
__device__ float g_Wl1i[64 * 32];
__device__ ull   g_eW[3 * 4096];

__device__ __forceinline__ float sspf(float x) {
    float sp = (x > 15.f) ? x : log1pf(expf(x));
    return sp - 0.69314718055994531f;
}
__device__ __forceinline__ float siluf(float x) {
    return x / (1.f + expf(-x));
}
__device__ __forceinline__ ull pack2(float a, float b) {
    ull r; asm("mov.b64 %0, {%1, %2};" : "=l"(r) : "f"(a), "f"(b)); return r;
}
__device__ __forceinline__ void fma2(ull& d, ull a, ull b) {
    asm("fma.rn.f32x2 %0, %1, %2, %0;" : "+l"(d) : "l"(a), "l"(b));
}
__device__ __forceinline__ void unpack2(ull v, float& lo, float& hi) {
    asm("mov.b64 {%0, %1}, %2;" : "=f"(lo), "=f"(hi) : "l"(v));
}
__device__ __forceinline__ unsigned tf32r(float x) {
    unsigned r; asm("cvt.rna.tf32.f32 %0, %1;" : "=r"(r) : "f"(x)); return r;
}
__device__ __forceinline__ void mma_tf32(float* d, const unsigned* a, const unsigned* b) {
    asm("mma.sync.aligned.m16n8k8.row.col.f32.tf32.tf32.f32 "
        "{%0,%1,%2,%3}, {%4,%5,%6,%7}, {%8,%9}, {%0,%1,%2,%3};"
        : "+f"(d[0]), "+f"(d[1]), "+f"(d[2]), "+f"(d[3])
        : "r"(a[0]), "r"(a[1]), "r"(a[2]), "r"(a[3]), "r"(b[0]), "r"(b[1]));
}

// ---------------- weight prep ----------------------------------------------
__global__ void prep_kernel(const float* __restrict__ Wf2,
                            const float* __restrict__ Wl2,
                            const float* __restrict__ Wl1,
                            const float* __restrict__ Wpre0,
                            const float* __restrict__ Wpre1,
                            const float* __restrict__ Wn0,
                            const float* __restrict__ Wn1,
                            const float* __restrict__ Wo0,
                            const float* __restrict__ Wo1) {
    int i = blockIdx.x * 256 + threadIdx.x;
    const float is32 = 0.17677669529663687f;   // 1/sqrt(32)
    if (i < 320 * 32) {
        int c = i >> 5, k = i & 31;
        g_WfT[i] = __uint_as_float(tf32r(Wf2[k * 320 + c] * is32));
        g_WlT[i] = __uint_as_float(tf32r(Wl2[k * 320 + c] * is32));
    }
    if (i < 64 * 32) {
        const float r192 = 0.07216878364870323f;  // 1/sqrt(192)
        g_Wl1s[i] = (Wl1[i] + Wl1[64 * 32 + i]) * r192;
        g_Wl1i[i] = Wl1[128 * 32 + i] * r192;
    }
    if (i < 3 * 4096) {
        int p = i >> 12, r = i & 4095;
        const float* w0 = (p == 0) ? Wpre0 : (p == 1) ? Wn0 : Wo0;
        const float* w1 = (p == 0) ? Wpre1 : (p == 1) ? Wn1 : Wo1;
        g_eW[i] = pack2(w0[r] * 0.125f, w1[r] * 0.125f);
    }
}

// ---------------- e3_linear: 16 nodes/block --------------------------------
template<int IL, int OL, int OL2>
__global__ void e3_kernel(const float* __restrict__ in,
                          int widx,
                          const float* __restrict__ b0,
                          float* __restrict__ out,
                          float* __restrict__ out2, int nN) {
    extern __shared__ float sme3[];
    ull*   Wp  = (ull*)sme3;
    float* ins = sme3 + 8192;
    float* b0s = sme3 + 8192 + 4096;
    int tid = threadIdx.x;
    {
        const ull2* src = (const ull2*)(g_eW + widx * 4096);
        ull2* dst = (ull2*)Wp;
        for (int i = tid; i < 2048; i += 256) dst[i] = src[i];
    }
    if (tid < 64) b0s[tid] = b0[tid];
    int n0 = blockIdx.x * 16;
    if (IL == 0) {
        for (int i = tid; i < 256; i += 256) {
            int nl = i >> 4, g4 = i & 15;
            int u0 = g4 * 4;
            int n = n0 + nl;
            float4 a = make_float4(0.f,0.f,0.f,0.f), b = a, cc = a, dd = a;
            if (n < nN) {
                const float* xr = in + n * 256;
                a  = *(const float4*)(xr + u0);
                const float4* vp = (const float4*)(xr + 64 + u0 * 3);
                b = vp[0]; cc = vp[1]; dd = vp[2];
            }
            float4* q = (float4*)(ins + nl * 256 + u0 * 4);
            q[0] = make_float4(a.x, b.x, b.y, b.z);
            q[1] = make_float4(a.y, b.w, cc.x, cc.y);
            q[2] = make_float4(a.z, cc.z, cc.w, dd.x);
            q[3] = make_float4(a.w, dd.y, dd.z, dd.w);
        }
    } else {
        for (int i = tid; i < 1024; i += 256) {
            int nl = i >> 6, q = i & 63;
            int n = n0 + nl;
            float4 v = (n < nN) ? ((const float4*)(in + n * 256))[q]
                                : make_float4(0.f, 0.f, 0.f, 0.f);
            ((float4*)(ins + nl * 256))[q] = v;
        }
    }
    __syncthreads();
    int v = tid & 63, g = tid >> 6;
    const float* base = ins + g * 4 * 256;
    ull acc[4][2] = {};
    #pragma unroll 4
    for (int u = 0; u < 64; u++) {
        ull wp = Wp[u * 64 + v];
        float w0, w1; unpack2(wp, w0, w1);
        ull wq = pack2(w1, w1);
        #pragma unroll
        for (int t = 0; t < 4; t++) {
            ull2 q = *(const ull2*)(base + t * 256 + u * 4);
            fma2(acc[t][0], wp, q.x);
            fma2(acc[t][1], wq, q.y);
        }
    }
    float bias = b0s[v];
    float rs[4], r0[4], r1[4], r2[4];
    #pragma unroll
    for (int t = 0; t < 4; t++) {
        unpack2(acc[t][0], rs[t], r0[t]);
        unpack2(acc[t][1], r1[t], r2[t]);
        rs[t] += bias;
    }
    #pragma unroll
    for (int t = 0; t < 4; t++) {
        int n = n0 + g * 4 + t;
        if (n >= nN) continue;
        float4 q = make_float4(rs[t], r0[t], r1[t], r2[t]);
        if (OL == 1) ((float4*)(out + n * 256))[v] = q;
        if (out2 && OL2 == 1) ((float4*)(out2 + n * 256))[v] = q;
    }
    if (OL == 0) {
        __syncthreads();
        #pragma unroll
        for (int t = 0; t < 4; t++) {
            float* row = ins + (g * 4 + t) * 256;
            row[v] = rs[t];
            row[64 + v * 3 + 0] = r0[t];
            row[64 + v * 3 + 1] = r1[t];
            row[64 + v * 3 + 2] = r2[t];
        }
        __syncthreads();
        for (int i = tid; i < 1024; i += 256) {
            int nl = i >> 6, q = i & 63;
            int n = n0 + nl;
            if (n < nN)
                ((float4*)(out + n * 256))[q] = ((float4*)(ins + nl * 256))[q];
        }
    }
}

// ---------------- gate MLP (32 nodes/block, 512 thr) -> quad output ---------
__global__ void gate_kernel(const float* __restrict__ x,
                            const float* __restrict__ Wg1,
                            const float* __restrict__ bg1,
                            const float* __restrict__ Wg2,
                            const float* __restrict__ bg2,
                            float* __restrict__ outb, int nN) {
    extern __shared__ float sm[];
    float* W1s = sm;
    float* W2s = sm + 16384;
    float* f0t = sm + 32768;
    float* hst = sm + 32768 + 4352;
    int tid = threadIdx.x;
    for (int i = tid; i < 4096; i += 512) {
        ((float4*)W1s)[i] = ((const float4*)Wg1)[i];
        ((float4*)W2s)[i] = ((const float4*)Wg2)[i];
    }
    int n0 = blockIdx.x * 32;
    for (int i = tid; i < 4096; i += 512) {
        int nl = i >> 7, j = i & 127;
        int n = n0 + nl;
        float val = 0.f;
        if (n < nN) {
            const float* xr = x + n * 256;
            if (j < 64) val = xr[j];
            else {
                int u = j - 64;
                float v0 = xr[64 + u * 3], v1 = xr[64 + u * 3 + 1], v2 = xr[64 + u * 3 + 2];
                val = sqrtf(v0 * v0 + v1 * v1 + v2 * v2 + 1e-12f);
            }
        }
        f0t[j * 34 + nl] = val;
    }
    __syncthreads();
    int j = tid & 127, quarter = tid >> 7;
    {
        ull a0 = 0, a1 = 0, a2 = 0, a3 = 0;
        #pragma unroll 8
        for (int k = 0; k < 128; k++) {
            float w = W1s[k * 128 + j];
            ull wp = pack2(w, w);
            const ull* f = (const ull*)&f0t[k * 34 + quarter * 8];
            fma2(a0, wp, f[0]); fma2(a1, wp, f[1]); fma2(a2, wp, f[2]); fma2(a3, wp, f[3]);
        }
        float b = bg1[j];
        float lo, hi;
        unpack2(a0, lo, hi); hst[j * 34 + quarter * 8 + 0] = siluf(lo + b); hst[j * 34 + quarter * 8 + 1] = siluf(hi + b);
        unpack2(a1, lo, hi); hst[j * 34 + quarter * 8 + 2] = siluf(lo + b); hst[j * 34 + quarter * 8 + 3] = siluf(hi + b);
        unpack2(a2, lo, hi); hst[j * 34 + quarter * 8 + 4] = siluf(lo + b); hst[j * 34 + quarter * 8 + 5] = siluf(hi + b);
        unpack2(a3, lo, hi); hst[j * 34 + quarter * 8 + 6] = siluf(lo + b); hst[j * 34 + quarter * 8 + 7] = siluf(hi + b);
    }
    __syncthreads();
    float g[8];
    {
        ull a0 = 0, a1 = 0, a2 = 0, a3 = 0;
        #pragma unroll 8
        for (int k = 0; k < 128; k++) {
            float w = W2s[k * 128 + j];
            ull wp = pack2(w, w);
            const ull* h = (const ull*)&hst[k * 34 + quarter * 8];
            fma2(a0, wp, h[0]); fma2(a1, wp, h[1]); fma2(a2, wp, h[2]); fma2(a3, wp, h[3]);
        }
        float b = bg2[j];
        unpack2(a0, g[0], g[1]); unpack2(a1, g[2], g[3]);
        unpack2(a2, g[4], g[5]); unpack2(a3, g[6], g[7]);
        #pragma unroll
        for (int p = 0; p < 8; p++) g[p] += b;
    }
    __syncthreads();
    #pragma unroll
    for (int p = 0; p < 8; p++) f0t[(quarter * 8 + p) * 128 + j] = g[p];
    __syncthreads();
    for (int q = tid; q < 2048; q += 512) {
        int nl = q >> 6, u = q & 63;
        int n = n0 + nl;
        if (n >= nN) continue;
        float gs = f0t[nl * 128 + u];
        float gv = f0t[nl * 128 + 64 + u];
        const float* xr = x + n * 256 + 64 + u * 3;
        ((float4*)(outb + n * 256))[u] = make_float4(gs, xr[0] * gv, xr[1] * gv, xr[2] * gv);
    }
}

// ---------------- h1a = ssp(edge_attr @ Wf1 / 8) ---------------------------
__global__ void h1a_kernel(const float* __restrict__ attr,
                           const float* __restrict__ Wf1,
                           float* __restrict__ h1a, int nE) {
    __shared__ float at[64 * 68];
    __shared__ float Wf1s[64 * 32];
    int tid = threadIdx.x;
    int e0 = blockIdx.x * 64;
    for (int i = tid; i < 512; i += 256)
        ((float4*)Wf1s)[i] = ((const float4*)Wf1)[i];
    for (int i = tid; i < 1024; i += 256) {
        int el = i >> 4, u0 = (i & 15) * 4;
        int e = e0 + el;
        float4 a4 = (e < nE) ? *(const float4*)&attr[e * 64 + u0]
                             : make_float4(0.f, 0.f, 0.f, 0.f);
        at[(u0 + 0) * 68 + el] = a4.x;
        at[(u0 + 1) * 68 + el] = a4.y;
        at[(u0 + 2) * 68 + el] = a4.z;
        at[(u0 + 3) * 68 + el] = a4.w;
    }
    __syncthreads();
    int k = tid & 31, g = tid >> 5;
    ull a0 = 0, a1 = 0, a2 = 0, a3 = 0;
    #pragma unroll 4
    for (int u = 0; u < 64; u++) {
        float w = Wf1s[u * 32 + k];
        ull wp = pack2(w, w);
        const ull2* pa = (const ull2*)(at + u * 68 + g * 8);
        ull2 A0 = pa[0], A1 = pa[1];
        fma2(a0, wp, A0.x); fma2(a1, wp, A0.y);
        fma2(a2, wp, A1.x); fma2(a3, wp, A1.y);
    }
    float r[8];
    unpack2(a0, r[0], r[1]); unpack2(a1, r[2], r[3]);
    unpack2(a2, r[4], r[5]); unpack2(a3, r[6], r[7]);
    #pragma unroll
    for (int ee = 0; ee < 8; ee++) {
        int e = e0 + g * 8 + ee;
        if (e < nE) h1a[e * 32 + k] = sspf(r[ee] * 0.125f);
    }
}

// ---------------- h1l = ssp(s0 @ Wl1 / sqrt192) ----------------------------
__global__ void h1l_kernel(const int* __restrict__ ei,
                           const float* __restrict__ pre,
                           float* __restrict__ h1l, int nE, int Etot) {
    extern __shared__ float smh[];
    float* ps_t = smh;
    float* ip_t = smh + 4352;
    float* Ws   = smh + 8704;
    float* Wi   = smh + 10752;
    int*   idx  = (int*)(smh + 12800);
    int tid = threadIdx.x;
    int e0 = blockIdx.x * 64;
    for (int i = tid; i < 512; i += 256) {
        ((float4*)Ws)[i] = ((const float4*)g_Wl1s)[i];
        ((float4*)Wi)[i] = ((const float4*)g_Wl1i)[i];
    }
    if (tid < 64) {
        int e = e0 + tid;
        bool v = (e < nE);
        idx[tid]      = v ? ei[e] : 0;
        idx[64 + tid] = v ? ei[Etot + e] : 0;
    }
    __syncthreads();
    for (int i = tid; i < 4096; i += 256) {
        int u = i & 63, el = i >> 6;
        int d = idx[el], s = idx[64 + el];
        float4 qd = *(const float4*)&pre[d * 256 + u * 4];
        float4 qs = *(const float4*)&pre[s * 256 + u * 4];
        ps_t[u * 68 + el] = qd.x;
        ip_t[u * 68 + el] = (qd.y * qs.y + qd.z * qs.z + qd.w * qs.w) * (1.f / 3.f);
    }
    __syncthreads();
    int k = tid & 31, g = tid >> 5;
    ull a[4] = {};
    #pragma unroll 4
    for (int u = 0; u < 64; u++) {
        float ws = Ws[u * 32 + k];
        float wi = Wi[u * 32 + k];
        ull wps = pack2(ws, ws), wpi = pack2(wi, wi);
        const ull2* P = (const ull2*)(ps_t + u * 68 + g * 8);
        const ull2* I = (const ull2*)(ip_t + u * 68 + g * 8);
        ull2 P0 = P[0], P1 = P[1], I0 = I[0], I1 = I[1];
        fma2(a[0], wps, P0.x); fma2(a[1], wps, P0.y);
        fma2(a[2], wps, P1.x); fma2(a[3], wps, P1.y);
        fma2(a[0], wpi, I0.x); fma2(a[1], wpi, I0.y);
        fma2(a[2], wpi, I1.x); fma2(a[3], wpi, I1.y);
    }
    float r[8];
    unpack2(a[0], r[0], r[1]); unpack2(a[1], r[2], r[3]);
    unpack2(a[2], r[4], r[5]); unpack2(a[3], r[6], r[7]);
    #pragma unroll
    for (int ee = 0; ee < 8; ee++) {
        int e = e0 + g * 8 + ee;
        if (e < nE) h1l[e * 32 + k] = sspf(r[ee]);
    }
}

// ---------------- fused edge kernel: PERSISTENT + tf32 MMA -----------------
#define TE 128
#define HS 136                 // h-tile edge stride (bank-clean for A frags)
#define WSS 324                // ws row stride (floats)
#define EDGE_BLOCKS 148
__global__ void __launch_bounds__(320, 1)
edge_kernel(const int* __restrict__ ei,
            const float* __restrict__ sh,
            const float* __restrict__ h1a,
            const float* __restrict__ h1l,
            const float* __restrict__ xg,
            float* __restrict__ acc, int nE, int Etot) {
    extern __shared__ float sm[];
    float* hA  = sm;                       // 32 * 136
    float* hB  = sm + 32 * HS;             // 32 * 136
    float* ws  = sm + 2 * 32 * HS;         // 128 * 324
    float* shs = ws + TE * WSS;            // 128 * 4
    int*   idxs = (int*)(shs + TE * 4);    // src[128] | dst[128]
    int tid = threadIdx.x;
    int lane = tid & 31, wrp = tid >> 5;   // 10 warps
    int group = lane >> 2, tig = lane & 3;

    // persistent B fragments (tf32 weights) : warp wrp owns n-tiles wrp*4..wrp*4+3
    unsigned bf[4][4][2], bl[4][4][2];
    #pragma unroll
    for (int j = 0; j < 4; j++) {
        int n0 = (wrp * 4 + j) * 8;
        #pragma unroll
        for (int ks = 0; ks < 4; ks++) {
            bf[j][ks][0] = __float_as_uint(g_WfT[(n0 + group) * 32 + ks * 8 + tig]);
            bf[j][ks][1] = __float_as_uint(g_WfT[(n0 + group) * 32 + ks * 8 + tig + 4]);
            bl[j][ks][0] = __float_as_uint(g_WlT[(n0 + group) * 32 + ks * 8 + tig]);
            bl[j][ks][1] = __float_as_uint(g_WlT[(n0 + group) * 32 + ks * 8 + tig + 4]);
        }
    }

    const float PW_S = 0.44721359549995793f;
    const float PW_V = 0.77459666924148337f;
    const float IS3  = 0.57735026918962576f;
    const float IS2  = 0.70710678118654752f;

    int ntiles = (nE + TE - 1) / TE;
    for (int tile = blockIdx.x; tile < ntiles; tile += gridDim.x) {
        int e0 = tile * TE;
        // ---- stage ----
        if (tid < 128) {
            int e = e0 + tid;
            bool v = (e < nE);
            idxs[tid]       = v ? ei[Etot + e] : 0;
            idxs[128 + tid] = v ? ei[e] : -1;
            float4 s4 = v ? *(const float4*)&sh[e * 4] : make_float4(0.f, 0.f, 0.f, 0.f);
            ((float4*)shs)[tid] = s4;
        }
        for (int i = tid; i < 1024; i += 320) {
            int el = i >> 3, k0 = (i & 7) * 4;
            int e = e0 + el;
            float4 a = make_float4(0.f, 0.f, 0.f, 0.f), b = a;
            if (e < nE) {
                a = *(const float4*)&h1a[e * 32 + k0];
                b = *(const float4*)&h1l[e * 32 + k0];
            }
            hA[(k0 + 0) * HS + el] = __uint_as_float(tf32r(a.x));
            hA[(k0 + 1) * HS + el] = __uint_as_float(tf32r(a.y));
            hA[(k0 + 2) * HS + el] = __uint_as_float(tf32r(a.z));
            hA[(k0 + 3) * HS + el] = __uint_as_float(tf32r(a.w));
            hB[(k0 + 0) * HS + el] = __uint_as_float(tf32r(b.x));
            hB[(k0 + 1) * HS + el] = __uint_as_float(tf32r(b.y));
            hB[(k0 + 2) * HS + el] = __uint_as_float(tf32r(b.z));
            hB[(k0 + 3) * HS + el] = __uint_as_float(tf32r(b.w));
        }
        __syncthreads();
        // ---- phase 1: tf32 MMA pair, w = (hA@Wf) ⊙ (hB@Wl) ----
        #pragma unroll 1
        for (int m = 0; m < 8; m++) {
            int m0 = m * 16;
            unsigned aA[16], aB[16];
            #pragma unroll
            for (int ks = 0; ks < 4; ks++) {
                int r0 = (ks * 8 + tig) * HS + m0 + group;
                int r1 = (ks * 8 + tig + 4) * HS + m0 + group;
                aA[ks * 4 + 0] = __float_as_uint(hA[r0]);
                aA[ks * 4 + 1] = __float_as_uint(hA[r0 + 8]);
                aA[ks * 4 + 2] = __float_as_uint(hA[r1]);
                aA[ks * 4 + 3] = __float_as_uint(hA[r1 + 8]);
                aB[ks * 4 + 0] = __float_as_uint(hB[r0]);
                aB[ks * 4 + 1] = __float_as_uint(hB[r0 + 8]);
                aB[ks * 4 + 2] = __float_as_uint(hB[r1]);
                aB[ks * 4 + 3] = __float_as_uint(hB[r1 + 8]);
            }
            #pragma unroll
            for (int j = 0; j < 4; j++) {
                float dA[4] = {0.f, 0.f, 0.f, 0.f};
                float dB[4] = {0.f, 0.f, 0.f, 0.f};
                #pragma unroll
                for (int ks = 0; ks < 4; ks++) {
                    mma_tf32(dA, &aA[ks * 4], bf[j][ks]);
                    mma_tf32(dB, &aB[ks * 4], bl[j][ks]);
                }
                int col0 = (wrp * 4 + j) * 8 + 2 * tig;
                *(float2*)&ws[(m0 + group) * WSS + col0] =
                    make_float2(dA[0] * dB[0], dA[1] * dB[1]);
                *(float2*)&ws[(m0 + group + 8) * WSS + col0] =
                    make_float2(dA[2] * dB[2], dA[3] * dB[3]);
            }
        }
        __syncthreads();
        // ---- phase 2: tensor product + red.v4 scatter ----
        #pragma unroll 4
        for (int it = tid; it < TE * 64; it += 320) {
            int e = it >> 6, u = it & 63;
            int d = idxs[128 + e];
            if (d < 0) continue;
            int s = idxs[e];
            float4 q = *(const float4*)&xg[s * 256 + u * 4];
            float es = q.x, ev0 = q.y, ev1 = q.z, ev2 = q.w;
            float s0 = shs[e * 4], s1 = shs[e * 4 + 1], s2 = shs[e * 4 + 2], s3 = shs[e * 4 + 3];
            const float* we = ws + e * WSS;
            float w0 = we[u], w1 = we[64 + u], w2 = we[128 + u], w3 = we[192 + u], w4 = we[256 + u];
            float dotv = ev0 * s1 + ev1 * s2 + ev2 * s3;
            float c0 = ev1 * s3 - ev2 * s2;
            float c1 = ev2 * s1 - ev0 * s3;
            float c2 = ev0 * s2 - ev1 * s1;
            float outs = PW_S * (w0 * es * s0 + w3 * dotv * IS3);
            float k2 = PW_V * w2 * s0;
            float k4 = PW_V * w4 * IS2;
            float k1 = PW_V * w1 * es;
            float o0 = k1 * s1 + k2 * ev0 + k4 * c0;
            float o1 = k1 * s2 + k2 * ev1 + k4 * c1;
            float o2 = k1 * s3 + k2 * ev2 + k4 * c2;
            float* pa = acc + d * 256 + u * 4;
            asm volatile("red.global.add.v4.f32 [%0], {%1, %2, %3, %4};"
                         :: "l"(pa), "f"(outs), "f"(o0), "f"(o1), "f"(o2) : "memory");
        }
        __syncthreads();
    }
}

// ---------------- launch ----------------------------------------------------
extern "C" void kernel_launch(void* const* d_in, const int* in_sizes, int n_in,
                              void* d_out, int out_size) {
    const float* x     = (const float*)d_in[0];
    const int*   ei    = (const int*)  d_in[1];
    const float* sh    = (const float*)d_in[2];
    const float* attr  = (const float*)d_in[3];
    const float* Wpre0 = (const float*)d_in[4];
    const float* bpre0 = (const float*)d_in[5];
    const float* Wpre1 = (const float*)d_in[6];
    const float* Wg1   = (const float*)d_in[7];
    const float* bg1   = (const float*)d_in[8];
    const float* Wg2   = (const float*)d_in[9];
    const float* bg2   = (const float*)d_in[10];
    const float* Wn0   = (const float*)d_in[11];
    const float* bn0   = (const float*)d_in[12];
    const float* Wn1   = (const float*)d_in[13];
    const float* Wf1   = (const float*)d_in[14];
    const float* Wf2   = (const float*)d_in[15];
    const float* Wl1   = (const float*)d_in[16];
    const float* Wl2   = (const float*)d_in[17];
    const float* Wo0   = (const float*)d_in[18];
    const float* bo0   = (const float*)d_in[19];
    const float* Wo1   = (const float*)d_in[20];

    int N = in_sizes[0] / 256;
    int E = in_sizes[1] / 2;

    float *pre, *tmp, *xgp, *accp, *h1a, *h1l;
    cudaGetSymbolAddress((void**)&pre,  g_pre);
    cudaGetSymbolAddress((void**)&tmp,  g_tmp);
    cudaGetSymbolAddress((void**)&xgp,  g_xg);
    cudaGetSymbolAddress((void**)&accp, g_acc);
    cudaGetSymbolAddress((void**)&h1a,  g_h1a);
    cudaGetSymbolAddress((void**)&h1l,  g_h1l);

    static const int E3_SMEM   = (8192 + 4096 + 64) * 4;
    static const int GATE_SMEM = (16384 * 2 + 4352 * 2) * 4;
    static const int H1L_SMEM  = (4352 * 2 + 2048 * 2 + 128) * 4;
    static const int EDGE_SMEM = (2 * 32 * HS + TE * WSS + TE * 4 + 256 + 64) * 4;
    cudaFuncSetAttribute(e3_kernel<0,1,1>, cudaFuncAttributeMaxDynamicSharedMemorySize, E3_SMEM);
    cudaFuncSetAttribute(e3_kernel<1,1,1>, cudaFuncAttributeMaxDynamicSharedMemorySize, E3_SMEM);
    cudaFuncSetAttribute(e3_kernel<1,0,0>, cudaFuncAttributeMaxDynamicSharedMemorySize, E3_SMEM);
    cudaFuncSetAttribute(gate_kernel, cudaFuncAttributeMaxDynamicSharedMemorySize, GATE_SMEM);
    cudaFuncSetAttribute(h1l_kernel,  cudaFuncAttributeMaxDynamicSharedMemorySize, H1L_SMEM);
    cudaFuncSetAttribute(edge_kernel, cudaFuncAttributeMaxDynamicSharedMemorySize, EDGE_SMEM);

    static cudaStream_t s1 = nullptr, s2 = nullptr;
    static cudaEvent_t ev0, evP, ev1, ev2;
    if (!s1) {
        cudaStreamCreateWithFlags(&s1, cudaStreamNonBlocking);
        cudaStreamCreateWithFlags(&s2, cudaStreamNonBlocking);
        cudaEventCreateWithFlags(&ev0, cudaEventDisableTiming);
        cudaEventCreateWithFlags(&evP, cudaEventDisableTiming);
        cudaEventCreateWithFlags(&ev1, cudaEventDisableTiming);
        cudaEventCreateWithFlags(&ev2, cudaEventDisableTiming);
    }
    cudaStream_t d = 0;

    cudaEventRecord(ev0, d);
    cudaStreamWaitEvent(s1, ev0, 0);
    cudaStreamWaitEvent(s2, ev0, 0);

    gate_kernel<<<(N + 31) / 32, 512, GATE_SMEM, s1>>>(x, Wg1, bg1, Wg2, bg2, tmp, N);
    h1a_kernel<<<(E + 63) / 64, 256, 0, s2>>>(attr, Wf1, h1a, E);

    prep_kernel<<<48, 256, 0, d>>>(Wf2, Wl2, Wl1, Wpre0, Wpre1, Wn0, Wn1, Wo0, Wo1);
    cudaEventRecord(evP, d);
    e3_kernel<0, 1, 1><<<(N + 15) / 16, 256, E3_SMEM, d>>>(x, 0, bpre0, pre, nullptr, N);
    h1l_kernel<<<(E + 63) / 64, 256, H1L_SMEM, d>>>(ei, pre, h1l, E, E);

    cudaStreamWaitEvent(s1, evP, 0);
    e3_kernel<1, 1, 1><<<(N + 15) / 16, 256, E3_SMEM, s1>>>(tmp, 1, bn0, xgp, accp, N);
    cudaEventRecord(ev1, s1);
    cudaEventRecord(ev2, s2);

    cudaStreamWaitEvent(d, ev1, 0);
    cudaStreamWaitEvent(d, ev2, 0);
    int ntiles = (E + TE - 1) / TE;
    int eblocks = ntiles < EDGE_BLOCKS ? ntiles : EDGE_BLOCKS;
    edge_kernel<<<eblocks, 320, EDGE_SMEM, d>>>(ei, sh, h1a, h1l, xgp, accp, E, E);
    e3_kernel<1, 0, 0><<<(N + 15) / 16, 256, E3_SMEM, d>>>(accp, 2, bo0, (float*)d_out, nullptr, N);
}

// round 8
// speedup vs baseline: 2.2084x; 1.0716x over previous
#include <cuda_runtime.h>
#include <math.h>

#define MAXN 20000
#define MAXE 320000

typedef unsigned long long ull;
typedef ulonglong2 ull2;

// ---------------- scratch (device globals) ---------------------------------
__device__ float g_pre[MAXN * 256];
__device__ float g_tmp[MAXN * 256];
__device__ float g_xg [MAXN * 256];
__device__ float g_acc[MAXN * 256];
__device__ float g_h1a[MAXE * 32];
__device__ float g_h1l[MAXE * 32];
__device__ float g_WfT[320 * 32];     // Wf2^T * (1/sqrt32), tf32, [col][k]
__device__ float g_WlT[320 * 32];
__device__ float g_Wg1T[128 * 132];   // Wg1^T tf32, [out][in] stride 132
__device__ float g_Wg2T[128 * 132];
__device__ float g_Wf1T[32 * 72];     // (Wf1/8)^T tf32, [out][k] stride 72
__device__ float g_Wl1T[32 * 136];    // stacked Wl1^T/sqrt192 tf32, [out][k(ps64|ip64)]
__device__ ull   g_eW[3 * 4096];

__device__ __forceinline__ float sspf(float x) {
    float sp = (x > 15.f) ? x : log1pf(expf(x));
    return sp - 0.69314718055994531f;
}
__device__ __forceinline__ float siluf(float x) {
    return x / (1.f + expf(-x));
}
__device__ __forceinline__ ull pack2(float a, float b) {
    ull r; asm("mov.b64 %0, {%1, %2};" : "=l"(r) : "f"(a), "f"(b)); return r;
}
__device__ __forceinline__ void fma2(ull& d, ull a, ull b) {
    asm("fma.rn.f32x2 %0, %1, %2, %0;" : "+l"(d) : "l"(a), "l"(b));
}
__device__ __forceinline__ void unpack2(ull v, float& lo, float& hi) {
    asm("mov.b64 {%0, %1}, %2;" : "=f"(lo), "=f"(hi) : "l"(v));
}
__device__ __forceinline__ unsigned tf32r(float x) {
    unsigned r; asm("cvt.rna.tf32.f32 %0, %1;" : "=r"(r) : "f"(x)); return r;
}
__device__ __forceinline__ float tf32f(float x) {
    return __uint_as_float(tf32r(x));
}
__device__ __forceinline__ void mma_tf32(float* d, const unsigned* a, const unsigned* b) {
    asm("mma.sync.aligned.m16n8k8.row.col.f32.tf32.tf32.f32 "
        "{%0,%1,%2,%3}, {%4,%5,%6,%7}, {%8,%9}, {%0,%1,%2,%3};"
        : "+f"(d[0]), "+f"(d[1]), "+f"(d[2]), "+f"(d[3])
        : "r"(a[0]), "r"(a[1]), "r"(a[2]), "r"(a[3]), "r"(b[0]), "r"(b[1]));
}

// ---------------- weight prep ----------------------------------------------
__global__ void prep_kernel(const float* __restrict__ Wf2,
                            const float* __restrict__ Wl2,
                            const float* __restrict__ Wl1,
                            const float* __restrict__ Wpre0,
                            const float* __restrict__ Wpre1,
                            const float* __restrict__ Wn0,
                            const float* __restrict__ Wn1,
                            const float* __restrict__ Wo0,
                            const float* __restrict__ Wo1,
                            const float* __restrict__ Wg1,
                            const float* __restrict__ Wg2,
                            const float* __restrict__ Wf1) {
    int i = blockIdx.x * 256 + threadIdx.x;
    const float is32 = 0.17677669529663687f;   // 1/sqrt(32)
    const float r192 = 0.07216878364870323f;   // 1/sqrt(192)
    if (i < 320 * 32) {
        int c = i >> 5, k = i & 31;
        g_WfT[i] = tf32f(Wf2[k * 320 + c] * is32);
        g_WlT[i] = tf32f(Wl2[k * 320 + c] * is32);
    }
    if (i < 3 * 4096) {
        int p = i >> 12, r = i & 4095;
        const float* w0 = (p == 0) ? Wpre0 : (p == 1) ? Wn0 : Wo0;
        const float* w1 = (p == 0) ? Wpre1 : (p == 1) ? Wn1 : Wo1;
        g_eW[i] = pack2(w0[r] * 0.125f, w1[r] * 0.125f);
    }
    if (i < 16384) {
        int c = i >> 7, k = i & 127;
        g_Wg1T[c * 132 + k] = tf32f(Wg1[k * 128 + c]);
        g_Wg2T[c * 132 + k] = tf32f(Wg2[k * 128 + c]);
    }
    if (i < 2048) {
        int c = i >> 6, k = i & 63;
        g_Wf1T[c * 72 + k] = tf32f(Wf1[k * 32 + c] * 0.125f);
    }
    if (i < 4096) {
        int c = i >> 7, k = i & 127;
        float v = (k < 64) ? (Wl1[k * 32 + c] + Wl1[(64 + k) * 32 + c]) * r192
                           : Wl1[(64 + k) * 32 + c] * r192;
        g_Wl1T[c * 136 + k] = tf32f(v);
    }
}

// ---------------- e3_linear: 16 nodes/block --------------------------------
template<int IL, int OL, int OL2>
__global__ void e3_kernel(const float* __restrict__ in,
                          int widx,
                          const float* __restrict__ b0,
                          float* __restrict__ out,
                          float* __restrict__ out2, int nN) {
    extern __shared__ float sme3[];
    ull*   Wp  = (ull*)sme3;
    float* ins = sme3 + 8192;
    float* b0s = sme3 + 8192 + 4096;
    int tid = threadIdx.x;
    {
        const ull2* src = (const ull2*)(g_eW + widx * 4096);
        ull2* dst = (ull2*)Wp;
        for (int i = tid; i < 2048; i += 256) dst[i] = src[i];
    }
    if (tid < 64) b0s[tid] = b0[tid];
    int n0 = blockIdx.x * 16;
    if (IL == 0) {
        for (int i = tid; i < 256; i += 256) {
            int nl = i >> 4, g4 = i & 15;
            int u0 = g4 * 4;
            int n = n0 + nl;
            float4 a = make_float4(0.f,0.f,0.f,0.f), b = a, cc = a, dd = a;
            if (n < nN) {
                const float* xr = in + n * 256;
                a  = *(const float4*)(xr + u0);
                const float4* vp = (const float4*)(xr + 64 + u0 * 3);
                b = vp[0]; cc = vp[1]; dd = vp[2];
            }
            float4* q = (float4*)(ins + nl * 256 + u0 * 4);
            q[0] = make_float4(a.x, b.x, b.y, b.z);
            q[1] = make_float4(a.y, b.w, cc.x, cc.y);
            q[2] = make_float4(a.z, cc.z, cc.w, dd.x);
            q[3] = make_float4(a.w, dd.y, dd.z, dd.w);
        }
    } else {
        for (int i = tid; i < 1024; i += 256) {
            int nl = i >> 6, q = i & 63;
            int n = n0 + nl;
            float4 v = (n < nN) ? ((const float4*)(in + n * 256))[q]
                                : make_float4(0.f, 0.f, 0.f, 0.f);
            ((float4*)(ins + nl * 256))[q] = v;
        }
    }
    __syncthreads();
    int v = tid & 63, g = tid >> 6;
    const float* base = ins + g * 4 * 256;
    ull acc[4][2] = {};
    #pragma unroll 4
    for (int u = 0; u < 64; u++) {
        ull wp = Wp[u * 64 + v];
        float w0, w1; unpack2(wp, w0, w1);
        ull wq = pack2(w1, w1);
        #pragma unroll
        for (int t = 0; t < 4; t++) {
            ull2 q = *(const ull2*)(base + t * 256 + u * 4);
            fma2(acc[t][0], wp, q.x);
            fma2(acc[t][1], wq, q.y);
        }
    }
    float bias = b0s[v];
    float rs[4], r0[4], r1[4], r2[4];
    #pragma unroll
    for (int t = 0; t < 4; t++) {
        unpack2(acc[t][0], rs[t], r0[t]);
        unpack2(acc[t][1], r1[t], r2[t]);
        rs[t] += bias;
    }
    #pragma unroll
    for (int t = 0; t < 4; t++) {
        int n = n0 + g * 4 + t;
        if (n >= nN) continue;
        float4 q = make_float4(rs[t], r0[t], r1[t], r2[t]);
        if (OL == 1) ((float4*)(out + n * 256))[v] = q;
        if (out2 && OL2 == 1) ((float4*)(out2 + n * 256))[v] = q;
    }
    if (OL == 0) {
        __syncthreads();
        #pragma unroll
        for (int t = 0; t < 4; t++) {
            float* row = ins + (g * 4 + t) * 256;
            row[v] = rs[t];
            row[64 + v * 3 + 0] = r0[t];
            row[64 + v * 3 + 1] = r1[t];
            row[64 + v * 3 + 2] = r2[t];
        }
        __syncthreads();
        for (int i = tid; i < 1024; i += 256) {
            int nl = i >> 6, q = i & 63;
            int n = n0 + nl;
            if (n < nN)
                ((float4*)(out + n * 256))[q] = ((float4*)(ins + nl * 256))[q];
        }
    }
}

// ---------------- gate MLP: tf32 MMA, 64 nodes/block, 256 thr ---------------
// smem floats: W1T 0..16896 | W2T ..33792 | f0t(128x72) ..43008 (alias gbuf 64x132)
//              hst(128x72) ..52224 | biases 256
__global__ void __launch_bounds__(256, 1)
gate_mma(const float* __restrict__ x,
         const float* __restrict__ bg1,
         const float* __restrict__ bg2,
         float* __restrict__ outb, int nN) {
    extern __shared__ float sg[];
    float* W1T = sg;
    float* W2T = sg + 16896;
    float* f0t = sg + 33792;           // [k=128][node stride 72]
    float* hst = sg + 43008;           // [k=128][node stride 72]
    float* gbuf = sg + 33792;          // alias f0t: [node][132]
    float* bgs = sg + 52224;           // bg1[128] | bg2[128]
    int tid = threadIdx.x;
    for (int i = tid; i < 4224; i += 256) {
        ((float4*)W1T)[i] = ((const float4*)g_Wg1T)[i];
        ((float4*)W2T)[i] = ((const float4*)g_Wg2T)[i];
    }
    if (tid < 128) { bgs[tid] = bg1[tid]; bgs[128 + tid] = bg2[tid]; }
    int n0 = blockIdx.x * 64;
    for (int i = tid; i < 8192; i += 256) {
        int j = i >> 6, nl = i & 63;
        int n = n0 + nl;
        float val = 0.f;
        if (n < nN) {
            const float* xr = x + n * 256;
            if (j < 64) val = xr[j];
            else {
                int u = j - 64;
                float v0 = xr[64 + u * 3], v1 = xr[64 + u * 3 + 1], v2 = xr[64 + u * 3 + 2];
                val = sqrtf(v0 * v0 + v1 * v1 + v2 * v2 + 1e-12f);
            }
        }
        f0t[j * 72 + nl] = tf32f(val);
    }
    __syncthreads();
    int lane = tid & 31, w = tid >> 5;
    int group = lane >> 2, tig = lane & 3;
    int m0 = (w & 3) * 16;
    int nb = (w >> 2) * 8;             // first n-tile of this warp's 8
    // ---- layer 1 ----
    {
        float acc[8][4] = {};
        #pragma unroll 1
        for (int ks = 0; ks < 16; ks++) {
            unsigned a[4];
            int ra = (ks * 8 + tig) * 72 + m0 + group;
            int rb = (ks * 8 + tig + 4) * 72 + m0 + group;
            a[0] = __float_as_uint(f0t[ra]);
            a[1] = __float_as_uint(f0t[ra + 8]);
            a[2] = __float_as_uint(f0t[rb]);
            a[3] = __float_as_uint(f0t[rb + 8]);
            #pragma unroll
            for (int j = 0; j < 8; j++) {
                unsigned b[2];
                int br = ((nb + j) * 8 + group) * 132 + ks * 8 + tig;
                b[0] = __float_as_uint(W1T[br]);
                b[1] = __float_as_uint(W1T[br + 4]);
                mma_tf32(acc[j], a, b);
            }
        }
        #pragma unroll
        for (int j = 0; j < 8; j++) {
            int c0 = (nb + j) * 8 + 2 * tig;
            float b0 = bgs[c0], b1 = bgs[c0 + 1];
            hst[c0 * 72 + m0 + group]           = tf32f(siluf(acc[j][0] + b0));
            hst[(c0 + 1) * 72 + m0 + group]     = tf32f(siluf(acc[j][1] + b1));
            hst[c0 * 72 + m0 + group + 8]       = tf32f(siluf(acc[j][2] + b0));
            hst[(c0 + 1) * 72 + m0 + group + 8] = tf32f(siluf(acc[j][3] + b1));
        }
    }
    __syncthreads();
    // ---- layer 2 ----
    {
        float acc[8][4] = {};
        #pragma unroll 1
        for (int ks = 0; ks < 16; ks++) {
            unsigned a[4];
            int ra = (ks * 8 + tig) * 72 + m0 + group;
            int rb = (ks * 8 + tig + 4) * 72 + m0 + group;
            a[0] = __float_as_uint(hst[ra]);
            a[1] = __float_as_uint(hst[ra + 8]);
            a[2] = __float_as_uint(hst[rb]);
            a[3] = __float_as_uint(hst[rb + 8]);
            #pragma unroll
            for (int j = 0; j < 8; j++) {
                unsigned b[2];
                int br = ((nb + j) * 8 + group) * 132 + ks * 8 + tig;
                b[0] = __float_as_uint(W2T[br]);
                b[1] = __float_as_uint(W2T[br + 4]);
                mma_tf32(acc[j], a, b);
            }
        }
        #pragma unroll
        for (int j = 0; j < 8; j++) {
            int c0 = (nb + j) * 8 + 2 * tig;
            float b0 = bgs[128 + c0], b1 = bgs[128 + c0 + 1];
            gbuf[(m0 + group) * 132 + c0]           = acc[j][0] + b0;
            gbuf[(m0 + group) * 132 + c0 + 1]       = acc[j][1] + b1;
            gbuf[(m0 + group + 8) * 132 + c0]       = acc[j][2] + b0;
            gbuf[(m0 + group + 8) * 132 + c0 + 1]   = acc[j][3] + b1;
        }
    }
    __syncthreads();
    // ---- gating epilogue -> quad layout ----
    for (int q = tid; q < 4096; q += 256) {
        int nl = q >> 6, u = q & 63;
        int n = n0 + nl;
        if (n >= nN) continue;
        float gs = gbuf[nl * 132 + u];
        float gv = gbuf[nl * 132 + 64 + u];
        const float* xr = x + n * 256 + 64 + u * 3;
        ((float4*)(outb + n * 256))[u] = make_float4(gs, xr[0] * gv, xr[1] * gv, xr[2] * gv);
    }
}

// ---------------- h1a: tf32 MMA, 128 edges/block ----------------------------
// smem: at [64k][136] = 8704 | BT [32][72] = 2304
__global__ void __launch_bounds__(256, 2)
h1a_mma(const float* __restrict__ attr, float* __restrict__ h1a, int nE) {
    extern __shared__ float sa[];
    float* at = sa;
    float* BT = sa + 8704;
    int tid = threadIdx.x;
    int e0 = blockIdx.x * 128;
    for (int i = tid; i < 576; i += 256)
        ((float4*)BT)[i] = ((const float4*)g_Wf1T)[i];
    for (int i = tid; i < 2048; i += 256) {
        int el = i >> 4, u0 = (i & 15) * 4;
        int e = e0 + el;
        float4 a4 = (e < nE) ? *(const float4*)&attr[e * 64 + u0]
                             : make_float4(0.f, 0.f, 0.f, 0.f);
        at[(u0 + 0) * 136 + el] = tf32f(a4.x);
        at[(u0 + 1) * 136 + el] = tf32f(a4.y);
        at[(u0 + 2) * 136 + el] = tf32f(a4.z);
        at[(u0 + 3) * 136 + el] = tf32f(a4.w);
    }
    __syncthreads();
    int lane = tid & 31, w = tid >> 5;
    int group = lane >> 2, tig = lane & 3;
    int m0 = w * 16;
    float acc[4][4] = {};
    #pragma unroll 1
    for (int ks = 0; ks < 8; ks++) {
        unsigned a[4];
        int ra = (ks * 8 + tig) * 136 + m0 + group;
        int rb = (ks * 8 + tig + 4) * 136 + m0 + group;
        a[0] = __float_as_uint(at[ra]);
        a[1] = __float_as_uint(at[ra + 8]);
        a[2] = __float_as_uint(at[rb]);
        a[3] = __float_as_uint(at[rb + 8]);
        #pragma unroll
        for (int j = 0; j < 4; j++) {
            unsigned b[2];
            int br = (j * 8 + group) * 72 + ks * 8 + tig;
            b[0] = __float_as_uint(BT[br]);
            b[1] = __float_as_uint(BT[br + 4]);
            mma_tf32(acc[j], a, b);
        }
    }
    int eA = e0 + m0 + group, eB = eA + 8;
    #pragma unroll
    for (int j = 0; j < 4; j++) {
        int c0 = j * 8 + 2 * tig;
        if (eA < nE)
            *(float2*)&h1a[eA * 32 + c0] = make_float2(sspf(acc[j][0]), sspf(acc[j][1]));
        if (eB < nE)
            *(float2*)&h1a[eB * 32 + c0] = make_float2(sspf(acc[j][2]), sspf(acc[j][3]));
    }
}

// ---------------- h1l: tf32 MMA, 128 edges/block ----------------------------
// smem: st [128k][136] = 17408 | BT [32][136] = 4352 | idx 256
__global__ void __launch_bounds__(256, 2)
h1l_mma(const int* __restrict__ ei, const float* __restrict__ pre,
        float* __restrict__ h1l, int nE, int Etot) {
    extern __shared__ float sl[];
    float* st = sl;
    float* BT = sl + 17408;
    int*   idx = (int*)(sl + 21760);
    int tid = threadIdx.x;
    int e0 = blockIdx.x * 128;
    for (int i = tid; i < 1088; i += 256)
        ((float4*)BT)[i] = ((const float4*)g_Wl1T)[i];
    if (tid < 128) {
        int e = e0 + tid;
        bool v = (e < nE);
        idx[tid]       = v ? ei[e] : 0;          // dst
        idx[128 + tid] = v ? ei[Etot + e] : 0;   // src
    }
    __syncthreads();
    for (int i = tid; i < 8192; i += 256) {
        int el = i >> 6, u = i & 63;
        int d = idx[el], s = idx[128 + el];
        float4 qd = *(const float4*)&pre[d * 256 + u * 4];
        float4 qs = *(const float4*)&pre[s * 256 + u * 4];
        st[u * 136 + el] = tf32f(qd.x);
        st[(64 + u) * 136 + el] =
            tf32f((qd.y * qs.y + qd.z * qs.z + qd.w * qs.w) * (1.f / 3.f));
    }
    __syncthreads();
    int lane = tid & 31, w = tid >> 5;
    int group = lane >> 2, tig = lane & 3;
    int m0 = w * 16;
    float acc[4][4] = {};
    #pragma unroll 1
    for (int ks = 0; ks < 16; ks++) {
        unsigned a[4];
        int ra = (ks * 8 + tig) * 136 + m0 + group;
        int rb = (ks * 8 + tig + 4) * 136 + m0 + group;
        a[0] = __float_as_uint(st[ra]);
        a[1] = __float_as_uint(st[ra + 8]);
        a[2] = __float_as_uint(st[rb]);
        a[3] = __float_as_uint(st[rb + 8]);
        #pragma unroll
        for (int j = 0; j < 4; j++) {
            unsigned b[2];
            int br = (j * 8 + group) * 136 + ks * 8 + tig;
            b[0] = __float_as_uint(BT[br]);
            b[1] = __float_as_uint(BT[br + 4]);
            mma_tf32(acc[j], a, b);
        }
    }
    int eA = e0 + m0 + group, eB = eA + 8;
    #pragma unroll
    for (int j = 0; j < 4; j++) {
        int c0 = j * 8 + 2 * tig;
        if (eA < nE)
            *(float2*)&h1l[eA * 32 + c0] = make_float2(sspf(acc[j][0]), sspf(acc[j][1]));
        if (eB < nE)
            *(float2*)&h1l[eB * 32 + c0] = make_float2(sspf(acc[j][2]), sspf(acc[j][3]));
    }
}

// ---------------- fused edge kernel: PERSISTENT + tf32 MMA -----------------
#define TE 128
#define HS 136
#define WSS 324
#define EDGE_BLOCKS 148
__global__ void __launch_bounds__(320, 1)
edge_kernel(const int* __restrict__ ei,
            const float* __restrict__ sh,
            const float* __restrict__ h1a,
            const float* __restrict__ h1l,
            const float* __restrict__ xg,
            float* __restrict__ acc, int nE, int Etot) {
    extern __shared__ float sm[];
    float* hA  = sm;
    float* hB  = sm + 32 * HS;
    float* ws  = sm + 2 * 32 * HS;
    float* shs = ws + TE * WSS;
    int*   idxs = (int*)(shs + TE * 4);
    int tid = threadIdx.x;
    int lane = tid & 31, wrp = tid >> 5;
    int group = lane >> 2, tig = lane & 3;

    unsigned bf[4][4][2], bl[4][4][2];
    #pragma unroll
    for (int j = 0; j < 4; j++) {
        int n0 = (wrp * 4 + j) * 8;
        #pragma unroll
        for (int ks = 0; ks < 4; ks++) {
            bf[j][ks][0] = __float_as_uint(g_WfT[(n0 + group) * 32 + ks * 8 + tig]);
            bf[j][ks][1] = __float_as_uint(g_WfT[(n0 + group) * 32 + ks * 8 + tig + 4]);
            bl[j][ks][0] = __float_as_uint(g_WlT[(n0 + group) * 32 + ks * 8 + tig]);
            bl[j][ks][1] = __float_as_uint(g_WlT[(n0 + group) * 32 + ks * 8 + tig + 4]);
        }
    }

    const float PW_S = 0.44721359549995793f;
    const float PW_V = 0.77459666924148337f;
    const float IS3  = 0.57735026918962576f;
    const float IS2  = 0.70710678118654752f;

    int ntiles = (nE + TE - 1) / TE;
    for (int tile = blockIdx.x; tile < ntiles; tile += gridDim.x) {
        int e0 = tile * TE;
        if (tid < 128) {
            int e = e0 + tid;
            bool v = (e < nE);
            idxs[tid]       = v ? ei[Etot + e] : 0;
            idxs[128 + tid] = v ? ei[e] : -1;
            float4 s4 = v ? *(const float4*)&sh[e * 4] : make_float4(0.f, 0.f, 0.f, 0.f);
            ((float4*)shs)[tid] = s4;
        }
        for (int i = tid; i < 1024; i += 320) {
            int el = i >> 3, k0 = (i & 7) * 4;
            int e = e0 + el;
            float4 a = make_float4(0.f, 0.f, 0.f, 0.f), b = a;
            if (e < nE) {
                a = *(const float4*)&h1a[e * 32 + k0];
                b = *(const float4*)&h1l[e * 32 + k0];
            }
            hA[(k0 + 0) * HS + el] = tf32f(a.x);
            hA[(k0 + 1) * HS + el] = tf32f(a.y);
            hA[(k0 + 2) * HS + el] = tf32f(a.z);
            hA[(k0 + 3) * HS + el] = tf32f(a.w);
            hB[(k0 + 0) * HS + el] = tf32f(b.x);
            hB[(k0 + 1) * HS + el] = tf32f(b.y);
            hB[(k0 + 2) * HS + el] = tf32f(b.z);
            hB[(k0 + 3) * HS + el] = tf32f(b.w);
        }
        __syncthreads();
        #pragma unroll 1
        for (int m = 0; m < 8; m++) {
            int m0 = m * 16;
            unsigned aA[16], aB[16];
            #pragma unroll
            for (int ks = 0; ks < 4; ks++) {
                int r0 = (ks * 8 + tig) * HS + m0 + group;
                int r1 = (ks * 8 + tig + 4) * HS + m0 + group;
                aA[ks * 4 + 0] = __float_as_uint(hA[r0]);
                aA[ks * 4 + 1] = __float_as_uint(hA[r0 + 8]);
                aA[ks * 4 + 2] = __float_as_uint(hA[r1]);
                aA[ks * 4 + 3] = __float_as_uint(hA[r1 + 8]);
                aB[ks * 4 + 0] = __float_as_uint(hB[r0]);
                aB[ks * 4 + 1] = __float_as_uint(hB[r0 + 8]);
                aB[ks * 4 + 2] = __float_as_uint(hB[r1]);
                aB[ks * 4 + 3] = __float_as_uint(hB[r1 + 8]);
            }
            #pragma unroll
            for (int j = 0; j < 4; j++) {
                float dA[4] = {0.f, 0.f, 0.f, 0.f};
                float dB[4] = {0.f, 0.f, 0.f, 0.f};
                #pragma unroll
                for (int ks = 0; ks < 4; ks++) {
                    mma_tf32(dA, &aA[ks * 4], bf[j][ks]);
                    mma_tf32(dB, &aB[ks * 4], bl[j][ks]);
                }
                int col0 = (wrp * 4 + j) * 8 + 2 * tig;
                *(float2*)&ws[(m0 + group) * WSS + col0] =
                    make_float2(dA[0] * dB[0], dA[1] * dB[1]);
                *(float2*)&ws[(m0 + group + 8) * WSS + col0] =
                    make_float2(dA[2] * dB[2], dA[3] * dB[3]);
            }
        }
        __syncthreads();
        #pragma unroll 4
        for (int it = tid; it < TE * 64; it += 320) {
            int e = it >> 6, u = it & 63;
            int d = idxs[128 + e];
            if (d < 0) continue;
            int s = idxs[e];
            float4 q = *(const float4*)&xg[s * 256 + u * 4];
            float es = q.x, ev0 = q.y, ev1 = q.z, ev2 = q.w;
            float s0 = shs[e * 4], s1 = shs[e * 4 + 1], s2 = shs[e * 4 + 2], s3 = shs[e * 4 + 3];
            const float* we = ws + e * WSS;
            float w0 = we[u], w1 = we[64 + u], w2 = we[128 + u], w3 = we[192 + u], w4 = we[256 + u];
            float dotv = ev0 * s1 + ev1 * s2 + ev2 * s3;
            float c0 = ev1 * s3 - ev2 * s2;
            float c1 = ev2 * s1 - ev0 * s3;
            float c2 = ev0 * s2 - ev1 * s1;
            float outs = PW_S * (w0 * es * s0 + w3 * dotv * IS3);
            float k2 = PW_V * w2 * s0;
            float k4 = PW_V * w4 * IS2;
            float k1 = PW_V * w1 * es;
            float o0 = k1 * s1 + k2 * ev0 + k4 * c0;
            float o1 = k1 * s2 + k2 * ev1 + k4 * c1;
            float o2 = k1 * s3 + k2 * ev2 + k4 * c2;
            float* pa = acc + d * 256 + u * 4;
            asm volatile("red.global.add.v4.f32 [%0], {%1, %2, %3, %4};"
                         :: "l"(pa), "f"(outs), "f"(o0), "f"(o1), "f"(o2) : "memory");
        }
        __syncthreads();
    }
}

// ---------------- launch ----------------------------------------------------
extern "C" void kernel_launch(void* const* d_in, const int* in_sizes, int n_in,
                              void* d_out, int out_size) {
    const float* x     = (const float*)d_in[0];
    const int*   ei    = (const int*)  d_in[1];
    const float* sh    = (const float*)d_in[2];
    const float* attr  = (const float*)d_in[3];
    const float* Wpre0 = (const float*)d_in[4];
    const float* bpre0 = (const float*)d_in[5];
    const float* Wpre1 = (const float*)d_in[6];
    const float* Wg1   = (const float*)d_in[7];
    const float* bg1   = (const float*)d_in[8];
    const float* Wg2   = (const float*)d_in[9];
    const float* bg2   = (const float*)d_in[10];
    const float* Wn0   = (const float*)d_in[11];
    const float* bn0   = (const float*)d_in[12];
    const float* Wn1   = (const float*)d_in[13];
    const float* Wf1   = (const float*)d_in[14];
    const float* Wf2   = (const float*)d_in[15];
    const float* Wl1   = (const float*)d_in[16];
    const float* Wl2   = (const float*)d_in[17];
    const float* Wo0   = (const float*)d_in[18];
    const float* bo0   = (const float*)d_in[19];
    const float* Wo1   = (const float*)d_in[20];

    int N = in_sizes[0] / 256;
    int E = in_sizes[1] / 2;

    float *pre, *tmp, *xgp, *accp, *h1a, *h1l;
    cudaGetSymbolAddress((void**)&pre,  g_pre);
    cudaGetSymbolAddress((void**)&tmp,  g_tmp);
    cudaGetSymbolAddress((void**)&xgp,  g_xg);
    cudaGetSymbolAddress((void**)&accp, g_acc);
    cudaGetSymbolAddress((void**)&h1a,  g_h1a);
    cudaGetSymbolAddress((void**)&h1l,  g_h1l);

    static const int E3_SMEM   = (8192 + 4096 + 64) * 4;
    static const int GATE_SMEM = 52480 * 4;                     // 209,920 B
    static const int H1A_SMEM  = (8704 + 2304) * 4;             // 44 KB
    static const int H1L_SMEM  = (17408 + 4352 + 256) * 4;      // 88 KB
    static const int EDGE_SMEM = (2 * 32 * HS + TE * WSS + TE * 4 + 256 + 64) * 4;
    cudaFuncSetAttribute(e3_kernel<0,1,1>, cudaFuncAttributeMaxDynamicSharedMemorySize, E3_SMEM);
    cudaFuncSetAttribute(e3_kernel<1,1,1>, cudaFuncAttributeMaxDynamicSharedMemorySize, E3_SMEM);
    cudaFuncSetAttribute(e3_kernel<1,0,0>, cudaFuncAttributeMaxDynamicSharedMemorySize, E3_SMEM);
    cudaFuncSetAttribute(gate_mma, cudaFuncAttributeMaxDynamicSharedMemorySize, GATE_SMEM);
    cudaFuncSetAttribute(h1a_mma,  cudaFuncAttributeMaxDynamicSharedMemorySize, H1A_SMEM);
    cudaFuncSetAttribute(h1l_mma,  cudaFuncAttributeMaxDynamicSharedMemorySize, H1L_SMEM);
    cudaFuncSetAttribute(edge_kernel, cudaFuncAttributeMaxDynamicSharedMemorySize, EDGE_SMEM);

    static cudaStream_t s1 = nullptr, s2 = nullptr;
    static cudaEvent_t ev0, evP, ev1, ev2;
    if (!s1) {
        cudaStreamCreateWithFlags(&s1, cudaStreamNonBlocking);
        cudaStreamCreateWithFlags(&s2, cudaStreamNonBlocking);
        cudaEventCreateWithFlags(&ev0, cudaEventDisableTiming);
        cudaEventCreateWithFlags(&evP, cudaEventDisableTiming);
        cudaEventCreateWithFlags(&ev1, cudaEventDisableTiming);
        cudaEventCreateWithFlags(&ev2, cudaEventDisableTiming);
    }
    cudaStream_t d = 0;

    // prep first (everything tf32/transposed depends on it)
    prep_kernel<<<64, 256, 0, d>>>(Wf2, Wl2, Wl1, Wpre0, Wpre1, Wn0, Wn1, Wo0, Wo1,
                                   Wg1, Wg2, Wf1);
    cudaEventRecord(evP, d);
    cudaStreamWaitEvent(s1, evP, 0);
    cudaStreamWaitEvent(s2, evP, 0);

    // s1: gate -> e3n
    gate_mma<<<(N + 63) / 64, 256, GATE_SMEM, s1>>>(x, bg1, bg2, tmp, N);
    e3_kernel<1, 1, 1><<<(N + 15) / 16, 256, E3_SMEM, s1>>>(tmp, 1, bn0, xgp, accp, N);
    cudaEventRecord(ev1, s1);

    // s2: h1a
    h1a_mma<<<(E + 127) / 128, 256, H1A_SMEM, s2>>>(attr, h1a, E);
    cudaEventRecord(ev2, s2);

    // d: e3pre -> h1l
    e3_kernel<0, 1, 1><<<(N + 15) / 16, 256, E3_SMEM, d>>>(x, 0, bpre0, pre, nullptr, N);
    h1l_mma<<<(E + 127) / 128, 256, H1L_SMEM, d>>>(ei, pre, h1l, E, E);

    // join: edge -> final e3
    cudaStreamWaitEvent(d, ev1, 0);
    cudaStreamWaitEvent(d, ev2, 0);
    int ntiles = (E + TE - 1) / TE;
    int eblocks = ntiles < EDGE_BLOCKS ? ntiles : EDGE_BLOCKS;
    edge_kernel<<<eblocks, 320, EDGE_SMEM, d>>>(ei, sh, h1a, h1l, xgp, accp, E, E);
    e3_kernel<1, 0, 0><<<(N + 15) / 16, 256, E3_SMEM, d>>>(accp, 2, bo0, (float*)d_out, nullptr, N);
}

// round 9
// speedup vs baseline: 2.4191x; 1.0954x over previous
#include <cuda_runtime.h>
#include <math.h>

#define MAXN 20000
#define MAXE 320000

typedef unsigned long long ull;
typedef ulonglong2 ull2;

// ---------------- scratch (device globals) ---------------------------------
__device__ float g_pre[MAXN * 256];
__device__ float g_tmp[MAXN * 256];
__device__ float g_xg [MAXN * 256];
__device__ float g_acc[MAXN * 256];
__device__ float g_h1a[MAXE * 32];
__device__ float g_h1l[MAXE * 32];
__device__ float g_WfT[320 * 32];     // Wf2^T * (1/sqrt32), tf32, [col][k]
__device__ float g_WlT[320 * 32];
__device__ float g_Wf1T[32 * 72];     // (Wf1/8)^T tf32, [out][k] stride 72
__device__ float g_Wl1T[32 * 136];    // stacked Wl1^T/sqrt192 tf32
__device__ ull   g_eW[3 * 4096];

__device__ __forceinline__ float sspf(float x) {
    float sp = (x > 15.f) ? x : log1pf(expf(x));
    return sp - 0.69314718055994531f;
}
__device__ __forceinline__ float siluf(float x) {
    return x / (1.f + expf(-x));
}
__device__ __forceinline__ ull pack2(float a, float b) {
    ull r; asm("mov.b64 %0, {%1, %2};" : "=l"(r) : "f"(a), "f"(b)); return r;
}
__device__ __forceinline__ void fma2(ull& d, ull a, ull b) {
    asm("fma.rn.f32x2 %0, %1, %2, %0;" : "+l"(d) : "l"(a), "l"(b));
}
__device__ __forceinline__ void unpack2(ull v, float& lo, float& hi) {
    asm("mov.b64 {%0, %1}, %2;" : "=f"(lo), "=f"(hi) : "l"(v));
}
__device__ __forceinline__ unsigned tf32r(float x) {
    unsigned r; asm("cvt.rna.tf32.f32 %0, %1;" : "=r"(r) : "f"(x)); return r;
}
__device__ __forceinline__ float tf32f(float x) {
    return __uint_as_float(tf32r(x));
}
__device__ __forceinline__ void mma_tf32(float* d, const unsigned* a, const unsigned* b) {
    asm("mma.sync.aligned.m16n8k8.row.col.f32.tf32.tf32.f32 "
        "{%0,%1,%2,%3}, {%4,%5,%6,%7}, {%8,%9}, {%0,%1,%2,%3};"
        : "+f"(d[0]), "+f"(d[1]), "+f"(d[2]), "+f"(d[3])
        : "r"(a[0]), "r"(a[1]), "r"(a[2]), "r"(a[3]), "r"(b[0]), "r"(b[1]));
}

// ---------------- weight prep ----------------------------------------------
__global__ void prep_kernel(const float* __restrict__ Wf2,
                            const float* __restrict__ Wl2,
                            const float* __restrict__ Wl1,
                            const float* __restrict__ Wpre0,
                            const float* __restrict__ Wpre1,
                            const float* __restrict__ Wn0,
                            const float* __restrict__ Wn1,
                            const float* __restrict__ Wo0,
                            const float* __restrict__ Wo1,
                            const float* __restrict__ Wf1) {
    int i = blockIdx.x * 256 + threadIdx.x;
    const float is32 = 0.17677669529663687f;   // 1/sqrt(32)
    const float r192 = 0.07216878364870323f;   // 1/sqrt(192)
    if (i < 320 * 32) {
        int c = i >> 5, k = i & 31;
        g_WfT[i] = tf32f(Wf2[k * 320 + c] * is32);
        g_WlT[i] = tf32f(Wl2[k * 320 + c] * is32);
    }
    if (i < 3 * 4096) {
        int p = i >> 12, r = i & 4095;
        const float* w0 = (p == 0) ? Wpre0 : (p == 1) ? Wn0 : Wo0;
        const float* w1 = (p == 0) ? Wpre1 : (p == 1) ? Wn1 : Wo1;
        g_eW[i] = pack2(w0[r] * 0.125f, w1[r] * 0.125f);
    }
    if (i < 2048) {
        int c = i >> 6, k = i & 63;
        g_Wf1T[c * 72 + k] = tf32f(Wf1[k * 32 + c] * 0.125f);
    }
    if (i < 4096) {
        int c = i >> 7, k = i & 127;
        float v = (k < 64) ? (Wl1[k * 32 + c] + Wl1[(64 + k) * 32 + c]) * r192
                           : Wl1[(64 + k) * 32 + c] * r192;
        g_Wl1T[c * 136 + k] = tf32f(v);
    }
}

// ---------------- e3_linear: 16 nodes/block --------------------------------
template<int IL, int OL, int OL2>
__global__ void e3_kernel(const float* __restrict__ in,
                          int widx,
                          const float* __restrict__ b0,
                          float* __restrict__ out,
                          float* __restrict__ out2, int nN) {
    extern __shared__ float sme3[];
    ull*   Wp  = (ull*)sme3;
    float* ins = sme3 + 8192;
    float* b0s = sme3 + 8192 + 4096;
    int tid = threadIdx.x;
    {
        const ull2* src = (const ull2*)(g_eW + widx * 4096);
        ull2* dst = (ull2*)Wp;
        for (int i = tid; i < 2048; i += 256) dst[i] = src[i];
    }
    if (tid < 64) b0s[tid] = b0[tid];
    int n0 = blockIdx.x * 16;
    if (IL == 0) {
        for (int i = tid; i < 256; i += 256) {
            int nl = i >> 4, g4 = i & 15;
            int u0 = g4 * 4;
            int n = n0 + nl;
            float4 a = make_float4(0.f,0.f,0.f,0.f), b = a, cc = a, dd = a;
            if (n < nN) {
                const float* xr = in + n * 256;
                a  = *(const float4*)(xr + u0);
                const float4* vp = (const float4*)(xr + 64 + u0 * 3);
                b = vp[0]; cc = vp[1]; dd = vp[2];
            }
            float4* q = (float4*)(ins + nl * 256 + u0 * 4);
            q[0] = make_float4(a.x, b.x, b.y, b.z);
            q[1] = make_float4(a.y, b.w, cc.x, cc.y);
            q[2] = make_float4(a.z, cc.z, cc.w, dd.x);
            q[3] = make_float4(a.w, dd.y, dd.z, dd.w);
        }
    } else {
        for (int i = tid; i < 1024; i += 256) {
            int nl = i >> 6, q = i & 63;
            int n = n0 + nl;
            float4 v = (n < nN) ? ((const float4*)(in + n * 256))[q]
                                : make_float4(0.f, 0.f, 0.f, 0.f);
            ((float4*)(ins + nl * 256))[q] = v;
        }
    }
    __syncthreads();
    int v = tid & 63, g = tid >> 6;
    const float* base = ins + g * 4 * 256;
    ull acc[4][2] = {};
    #pragma unroll 4
    for (int u = 0; u < 64; u++) {
        ull wp = Wp[u * 64 + v];
        float w0, w1; unpack2(wp, w0, w1);
        ull wq = pack2(w1, w1);
        #pragma unroll
        for (int t = 0; t < 4; t++) {
            ull2 q = *(const ull2*)(base + t * 256 + u * 4);
            fma2(acc[t][0], wp, q.x);
            fma2(acc[t][1], wq, q.y);
        }
    }
    float bias = b0s[v];
    float rs[4], r0[4], r1[4], r2[4];
    #pragma unroll
    for (int t = 0; t < 4; t++) {
        unpack2(acc[t][0], rs[t], r0[t]);
        unpack2(acc[t][1], r1[t], r2[t]);
        rs[t] += bias;
    }
    #pragma unroll
    for (int t = 0; t < 4; t++) {
        int n = n0 + g * 4 + t;
        if (n >= nN) continue;
        float4 q = make_float4(rs[t], r0[t], r1[t], r2[t]);
        if (OL == 1) ((float4*)(out + n * 256))[v] = q;
        if (out2 && OL2 == 1) ((float4*)(out2 + n * 256))[v] = q;
    }
    if (OL == 0) {
        __syncthreads();
        #pragma unroll
        for (int t = 0; t < 4; t++) {
            float* row = ins + (g * 4 + t) * 256;
            row[v] = rs[t];
            row[64 + v * 3 + 0] = r0[t];
            row[64 + v * 3 + 1] = r1[t];
            row[64 + v * 3 + 2] = r2[t];
        }
        __syncthreads();
        for (int i = tid; i < 1024; i += 256) {
            int nl = i >> 6, q = i & 63;
            int n = n0 + nl;
            if (n < nN)
                ((float4*)(out + n * 256))[q] = ((float4*)(ins + nl * 256))[q];
        }
    }
}

// ---------------- gate MLP (fp32 f32x2, 32 nodes/block, 512 thr) ------------
__global__ void gate_kernel(const float* __restrict__ x,
                            const float* __restrict__ Wg1,
                            const float* __restrict__ bg1,
                            const float* __restrict__ Wg2,
                            const float* __restrict__ bg2,
                            float* __restrict__ outb, int nN) {
    extern __shared__ float sm[];
    float* W1s = sm;
    float* W2s = sm + 16384;
    float* f0t = sm + 32768;
    float* hst = sm + 32768 + 4352;
    int tid = threadIdx.x;
    for (int i = tid; i < 4096; i += 512) {
        ((float4*)W1s)[i] = ((const float4*)Wg1)[i];
        ((float4*)W2s)[i] = ((const float4*)Wg2)[i];
    }
    int n0 = blockIdx.x * 32;
    for (int i = tid; i < 4096; i += 512) {
        int nl = i >> 7, j = i & 127;
        int n = n0 + nl;
        float val = 0.f;
        if (n < nN) {
            const float* xr = x + n * 256;
            if (j < 64) val = xr[j];
            else {
                int u = j - 64;
                float v0 = xr[64 + u * 3], v1 = xr[64 + u * 3 + 1], v2 = xr[64 + u * 3 + 2];
                val = sqrtf(v0 * v0 + v1 * v1 + v2 * v2 + 1e-12f);
            }
        }
        f0t[j * 34 + nl] = val;
    }
    __syncthreads();
    int j = tid & 127, quarter = tid >> 7;
    {
        ull a0 = 0, a1 = 0, a2 = 0, a3 = 0;
        #pragma unroll 8
        for (int k = 0; k < 128; k++) {
            float w = W1s[k * 128 + j];
            ull wp = pack2(w, w);
            const ull* f = (const ull*)&f0t[k * 34 + quarter * 8];
            fma2(a0, wp, f[0]); fma2(a1, wp, f[1]); fma2(a2, wp, f[2]); fma2(a3, wp, f[3]);
        }
        float b = bg1[j];
        float lo, hi;
        unpack2(a0, lo, hi); hst[j * 34 + quarter * 8 + 0] = siluf(lo + b); hst[j * 34 + quarter * 8 + 1] = siluf(hi + b);
        unpack2(a1, lo, hi); hst[j * 34 + quarter * 8 + 2] = siluf(lo + b); hst[j * 34 + quarter * 8 + 3] = siluf(hi + b);
        unpack2(a2, lo, hi); hst[j * 34 + quarter * 8 + 4] = siluf(lo + b); hst[j * 34 + quarter * 8 + 5] = siluf(hi + b);
        unpack2(a3, lo, hi); hst[j * 34 + quarter * 8 + 6] = siluf(lo + b); hst[j * 34 + quarter * 8 + 7] = siluf(hi + b);
    }
    __syncthreads();
    float g[8];
    {
        ull a0 = 0, a1 = 0, a2 = 0, a3 = 0;
        #pragma unroll 8
        for (int k = 0; k < 128; k++) {
            float w = W2s[k * 128 + j];
            ull wp = pack2(w, w);
            const ull* h = (const ull*)&hst[k * 34 + quarter * 8];
            fma2(a0, wp, h[0]); fma2(a1, wp, h[1]); fma2(a2, wp, h[2]); fma2(a3, wp, h[3]);
        }
        float b = bg2[j];
        unpack2(a0, g[0], g[1]); unpack2(a1, g[2], g[3]);
        unpack2(a2, g[4], g[5]); unpack2(a3, g[6], g[7]);
        #pragma unroll
        for (int p = 0; p < 8; p++) g[p] += b;
    }
    __syncthreads();
    #pragma unroll
    for (int p = 0; p < 8; p++) f0t[(quarter * 8 + p) * 128 + j] = g[p];
    __syncthreads();
    for (int q = tid; q < 2048; q += 512) {
        int nl = q >> 6, u = q & 63;
        int n = n0 + nl;
        if (n >= nN) continue;
        float gs = f0t[nl * 128 + u];
        float gv = f0t[nl * 128 + 64 + u];
        const float* xr = x + n * 256 + 64 + u * 3;
        ((float4*)(outb + n * 256))[u] = make_float4(gs, xr[0] * gv, xr[1] * gv, xr[2] * gv);
    }
}

// ---------------- h1a: tf32 MMA, row-major tile, 128 edges/block ------------
__global__ void __launch_bounds__(256, 2)
h1a_mma(const float* __restrict__ attr, float* __restrict__ h1a, int nE) {
    extern __shared__ float sa[];
    float* at = sa;                     // [el][68]
    float* BT = sa + 8704;              // [32][72]
    int tid = threadIdx.x;
    int e0 = blockIdx.x * 128;
    for (int i = tid; i < 576; i += 256)
        ((float4*)BT)[i] = ((const float4*)g_Wf1T)[i];
    for (int i = tid; i < 2048; i += 256) {
        int el = i >> 4, u0 = (i & 15) * 4;
        int e = e0 + el;
        float4 a4 = (e < nE) ? *(const float4*)&attr[e * 64 + u0]
                             : make_float4(0.f, 0.f, 0.f, 0.f);
        *(float4*)&at[el * 68 + u0] =
            make_float4(tf32f(a4.x), tf32f(a4.y), tf32f(a4.z), tf32f(a4.w));
    }
    __syncthreads();
    int lane = tid & 31, w = tid >> 5;
    int group = lane >> 2, tig = lane & 3;
    int m0 = w * 16;
    int rowA = (m0 + group) * 68;
    float acc[4][4] = {};
    #pragma unroll 1
    for (int ks = 0; ks < 8; ks++) {
        int c = ks * 8 + tig;
        unsigned a[4];
        a[0] = __float_as_uint(at[rowA + c]);
        a[1] = __float_as_uint(at[rowA + 544 + c]);
        a[2] = __float_as_uint(at[rowA + c + 4]);
        a[3] = __float_as_uint(at[rowA + 544 + c + 4]);
        #pragma unroll
        for (int j = 0; j < 4; j++) {
            unsigned b[2];
            int br = (j * 8 + group) * 72 + ks * 8 + tig;
            b[0] = __float_as_uint(BT[br]);
            b[1] = __float_as_uint(BT[br + 4]);
            mma_tf32(acc[j], a, b);
        }
    }
    int eA = e0 + m0 + group, eB = eA + 8;
    #pragma unroll
    for (int j = 0; j < 4; j++) {
        int c0 = j * 8 + 2 * tig;
        if (eA < nE)
            *(float2*)&h1a[eA * 32 + c0] = make_float2(sspf(acc[j][0]), sspf(acc[j][1]));
        if (eB < nE)
            *(float2*)&h1a[eB * 32 + c0] = make_float2(sspf(acc[j][2]), sspf(acc[j][3]));
    }
}

// ---------------- h1l: tf32 MMA, row-major tile, 128 edges/block ------------
__global__ void __launch_bounds__(256, 2)
h1l_mma(const int* __restrict__ ei, const float* __restrict__ pre,
        float* __restrict__ h1l, int nE, int Etot) {
    extern __shared__ float sl[];
    float* st = sl;                     // [el][132]
    float* BT = sl + 16896;             // [32][136]
    int*   idx = (int*)(sl + 21248);
    int tid = threadIdx.x;
    int e0 = blockIdx.x * 128;
    for (int i = tid; i < 1088; i += 256)
        ((float4*)BT)[i] = ((const float4*)g_Wl1T)[i];
    if (tid < 128) {
        int e = e0 + tid;
        bool v = (e < nE);
        idx[tid]       = v ? ei[e] : 0;
        idx[128 + tid] = v ? ei[Etot + e] : 0;
    }
    __syncthreads();
    for (int i = tid; i < 8192; i += 256) {
        int el = i >> 6, u = i & 63;
        int d = idx[el], s = idx[128 + el];
        float4 qd = *(const float4*)&pre[d * 256 + u * 4];
        float4 qs = *(const float4*)&pre[s * 256 + u * 4];
        st[el * 132 + u] = tf32f(qd.x);
        st[el * 132 + 64 + u] =
            tf32f((qd.y * qs.y + qd.z * qs.z + qd.w * qs.w) * (1.f / 3.f));
    }
    __syncthreads();
    int lane = tid & 31, w = tid >> 5;
    int group = lane >> 2, tig = lane & 3;
    int m0 = w * 16;
    int rowA = (m0 + group) * 132;
    float acc[4][4] = {};
    #pragma unroll 1
    for (int ks = 0; ks < 16; ks++) {
        int c = ks * 8 + tig;
        unsigned a[4];
        a[0] = __float_as_uint(st[rowA + c]);
        a[1] = __float_as_uint(st[rowA + 1056 + c]);   // +8*132
        a[2] = __float_as_uint(st[rowA + c + 4]);
        a[3] = __float_as_uint(st[rowA + 1056 + c + 4]);
        #pragma unroll
        for (int j = 0; j < 4; j++) {
            unsigned b[2];
            int br = (j * 8 + group) * 136 + ks * 8 + tig;
            b[0] = __float_as_uint(BT[br]);
            b[1] = __float_as_uint(BT[br + 4]);
            mma_tf32(acc[j], a, b);
        }
    }
    int eA = e0 + m0 + group, eB = eA + 8;
    #pragma unroll
    for (int j = 0; j < 4; j++) {
        int c0 = j * 8 + 2 * tig;
        if (eA < nE)
            *(float2*)&h1l[eA * 32 + c0] = make_float2(sspf(acc[j][0]), sspf(acc[j][1]));
        if (eB < nE)
            *(float2*)&h1l[eB * 32 + c0] = make_float2(sspf(acc[j][2]), sspf(acc[j][3]));
    }
}

// ---------------- fused edge kernel: PERSISTENT, TE=64, 2 blocks/SM ---------
#define TE 64
#define HRS 36                 // row-major h-tile stride
#define WSS 324
#define EDGE_BLOCKS 296
__global__ void __launch_bounds__(320, 2)
edge_kernel(const int* __restrict__ ei,
            const float* __restrict__ sh,
            const float* __restrict__ h1a,
            const float* __restrict__ h1l,
            const float* __restrict__ xg,
            float* __restrict__ acc, int nE, int Etot) {
    extern __shared__ float sm[];
    float* hA  = sm;                       // 64 * 36
    float* hB  = sm + TE * HRS;            // 64 * 36
    float* ws  = sm + 2 * TE * HRS;        // 64 * 324
    float* shs = ws + TE * WSS;            // 64 * 4
    int*   idxs = (int*)(shs + TE * 4);    // src[64] | dst[64]
    int tid = threadIdx.x;
    int lane = tid & 31, wrp = tid >> 5;   // 10 warps
    int group = lane >> 2, tig = lane & 3;

    // persistent Wf B-fragments; Wl fragments read from L1-resident global
    unsigned bf[4][4][2];
    #pragma unroll
    for (int j = 0; j < 4; j++) {
        int n0 = (wrp * 4 + j) * 8;
        #pragma unroll
        for (int ks = 0; ks < 4; ks++) {
            bf[j][ks][0] = __float_as_uint(g_WfT[(n0 + group) * 32 + ks * 8 + tig]);
            bf[j][ks][1] = __float_as_uint(g_WfT[(n0 + group) * 32 + ks * 8 + tig + 4]);
        }
    }

    const float PW_S = 0.44721359549995793f;
    const float PW_V = 0.77459666924148337f;
    const float IS3  = 0.57735026918962576f;
    const float IS2  = 0.70710678118654752f;

    int ntiles = (nE + TE - 1) / TE;
    for (int tile = blockIdx.x; tile < ntiles; tile += gridDim.x) {
        int e0 = tile * TE;
        // ---- stage ----
        if (tid < 64) {
            int e = e0 + tid;
            bool v = (e < nE);
            idxs[tid]      = v ? ei[Etot + e] : 0;
            idxs[64 + tid] = v ? ei[e] : -1;
            float4 s4 = v ? *(const float4*)&sh[e * 4] : make_float4(0.f, 0.f, 0.f, 0.f);
            ((float4*)shs)[tid] = s4;
        }
        for (int i = tid; i < 512; i += 320) {
            int el = i >> 3, k0 = (i & 7) * 4;
            int e = e0 + el;
            float4 a = make_float4(0.f, 0.f, 0.f, 0.f), b = a;
            if (e < nE) {
                a = *(const float4*)&h1a[e * 32 + k0];
                b = *(const float4*)&h1l[e * 32 + k0];
            }
            *(float4*)&hA[el * HRS + k0] =
                make_float4(tf32f(a.x), tf32f(a.y), tf32f(a.z), tf32f(a.w));
            *(float4*)&hB[el * HRS + k0] =
                make_float4(tf32f(b.x), tf32f(b.y), tf32f(b.z), tf32f(b.w));
        }
        __syncthreads();
        // ---- phase 1: tf32 MMA pair ----
        #pragma unroll 1
        for (int m = 0; m < 4; m++) {
            int m0 = m * 16;
            int rowA = (m0 + group) * HRS;
            float dA[4][4] = {}, dB[4][4] = {};
            #pragma unroll
            for (int ks = 0; ks < 4; ks++) {
                int c = ks * 8 + tig;
                unsigned aA[4], aB[4];
                aA[0] = __float_as_uint(hA[rowA + c]);
                aA[1] = __float_as_uint(hA[rowA + 8 * HRS + c]);
                aA[2] = __float_as_uint(hA[rowA + c + 4]);
                aA[3] = __float_as_uint(hA[rowA + 8 * HRS + c + 4]);
                aB[0] = __float_as_uint(hB[rowA + c]);
                aB[1] = __float_as_uint(hB[rowA + 8 * HRS + c]);
                aB[2] = __float_as_uint(hB[rowA + c + 4]);
                aB[3] = __float_as_uint(hB[rowA + 8 * HRS + c + 4]);
                #pragma unroll
                for (int j = 0; j < 4; j++) {
                    mma_tf32(dA[j], aA, bf[j][ks]);
                    unsigned bl[2];
                    int br = ((wrp * 4 + j) * 8 + group) * 32 + ks * 8 + tig;
                    bl[0] = __float_as_uint(g_WlT[br]);
                    bl[1] = __float_as_uint(g_WlT[br + 4]);
                    mma_tf32(dB[j], aB, bl);
                }
            }
            #pragma unroll
            for (int j = 0; j < 4; j++) {
                int col0 = (wrp * 4 + j) * 8 + 2 * tig;
                *(float2*)&ws[(m0 + group) * WSS + col0] =
                    make_float2(dA[j][0] * dB[j][0], dA[j][1] * dB[j][1]);
                *(float2*)&ws[(m0 + group + 8) * WSS + col0] =
                    make_float2(dA[j][2] * dB[j][2], dA[j][3] * dB[j][3]);
            }
        }
        __syncthreads();
        // ---- phase 2: tensor product + red.v4 scatter ----
        #pragma unroll 4
        for (int it = tid; it < TE * 64; it += 320) {
            int e = it >> 6, u = it & 63;
            int d = idxs[64 + e];
            if (d < 0) continue;
            int s = idxs[e];
            float4 q = *(const float4*)&xg[s * 256 + u * 4];
            float es = q.x, ev0 = q.y, ev1 = q.z, ev2 = q.w;
            float4 shq = ((const float4*)shs)[e];
            float s0 = shq.x, s1 = shq.y, s2 = shq.z, s3 = shq.w;
            const float* we = ws + e * WSS;
            float w0 = we[u], w1 = we[64 + u], w2 = we[128 + u], w3 = we[192 + u], w4 = we[256 + u];
            float dotv = ev0 * s1 + ev1 * s2 + ev2 * s3;
            float c0 = ev1 * s3 - ev2 * s2;
            float c1 = ev2 * s1 - ev0 * s3;
            float c2 = ev0 * s2 - ev1 * s1;
            float outs = PW_S * (w0 * es * s0 + w3 * dotv * IS3);
            float k2 = PW_V * w2 * s0;
            float k4 = PW_V * w4 * IS2;
            float k1 = PW_V * w1 * es;
            float o0 = k1 * s1 + k2 * ev0 + k4 * c0;
            float o1 = k1 * s2 + k2 * ev1 + k4 * c1;
            float o2 = k1 * s3 + k2 * ev2 + k4 * c2;
            float* pa = acc + d * 256 + u * 4;
            asm volatile("red.global.add.v4.f32 [%0], {%1, %2, %3, %4};"
                         :: "l"(pa), "f"(outs), "f"(o0), "f"(o1), "f"(o2) : "memory");
        }
        __syncthreads();
    }
}

// ---------------- launch ----------------------------------------------------
extern "C" void kernel_launch(void* const* d_in, const int* in_sizes, int n_in,
                              void* d_out, int out_size) {
    const float* x     = (const float*)d_in[0];
    const int*   ei    = (const int*)  d_in[1];
    const float* sh    = (const float*)d_in[2];
    const float* attr  = (const float*)d_in[3];
    const float* Wpre0 = (const float*)d_in[4];
    const float* bpre0 = (const float*)d_in[5];
    const float* Wpre1 = (const float*)d_in[6];
    const float* Wg1   = (const float*)d_in[7];
    const float* bg1   = (const float*)d_in[8];
    const float* Wg2   = (const float*)d_in[9];
    const float* bg2   = (const float*)d_in[10];
    const float* Wn0   = (const float*)d_in[11];
    const float* bn0   = (const float*)d_in[12];
    const float* Wn1   = (const float*)d_in[13];
    const float* Wf1   = (const float*)d_in[14];
    const float* Wf2   = (const float*)d_in[15];
    const float* Wl1   = (const float*)d_in[16];
    const float* Wl2   = (const float*)d_in[17];
    const float* Wo0   = (const float*)d_in[18];
    const float* bo0   = (const float*)d_in[19];
    const float* Wo1   = (const float*)d_in[20];

    int N = in_sizes[0] / 256;
    int E = in_sizes[1] / 2;

    float *pre, *tmp, *xgp, *accp, *h1a, *h1l;
    cudaGetSymbolAddress((void**)&pre,  g_pre);
    cudaGetSymbolAddress((void**)&tmp,  g_tmp);
    cudaGetSymbolAddress((void**)&xgp,  g_xg);
    cudaGetSymbolAddress((void**)&accp, g_acc);
    cudaGetSymbolAddress((void**)&h1a,  g_h1a);
    cudaGetSymbolAddress((void**)&h1l,  g_h1l);

    static const int E3_SMEM   = (8192 + 4096 + 64) * 4;
    static const int GATE_SMEM = (16384 * 2 + 4352 * 2) * 4;        // 165,888
    static const int H1A_SMEM  = (8704 + 2304) * 4;
    static const int H1L_SMEM  = (16896 + 4352 + 256) * 4;
    static const int EDGE_SMEM = (2 * TE * HRS + TE * WSS + TE * 4 + 128) * 4;
    cudaFuncSetAttribute(e3_kernel<0,1,1>, cudaFuncAttributeMaxDynamicSharedMemorySize, E3_SMEM);
    cudaFuncSetAttribute(e3_kernel<1,1,1>, cudaFuncAttributeMaxDynamicSharedMemorySize, E3_SMEM);
    cudaFuncSetAttribute(e3_kernel<1,0,0>, cudaFuncAttributeMaxDynamicSharedMemorySize, E3_SMEM);
    cudaFuncSetAttribute(gate_kernel, cudaFuncAttributeMaxDynamicSharedMemorySize, GATE_SMEM);
    cudaFuncSetAttribute(h1a_mma,  cudaFuncAttributeMaxDynamicSharedMemorySize, H1A_SMEM);
    cudaFuncSetAttribute(h1l_mma,  cudaFuncAttributeMaxDynamicSharedMemorySize, H1L_SMEM);
    cudaFuncSetAttribute(edge_kernel, cudaFuncAttributeMaxDynamicSharedMemorySize, EDGE_SMEM);

    static cudaStream_t s1 = nullptr, s2 = nullptr;
    static cudaEvent_t ev0, evP, ev1, ev2;
    if (!s1) {
        cudaStreamCreateWithFlags(&s1, cudaStreamNonBlocking);
        cudaStreamCreateWithFlags(&s2, cudaStreamNonBlocking);
        cudaEventCreateWithFlags(&ev0, cudaEventDisableTiming);
        cudaEventCreateWithFlags(&evP, cudaEventDisableTiming);
        cudaEventCreateWithFlags(&ev1, cudaEventDisableTiming);
        cudaEventCreateWithFlags(&ev2, cudaEventDisableTiming);
    }
    cudaStream_t d = 0;

    // s1: gate (fp32, no prep dependency) starts immediately
    cudaEventRecord(ev0, d);
    cudaStreamWaitEvent(s1, ev0, 0);
    gate_kernel<<<(N + 31) / 32, 512, GATE_SMEM, s1>>>(x, Wg1, bg1, Wg2, bg2, tmp, N);

    // d: prep
    prep_kernel<<<48, 256, 0, d>>>(Wf2, Wl2, Wl1, Wpre0, Wpre1, Wn0, Wn1, Wo0, Wo1, Wf1);
    cudaEventRecord(evP, d);
    cudaStreamWaitEvent(s2, evP, 0);

    // s2: h1a (needs prep for Wf1T)
    h1a_mma<<<(E + 127) / 128, 256, H1A_SMEM, s2>>>(attr, h1a, E);
    cudaEventRecord(ev2, s2);

    // d: e3pre -> h1l
    e3_kernel<0, 1, 1><<<(N + 15) / 16, 256, E3_SMEM, d>>>(x, 0, bpre0, pre, nullptr, N);
    h1l_mma<<<(E + 127) / 128, 256, H1L_SMEM, d>>>(ei, pre, h1l, E, E);

    // s1: e3n after gate + prep
    cudaStreamWaitEvent(s1, evP, 0);
    e3_kernel<1, 1, 1><<<(N + 15) / 16, 256, E3_SMEM, s1>>>(tmp, 1, bn0, xgp, accp, N);
    cudaEventRecord(ev1, s1);

    // join: edge -> final e3
    cudaStreamWaitEvent(d, ev1, 0);
    cudaStreamWaitEvent(d, ev2, 0);
    int ntiles = (E + TE - 1) / TE;
    int eblocks = ntiles < EDGE_BLOCKS ? ntiles : EDGE_BLOCKS;
    edge_kernel<<<eblocks, 320, EDGE_SMEM, d>>>(ei, sh, h1a, h1l, xgp, accp, E, E);
    e3_kernel<1, 0, 0><<<(N + 15) / 16, 256, E3_SMEM, d>>>(accp, 2, bo0, (float*)d_out, nullptr, N);
}